// round 1
// baseline (speedup 1.0000x reference)
#include <cuda_runtime.h>
#include <math.h>

// Problem constants
#define SEQ   2048
#define HID   2048
#define NH    16
#define HD    128
#define BATCH 2
#define MROWS (BATCH * SEQ)     // 4096
#define QKVN  (3 * HID)         // 6144

// ---------------------------------------------------------------------------
// Scratch (device globals — no runtime allocation allowed)
// ---------------------------------------------------------------------------
__device__ __align__(16) float g_qkv[(size_t)MROWS * QKVN];   // 100.7 MB: [row][3H], q|k|v blocks
__device__ __align__(16) float g_ctx[(size_t)MROWS * HID];    // 33.6 MB: attention output [B*S, H]
__device__ __align__(16) float g_cos[SEQ * 64];
__device__ __align__(16) float g_sin[SEQ * 64];

// ---------------------------------------------------------------------------
// RoPE cos/sin table. Reproduce reference numerics: inv_freq computed exactly
// (fp64) then rounded to fp32; angle = fp32(s) * fp32(inv_freq) rounded in
// fp32 (matches jnp.outer in fp32); cos/sin of that fp32 angle evaluated in
// fp64 (≈ exact for the reference's argument → ~1 ulp agreement).
// ---------------------------------------------------------------------------
__global__ void rope_table_kernel() {
    int idx = blockIdx.x * blockDim.x + threadIdx.x;
    if (idx >= SEQ * 64) return;
    int s = idx >> 6;
    int j = idx & 63;
    double inv = exp(-((double)j / 64.0) * log(10000.0));
    float  invf = (float)inv;
    float  ang  = (float)s * invf;      // fp32 rounding, like the reference
    g_cos[idx] = (float)cos((double)ang);
    g_sin[idx] = (float)sin((double)ang);
}

// ---------------------------------------------------------------------------
// In-place RoPE on the q and k blocks of g_qkv.
// rotate_half: out[j] = x[j]*c - x[j+64]*s ; out[j+64] = x[j+64]*c + x[j]*s
// (cos/sin identical for d and d+64 because emb = concat(freqs, freqs)).
// One thread handles one (row, head, j) for both q and k. Grid is exact.
// ---------------------------------------------------------------------------
__global__ void rope_apply_kernel() {
    int idx = blockIdx.x * blockDim.x + threadIdx.x;   // MROWS*NH*64 total
    int j   = idx & 63;
    int h   = (idx >> 6) & (NH - 1);
    int row = idx >> 10;                                // b*SEQ + s
    int s   = row & (SEQ - 1);
    float c  = g_cos[(s << 6) + j];
    float sn = g_sin[(s << 6) + j];
    float* qb = g_qkv + (size_t)row * QKVN + h * HD;
    float q1 = qb[j], q2 = qb[j + 64];
    qb[j]      = q1 * c - q2 * sn;
    qb[j + 64] = q2 * c + q1 * sn;
    float* kb = qb + HID;
    float k1 = kb[j], k2 = kb[j + 64];
    kb[j]      = k1 * c - k2 * sn;
    kb[j + 64] = k2 * c + k1 * sn;
}

// ---------------------------------------------------------------------------
// SGEMM "NT": C[M,N] = A[M,K] * B[N,K]^T, all row-major (K contiguous).
// 128x128 block tile, BK=8, 256 threads, 8x8 micro-tile per thread.
// M,N multiples of 128; K multiple of 8.
// ---------------------------------------------------------------------------
__global__ void __launch_bounds__(256) sgemm_nt_kernel(
    const float* __restrict__ A, const float* __restrict__ B,
    float* __restrict__ C, int M, int N, int K)
{
    __shared__ float As[8][128];
    __shared__ float Bs[8][128];
    int tid = threadIdx.x;
    const float* Ab = A + (size_t)(blockIdx.y * 128) * K;
    const float* Bb = B + (size_t)(blockIdx.x * 128) * K;
    int lr = tid >> 1;            // 0..127: tile row being loaded
    int lc = (tid & 1) << 2;      // 0 or 4: 4-float chunk within BK=8
    int ty = tid >> 4, tx = tid & 15;

    float acc[8][8];
#pragma unroll
    for (int i = 0; i < 8; i++)
#pragma unroll
        for (int j = 0; j < 8; j++) acc[i][j] = 0.f;

    for (int k0 = 0; k0 < K; k0 += 8) {
        float4 a4 = *(const float4*)(Ab + (size_t)lr * K + k0 + lc);
        float4 b4 = *(const float4*)(Bb + (size_t)lr * K + k0 + lc);
        __syncthreads();
        As[lc + 0][lr] = a4.x; As[lc + 1][lr] = a4.y;
        As[lc + 2][lr] = a4.z; As[lc + 3][lr] = a4.w;
        Bs[lc + 0][lr] = b4.x; Bs[lc + 1][lr] = b4.y;
        Bs[lc + 2][lr] = b4.z; Bs[lc + 3][lr] = b4.w;
        __syncthreads();
#pragma unroll
        for (int kk = 0; kk < 8; kk++) {
            float a[8], b[8];
            *(float4*)(a)     = *(const float4*)&As[kk][ty * 8];
            *(float4*)(a + 4) = *(const float4*)&As[kk][ty * 8 + 4];
            *(float4*)(b)     = *(const float4*)&Bs[kk][tx * 8];
            *(float4*)(b + 4) = *(const float4*)&Bs[kk][tx * 8 + 4];
#pragma unroll
            for (int i = 0; i < 8; i++)
#pragma unroll
                for (int j = 0; j < 8; j++)
                    acc[i][j] = fmaf(a[i], b[j], acc[i][j]);
        }
    }
    float* Cb = C + (size_t)(blockIdx.y * 128 + ty * 8) * N + blockIdx.x * 128 + tx * 8;
#pragma unroll
    for (int i = 0; i < 8; i++) {
        *(float4*)(Cb + (size_t)i * N)     = make_float4(acc[i][0], acc[i][1], acc[i][2], acc[i][3]);
        *(float4*)(Cb + (size_t)i * N + 4) = make_float4(acc[i][4], acc[i][5], acc[i][6], acc[i][7]);
    }
}

// ---------------------------------------------------------------------------
// Flash attention (fp32, causal). One CTA = one (b,h) x 64-row q-tile.
// K stored d-major in SMEM (Kts[128][64]) for conflict-light score loads.
// Causal mask applied analytically (identical to the -1e9 additive mask:
// exp underflows to exactly 0). Output written to g_ctx[b*S+s][h*128+d].
// ---------------------------------------------------------------------------
#define BQ 64
#define BKT 64
#define SS_STR 65
#define ATTN_SMEM_FLOATS (64*128 + 128*64 + 64*128 + 64*SS_STR + 4*64 + 4*64)
#define ATTN_SMEM_BYTES  (ATTN_SMEM_FLOATS * 4)

__global__ void __launch_bounds__(256) attn_kernel() {
    extern __shared__ float sm[];
    float* Qs    = sm;                       // [64][128]
    float* Kts   = Qs  + 64 * 128;           // [128][64] d-major
    float* Vs    = Kts + 128 * 64;           // [64][128]
    float* Ss    = Vs  + 64 * 128;           // [64][SS_STR]
    float* red   = Ss  + 64 * SS_STR;        // [4][64]
    float* m_sh  = red + 256;                // [64]
    float* l_sh  = m_sh + 64;                // [64]
    float* al_sh = l_sh + 64;                // [64]
    float* mn_sh = al_sh + 64;               // [64]

    int tid = threadIdx.x;
    int qt  = (int)gridDim.x - 1 - (int)blockIdx.x;   // big tiles scheduled first
    int bh  = blockIdx.y;
    int b   = bh >> 4, h = bh & 15;
    int q0  = qt * BQ;
    const float* base = g_qkv + (size_t)b * SEQ * QKVN + h * HD;

    // Load Q tile (row-major, float4)
    for (int i = tid; i < 64 * 32; i += 256) {
        int r = i >> 5, d4 = i & 31;
        *(float4*)&Qs[r * 128 + (d4 << 2)] =
            *(const float4*)(base + (size_t)(q0 + r) * QKVN + (d4 << 2));
    }
    if (tid < 64) { m_sh[tid] = -1e30f; l_sh[tid] = 0.f; }

    float acc[4][8];
#pragma unroll
    for (int i = 0; i < 4; i++)
#pragma unroll
        for (int j = 0; j < 8; j++) acc[i][j] = 0.f;

    int ry = tid >> 4, cx = tid & 15;   // scores: rows ry*4.., cols cx*4..; PV: cols cx*8..
    int rr = tid & 63, part = tid >> 6; // reduction mapping: 4 threads per row

    for (int kt = 0; kt <= qt; kt++) {
        int k0 = kt * BKT;
        __syncthreads();   // previous iteration's PV / Q-load done before overwrite
        // Load K (transposed to d-major) and V (row-major)
        for (int i = tid; i < 64 * 32; i += 256) {
            int r = i & 63, d4 = i >> 6;
            const float* kr = base + (size_t)(k0 + r) * QKVN + HID + (d4 << 2);
            float4 kv = *(const float4*)kr;
            Kts[(d4 * 4 + 0) * 64 + r] = kv.x;
            Kts[(d4 * 4 + 1) * 64 + r] = kv.y;
            Kts[(d4 * 4 + 2) * 64 + r] = kv.z;
            Kts[(d4 * 4 + 3) * 64 + r] = kv.w;
            *(float4*)&Vs[r * 128 + (d4 << 2)] = *(const float4*)(kr + HID);
        }
        __syncthreads();

        // S = Q K^T (4x4 per thread)
        float sv[4][4];
#pragma unroll
        for (int i = 0; i < 4; i++)
#pragma unroll
            for (int j = 0; j < 4; j++) sv[i][j] = 0.f;

        for (int d = 0; d < 128; d += 4) {
            float qv[4][4], kv[4][4];
#pragma unroll
            for (int i = 0; i < 4; i++) {
                float4 t = *(float4*)&Qs[(ry * 4 + i) * 128 + d];
                qv[i][0] = t.x; qv[i][1] = t.y; qv[i][2] = t.z; qv[i][3] = t.w;
            }
#pragma unroll
            for (int dd = 0; dd < 4; dd++) {
                float4 t = *(float4*)&Kts[(d + dd) * 64 + cx * 4];
                kv[dd][0] = t.x; kv[dd][1] = t.y; kv[dd][2] = t.z; kv[dd][3] = t.w;
            }
#pragma unroll
            for (int dd = 0; dd < 4; dd++)
#pragma unroll
                for (int i = 0; i < 4; i++)
#pragma unroll
                    for (int j = 0; j < 4; j++)
                        sv[i][j] = fmaf(qv[i][dd], kv[dd][j], sv[i][j]);
        }

        const float scale = 0.08838834764831845f;  // 1/sqrt(128)
        bool diag = (kt == qt);
#pragma unroll
        for (int i = 0; i < 4; i++) {
            int r = ry * 4 + i;
#pragma unroll
            for (int j = 0; j < 4; j++) {
                int c = cx * 4 + j;
                float v = sv[i][j] * scale;
                if (diag && c > r) v = -1e30f;  // k0+c > q0+r  (k0==q0 on diag tile)
                Ss[r * SS_STR + c] = v;
            }
        }
        __syncthreads();

        // Pass A: row max (4 partials per row)
        {
            float pm = -1e30f;
            int cb = part * 16;
#pragma unroll
            for (int c = 0; c < 16; c++) pm = fmaxf(pm, Ss[rr * SS_STR + cb + c]);
            red[part * 64 + rr] = pm;
        }
        __syncthreads();
        if (tid < 64) {
            float mt = fmaxf(fmaxf(red[tid], red[64 + tid]),
                             fmaxf(red[128 + tid], red[192 + tid]));
            float mo = m_sh[tid];
            float mn = fmaxf(mo, mt);
            mn_sh[tid] = mn;
            al_sh[tid] = __expf(mo - mn);
            m_sh[tid]  = mn;
        }
        __syncthreads();

        // Pass B: P = exp(S - m_new), partial row sums; rescale accumulators
        {
            float mn = mn_sh[rr];
            float ps = 0.f;
            int cb = part * 16;
#pragma unroll
            for (int c = 0; c < 16; c++) {
                float e = __expf(Ss[rr * SS_STR + cb + c] - mn);
                Ss[rr * SS_STR + cb + c] = e;
                ps += e;
            }
            red[part * 64 + rr] = ps;
        }
#pragma unroll
        for (int i = 0; i < 4; i++) {
            float a = al_sh[ry * 4 + i];
#pragma unroll
            for (int j = 0; j < 8; j++) acc[i][j] *= a;
        }
        __syncthreads();
        if (tid < 64)
            l_sh[tid] = l_sh[tid] * al_sh[tid] +
                        red[tid] + red[64 + tid] + red[128 + tid] + red[192 + tid];

        // PV: acc[64 x 128] += P[64 x 64] * V[64 x 128]
#pragma unroll 4
        for (int kk = 0; kk < 64; kk++) {
            float p[4];
#pragma unroll
            for (int i = 0; i < 4; i++) p[i] = Ss[(ry * 4 + i) * SS_STR + kk];
            float4 v0 = *(float4*)&Vs[kk * 128 + cx * 8];
            float4 v1 = *(float4*)&Vs[kk * 128 + cx * 8 + 4];
            float vv[8] = {v0.x, v0.y, v0.z, v0.w, v1.x, v1.y, v1.z, v1.w};
#pragma unroll
            for (int i = 0; i < 4; i++)
#pragma unroll
                for (int j = 0; j < 8; j++)
                    acc[i][j] = fmaf(p[i], vv[j], acc[i][j]);
        }
    }
    __syncthreads();

    // Epilogue: out = acc / l
    float* ob = g_ctx + (size_t)(b * SEQ + q0) * HID + h * HD;
#pragma unroll
    for (int i = 0; i < 4; i++) {
        float il = 1.f / l_sh[ry * 4 + i];
        float4 o0 = make_float4(acc[i][0] * il, acc[i][1] * il, acc[i][2] * il, acc[i][3] * il);
        float4 o1 = make_float4(acc[i][4] * il, acc[i][5] * il, acc[i][6] * il, acc[i][7] * il);
        *(float4*)(ob + (size_t)(ry * 4 + i) * HID + cx * 8)     = o0;
        *(float4*)(ob + (size_t)(ry * 4 + i) * HID + cx * 8 + 4) = o1;
    }
}

// ---------------------------------------------------------------------------
// Launch: table -> QKV GEMM -> RoPE -> attention -> output GEMM
// (all on the capture stream; no sync, no allocation)
// ---------------------------------------------------------------------------
extern "C" void kernel_launch(void* const* d_in, const int* in_sizes, int n_in,
                              void* d_out, int out_size) {
    const float* x    = (const float*)d_in[0];
    // d_in[1] = attn_mask: pure causal, reproduced analytically — not read.
    const float* Wqkv = (const float*)d_in[2];
    const float* Wout = (const float*)d_in[3];
    float* out = (float*)d_out;

    float *qkv_ptr = 0, *ctx_ptr = 0;
    cudaGetSymbolAddress((void**)&qkv_ptr, g_qkv);
    cudaGetSymbolAddress((void**)&ctx_ptr, g_ctx);

    cudaFuncSetAttribute(attn_kernel,
                         cudaFuncAttributeMaxDynamicSharedMemorySize,
                         ATTN_SMEM_BYTES);

    rope_table_kernel<<<(SEQ * 64 + 255) / 256, 256>>>();
    sgemm_nt_kernel<<<dim3(QKVN / 128, MROWS / 128), 256>>>(x, Wqkv, qkv_ptr,
                                                            MROWS, QKVN, HID);
    rope_apply_kernel<<<(MROWS * NH * 64) / 256, 256>>>();
    attn_kernel<<<dim3(SEQ / BQ, BATCH * NH), 256, ATTN_SMEM_BYTES>>>();
    sgemm_nt_kernel<<<dim3(HID / 128, MROWS / 128), 256>>>(ctx_ptr, Wout, out,
                                                           MROWS, HID, HID);
}

// round 3
// speedup vs baseline: 2.4297x; 2.4297x over previous
#include <cuda_runtime.h>
#include <cuda_bf16.h>
#include <math.h>
#include <stdint.h>

// Problem constants
#define SEQ   2048
#define HID   2048
#define NH    16
#define HD    128
#define BATCH 2
#define MROWS (BATCH * SEQ)     // 4096
#define QKVN  (3 * HID)         // 6144
#define KPACK 4096              // packed row length: [hi(2048) | lo(2048)]

// ---------------------------------------------------------------------------
// Scratch (device globals — no runtime allocation allowed)
// ---------------------------------------------------------------------------
__device__ __align__(16) float g_qkv[(size_t)MROWS * QKVN];    // fp32 QKV
__device__ __align__(16) float g_ctx[(size_t)MROWS * HID];     // fp32 attn out
__device__ __align__(16) float g_cos[SEQ * 64];
__device__ __align__(16) float g_sin[SEQ * 64];
__device__ __align__(16) __nv_bfloat16 g_xp  [(size_t)MROWS * KPACK];  // x packed
__device__ __align__(16) __nv_bfloat16 g_wqp [(size_t)QKVN  * KPACK];  // Wqkv packed
__device__ __align__(16) __nv_bfloat16 g_wop [(size_t)HID   * KPACK];  // Wout packed
__device__ __align__(16) __nv_bfloat16 g_cxp [(size_t)MROWS * KPACK];  // ctx packed

// ---------------------------------------------------------------------------
// PTX helpers (arch-agnostic: cp.async / ldmatrix / mma.sync only)
// ---------------------------------------------------------------------------
__device__ __forceinline__ uint32_t s2u(const void* p) {
    uint32_t a;
    asm("{ .reg .u64 t; cvta.to.shared.u64 t, %1; cvt.u32.u64 %0, t; }"
        : "=r"(a) : "l"(p));
    return a;
}

#define CP_ASYNC16(saddr, gptr) \
    asm volatile("cp.async.cg.shared.global [%0], [%1], 16;" \
                 :: "r"(saddr), "l"(gptr))
#define CP_COMMIT()  asm volatile("cp.async.commit_group;" ::: "memory")
#define CP_WAIT1()   asm volatile("cp.async.wait_group 1;" ::: "memory")
#define CP_WAIT0()   asm volatile("cp.async.wait_group 0;" ::: "memory")

#define LDSM4(r, addr)                                                        \
    asm volatile("ldmatrix.sync.aligned.m8n8.x4.shared.b16 {%0,%1,%2,%3}, [%4];" \
        : "=r"((r)[0]), "=r"((r)[1]), "=r"((r)[2]), "=r"((r)[3]) : "r"(addr))

#define MMA16816(d, a, b0, b1)                                                \
    asm volatile("mma.sync.aligned.m16n8k16.row.col.f32.bf16.bf16.f32 "       \
        "{%0,%1,%2,%3},{%4,%5,%6,%7},{%8,%9},{%0,%1,%2,%3};"                  \
        : "+f"((d)[0]), "+f"((d)[1]), "+f"((d)[2]), "+f"((d)[3])              \
        : "r"((a)[0]), "r"((a)[1]), "r"((a)[2]), "r"((a)[3]),                 \
          "r"(b0), "r"(b1))

// ---------------------------------------------------------------------------
// RoPE table (reference-matching numerics)
// ---------------------------------------------------------------------------
__global__ void rope_table_kernel() {
    int idx = blockIdx.x * blockDim.x + threadIdx.x;
    if (idx >= SEQ * 64) return;
    int s = idx >> 6;
    int j = idx & 63;
    double inv = exp(-((double)j / 64.0) * log(10000.0));
    float  invf = (float)inv;
    float  ang  = (float)s * invf;
    g_cos[idx] = (float)cos((double)ang);
    g_sin[idx] = (float)sin((double)ang);
}

// ---------------------------------------------------------------------------
// In-place RoPE on q,k blocks of g_qkv
// ---------------------------------------------------------------------------
__global__ void rope_apply_kernel() {
    int idx = blockIdx.x * blockDim.x + threadIdx.x;
    int j   = idx & 63;
    int h   = (idx >> 6) & (NH - 1);
    int row = idx >> 10;
    int s   = row & (SEQ - 1);
    float c  = g_cos[(s << 6) + j];
    float sn = g_sin[(s << 6) + j];
    float* qb = g_qkv + (size_t)row * QKVN + h * HD;
    float q1 = qb[j], q2 = qb[j + 64];
    qb[j]      = q1 * c - q2 * sn;
    qb[j + 64] = q2 * c + q1 * sn;
    float* kb = qb + HID;
    float k1 = kb[j], k2 = kb[j + 64];
    kb[j]      = k1 * c - k2 * sn;
    kb[j + 64] = k2 * c + k1 * sn;
}

// ---------------------------------------------------------------------------
// fp32 -> split bf16 pack: P[row][0:2048]=hi, P[row][2048:4096]=lo
// ---------------------------------------------------------------------------
__global__ void pack_kernel(const float* __restrict__ X,
                            __nv_bfloat16* __restrict__ P, int n) {
    int i = blockIdx.x * 256 + threadIdx.x;
    if (i >= n) return;
    int row = i >> 11, col = i & 2047;
    float v = X[i];
    __nv_bfloat16 h = __float2bfloat16(v);
    float hf = __bfloat162float(h);
    P[(size_t)row * KPACK + col]        = h;
    P[(size_t)row * KPACK + 2048 + col] = __float2bfloat16(v - hf);
}

// ---------------------------------------------------------------------------
// bf16x3 tensor-core GEMM via mma.sync (compute_103-portable).
// C[M,N] = A_f32 B_f32^T; A packed [M][4096], B packed [N][4096].
// CTA tile 128x128, BK=32, 8 warps (32x64 each), 3-stage cp.async pipeline.
// Smem rows padded to 40 bf16 (80 B): conflict-free ldmatrix.
// ---------------------------------------------------------------------------
#define AST         40
#define STG_MAT     (128 * AST * 2)      // bytes per matrix per stage (10240)
#define STG_BYTES   (2 * STG_MAT)        // A + B per stage (20480)
#define GEMM_STAGES 3
#define GEMM_SMEM   (GEMM_STAGES * STG_BYTES)   // 61440
#define GNITER      192                  // 3 passes x 64 chunks of K=32

__device__ __forceinline__ void g_load_stage(
    uint32_t sA, uint32_t sB,
    const __nv_bfloat16* Ab, const __nv_bfloat16* Bb, int tid)
{
#pragma unroll
    for (int t = 0; t < 2; t++) {
        int c = tid + t * 256;           // 0..511
        int r = c >> 2, co = (c & 3) << 3;   // row, col element (8 bf16 = 16 B)
        CP_ASYNC16(sA + (r * AST + co) * 2, Ab + (size_t)r * KPACK + co);
        CP_ASYNC16(sB + (r * AST + co) * 2, Bb + (size_t)r * KPACK + co);
    }
}

__global__ void __launch_bounds__(256, 1) tc_gemm_kernel(
    const __nv_bfloat16* __restrict__ A, const __nv_bfloat16* __restrict__ B,
    float* __restrict__ C, int ldc)
{
    extern __shared__ char sm[];
    uint32_t smb = s2u(sm);
    int tid  = threadIdx.x;
    int lane = tid & 31, wid = tid >> 5;
    int wm = (wid & 3) * 32, wn = (wid >> 2) * 64;
    int m0 = blockIdx.y * 128, n0 = blockIdx.x * 128;

    float acc[2][8][4];
#pragma unroll
    for (int i = 0; i < 2; i++)
#pragma unroll
        for (int j = 0; j < 8; j++)
#pragma unroll
            for (int k = 0; k < 4; k++) acc[i][j][k] = 0.f;

    // chunk -> gmem offset
    auto chunk_off = [&](int it, int& aoff, int& boff, int& k0) {
        int pass = it >> 6;
        k0   = (it & 63) << 5;
        aoff = (pass == 2) ? 2048 : 0;
        boff = (pass == 1) ? 2048 : 0;
    };

    // Prologue: stages 0,1
#pragma unroll
    for (int p = 0; p < GEMM_STAGES - 1; p++) {
        int aoff, boff, k0;
        chunk_off(p, aoff, boff, k0);
        uint32_t sA = smb + p * STG_BYTES;
        g_load_stage(sA, sA + STG_MAT,
                     A + (size_t)m0 * KPACK + aoff + k0,
                     B + (size_t)n0 * KPACK + boff + k0, tid);
        CP_COMMIT();
    }

    // Precomputed intra-stage ldmatrix offsets (bytes)
    uint32_t a_off[2][2], b_off[2][4];
#pragma unroll
    for (int ks = 0; ks < 2; ks++) {
#pragma unroll
        for (int mt = 0; mt < 2; mt++)
            a_off[ks][mt] = ((wm + mt * 16 + (lane & 15)) * AST +
                             ks * 16 + (lane >> 4) * 8) * 2;
#pragma unroll
        for (int np = 0; np < 4; np++)
            b_off[ks][np] = STG_MAT +
                ((wn + np * 16 + ((lane >> 4) & 1) * 8 + (lane & 7)) * AST +
                 ks * 16 + ((lane >> 3) & 1) * 8) * 2;
    }

    for (int it = 0; it < GNITER; ++it) {
        CP_WAIT1();
        __syncthreads();
        int nx = it + GEMM_STAGES - 1;
        if (nx < GNITER) {
            int aoff, boff, k0;
            chunk_off(nx, aoff, boff, k0);
            uint32_t sA = smb + (nx % GEMM_STAGES) * STG_BYTES;
            g_load_stage(sA, sA + STG_MAT,
                         A + (size_t)m0 * KPACK + aoff + k0,
                         B + (size_t)n0 * KPACK + boff + k0, tid);
        }
        CP_COMMIT();

        uint32_t sbase = smb + (it % GEMM_STAGES) * STG_BYTES;
#pragma unroll
        for (int ks = 0; ks < 2; ks++) {
            uint32_t afr[2][4];
#pragma unroll
            for (int mt = 0; mt < 2; mt++) LDSM4(afr[mt], sbase + a_off[ks][mt]);
#pragma unroll
            for (int np = 0; np < 4; np++) {
                uint32_t bfr[4];
                LDSM4(bfr, sbase + b_off[ks][np]);
#pragma unroll
                for (int mt = 0; mt < 2; mt++) {
                    MMA16816(acc[mt][2 * np],     afr[mt], bfr[0], bfr[1]);
                    MMA16816(acc[mt][2 * np + 1], afr[mt], bfr[2], bfr[3]);
                }
            }
        }
    }

    // Epilogue
    float* Cb = C + (size_t)(m0 + wm) * ldc + n0 + wn;
    int rq = lane >> 2, cq = (lane & 3) * 2;
#pragma unroll
    for (int mt = 0; mt < 2; mt++)
#pragma unroll
        for (int nt = 0; nt < 8; nt++) {
            *(float2*)(Cb + (size_t)(mt * 16 + rq) * ldc + nt * 8 + cq) =
                make_float2(acc[mt][nt][0], acc[mt][nt][1]);
            *(float2*)(Cb + (size_t)(mt * 16 + rq + 8) * ldc + nt * 8 + cq) =
                make_float2(acc[mt][nt][2], acc[mt][nt][3]);
        }
}

// ---------------------------------------------------------------------------
// Flash attention (fp32, causal) — unchanged (known good from round 1)
// ---------------------------------------------------------------------------
#define BQ 64
#define BKT 64
#define SS_STR 65
#define ATTN_SMEM_FLOATS (64*128 + 128*64 + 64*128 + 64*SS_STR + 4*64 + 4*64)
#define ATTN_SMEM_BYTES  (ATTN_SMEM_FLOATS * 4)

__global__ void __launch_bounds__(256) attn_kernel() {
    extern __shared__ float smf[];
    float* Qs    = smf;
    float* Kts   = Qs  + 64 * 128;
    float* Vs    = Kts + 128 * 64;
    float* Ss    = Vs  + 64 * 128;
    float* red   = Ss  + 64 * SS_STR;
    float* m_sh  = red + 256;
    float* l_sh  = m_sh + 64;
    float* al_sh = l_sh + 64;
    float* mn_sh = al_sh + 64;

    int tid = threadIdx.x;
    int qt  = (int)gridDim.x - 1 - (int)blockIdx.x;
    int bh  = blockIdx.y;
    int b   = bh >> 4, h = bh & 15;
    int q0  = qt * BQ;
    const float* base = g_qkv + (size_t)b * SEQ * QKVN + h * HD;

    for (int i = tid; i < 64 * 32; i += 256) {
        int r = i >> 5, d4 = i & 31;
        *(float4*)&Qs[r * 128 + (d4 << 2)] =
            *(const float4*)(base + (size_t)(q0 + r) * QKVN + (d4 << 2));
    }
    if (tid < 64) { m_sh[tid] = -1e30f; l_sh[tid] = 0.f; }

    float acc[4][8];
#pragma unroll
    for (int i = 0; i < 4; i++)
#pragma unroll
        for (int j = 0; j < 8; j++) acc[i][j] = 0.f;

    int ry = tid >> 4, cx = tid & 15;
    int rr = tid & 63, part = tid >> 6;

    for (int kt = 0; kt <= qt; kt++) {
        int k0 = kt * BKT;
        __syncthreads();
        for (int i = tid; i < 64 * 32; i += 256) {
            int r = i & 63, d4 = i >> 6;
            const float* kr = base + (size_t)(k0 + r) * QKVN + HID + (d4 << 2);
            float4 kv = *(const float4*)kr;
            Kts[(d4 * 4 + 0) * 64 + r] = kv.x;
            Kts[(d4 * 4 + 1) * 64 + r] = kv.y;
            Kts[(d4 * 4 + 2) * 64 + r] = kv.z;
            Kts[(d4 * 4 + 3) * 64 + r] = kv.w;
            *(float4*)&Vs[r * 128 + (d4 << 2)] = *(const float4*)(kr + HID);
        }
        __syncthreads();

        float sv[4][4];
#pragma unroll
        for (int i = 0; i < 4; i++)
#pragma unroll
            for (int j = 0; j < 4; j++) sv[i][j] = 0.f;

        for (int d = 0; d < 128; d += 4) {
            float qv[4][4], kv[4][4];
#pragma unroll
            for (int i = 0; i < 4; i++) {
                float4 t = *(float4*)&Qs[(ry * 4 + i) * 128 + d];
                qv[i][0] = t.x; qv[i][1] = t.y; qv[i][2] = t.z; qv[i][3] = t.w;
            }
#pragma unroll
            for (int dd = 0; dd < 4; dd++) {
                float4 t = *(float4*)&Kts[(d + dd) * 64 + cx * 4];
                kv[dd][0] = t.x; kv[dd][1] = t.y; kv[dd][2] = t.z; kv[dd][3] = t.w;
            }
#pragma unroll
            for (int dd = 0; dd < 4; dd++)
#pragma unroll
                for (int i = 0; i < 4; i++)
#pragma unroll
                    for (int j = 0; j < 4; j++)
                        sv[i][j] = fmaf(qv[i][dd], kv[dd][j], sv[i][j]);
        }

        const float scale = 0.08838834764831845f;
        bool diag = (kt == qt);
#pragma unroll
        for (int i = 0; i < 4; i++) {
            int rI = ry * 4 + i;
#pragma unroll
            for (int j = 0; j < 4; j++) {
                int c = cx * 4 + j;
                float v = sv[i][j] * scale;
                if (diag && c > rI) v = -1e30f;
                Ss[rI * SS_STR + c] = v;
            }
        }
        __syncthreads();

        {
            float pm = -1e30f;
            int cb = part * 16;
#pragma unroll
            for (int c = 0; c < 16; c++) pm = fmaxf(pm, Ss[rr * SS_STR + cb + c]);
            red[part * 64 + rr] = pm;
        }
        __syncthreads();
        if (tid < 64) {
            float mt = fmaxf(fmaxf(red[tid], red[64 + tid]),
                             fmaxf(red[128 + tid], red[192 + tid]));
            float mo = m_sh[tid];
            float mn = fmaxf(mo, mt);
            mn_sh[tid] = mn;
            al_sh[tid] = __expf(mo - mn);
            m_sh[tid]  = mn;
        }
        __syncthreads();

        {
            float mn = mn_sh[rr];
            float ps = 0.f;
            int cb = part * 16;
#pragma unroll
            for (int c = 0; c < 16; c++) {
                float e = __expf(Ss[rr * SS_STR + cb + c] - mn);
                Ss[rr * SS_STR + cb + c] = e;
                ps += e;
            }
            red[part * 64 + rr] = ps;
        }
#pragma unroll
        for (int i = 0; i < 4; i++) {
            float a = al_sh[ry * 4 + i];
#pragma unroll
            for (int j = 0; j < 8; j++) acc[i][j] *= a;
        }
        __syncthreads();
        if (tid < 64)
            l_sh[tid] = l_sh[tid] * al_sh[tid] +
                        red[tid] + red[64 + tid] + red[128 + tid] + red[192 + tid];

#pragma unroll 4
        for (int kk = 0; kk < 64; kk++) {
            float p[4];
#pragma unroll
            for (int i = 0; i < 4; i++) p[i] = Ss[(ry * 4 + i) * SS_STR + kk];
            float4 v0 = *(float4*)&Vs[kk * 128 + cx * 8];
            float4 v1 = *(float4*)&Vs[kk * 128 + cx * 8 + 4];
            float vv[8] = {v0.x, v0.y, v0.z, v0.w, v1.x, v1.y, v1.z, v1.w};
#pragma unroll
            for (int i = 0; i < 4; i++)
#pragma unroll
                for (int j = 0; j < 8; j++)
                    acc[i][j] = fmaf(p[i], vv[j], acc[i][j]);
        }
    }
    __syncthreads();

    float* ob = g_ctx + (size_t)(b * SEQ + q0) * HID + h * HD;
#pragma unroll
    for (int i = 0; i < 4; i++) {
        float il = 1.f / l_sh[ry * 4 + i];
        float4 o0 = make_float4(acc[i][0] * il, acc[i][1] * il, acc[i][2] * il, acc[i][3] * il);
        float4 o1 = make_float4(acc[i][4] * il, acc[i][5] * il, acc[i][6] * il, acc[i][7] * il);
        *(float4*)(ob + (size_t)(ry * 4 + i) * HID + cx * 8)     = o0;
        *(float4*)(ob + (size_t)(ry * 4 + i) * HID + cx * 8 + 4) = o1;
    }
}

// ---------------------------------------------------------------------------
// Launch graph
// ---------------------------------------------------------------------------
extern "C" void kernel_launch(void* const* d_in, const int* in_sizes, int n_in,
                              void* d_out, int out_size) {
    const float* x    = (const float*)d_in[0];
    // d_in[1] = attn_mask (pure causal) — reproduced analytically, not read
    const float* Wqkv = (const float*)d_in[2];
    const float* Wout = (const float*)d_in[3];
    float* out = (float*)d_out;

    float *qkv_ptr = 0, *ctx_ptr = 0;
    __nv_bfloat16 *xp = 0, *wqp = 0, *wop = 0, *cxp = 0;
    cudaGetSymbolAddress((void**)&qkv_ptr, g_qkv);
    cudaGetSymbolAddress((void**)&ctx_ptr, g_ctx);
    cudaGetSymbolAddress((void**)&xp,  g_xp);
    cudaGetSymbolAddress((void**)&wqp, g_wqp);
    cudaGetSymbolAddress((void**)&wop, g_wop);
    cudaGetSymbolAddress((void**)&cxp, g_cxp);

    cudaFuncSetAttribute(attn_kernel,
                         cudaFuncAttributeMaxDynamicSharedMemorySize,
                         ATTN_SMEM_BYTES);
    cudaFuncSetAttribute(tc_gemm_kernel,
                         cudaFuncAttributeMaxDynamicSharedMemorySize,
                         GEMM_SMEM);

    rope_table_kernel<<<(SEQ * 64 + 255) / 256, 256>>>();

    pack_kernel<<<(MROWS * HID + 255) / 256, 256>>>(x, xp, MROWS * HID);
    pack_kernel<<<(QKVN  * HID + 255) / 256, 256>>>(Wqkv, wqp, QKVN * HID);
    pack_kernel<<<(HID   * HID + 255) / 256, 256>>>(Wout, wop, HID * HID);

    tc_gemm_kernel<<<dim3(QKVN / 128, MROWS / 128), 256, GEMM_SMEM>>>(
        xp, wqp, qkv_ptr, QKVN);

    rope_apply_kernel<<<(MROWS * NH * 64) / 256, 256>>>();
    attn_kernel<<<dim3(SEQ / BQ, BATCH * NH), 256, ATTN_SMEM_BYTES>>>();

    pack_kernel<<<(MROWS * HID + 255) / 256, 256>>>(ctx_ptr, cxp, MROWS * HID);
    tc_gemm_kernel<<<dim3(HID / 128, MROWS / 128), 256, GEMM_SMEM>>>(
        cxp, wop, out, HID);
}

// round 4
// speedup vs baseline: 3.7804x; 1.5559x over previous
#include <cuda_runtime.h>
#include <cuda_bf16.h>
#include <math.h>
#include <stdint.h>

// Problem constants
#define SEQ   2048
#define HID   2048
#define NH    16
#define HD    128
#define BATCH 2
#define MROWS (BATCH * SEQ)     // 4096
#define QKVN  (3 * HID)         // 6144
#define KPACK 4096              // packed row length: [hi(2048) | lo(2048)]

// ---------------------------------------------------------------------------
// Scratch (device globals — no runtime allocation allowed)
// ---------------------------------------------------------------------------
__device__ __align__(16) float g_qkv[(size_t)MROWS * QKVN];    // fp32 QKV
__device__ __align__(16) float g_ctx[(size_t)MROWS * HID];     // fp32 attn out
__device__ __align__(16) float g_cos[SEQ * 64];
__device__ __align__(16) float g_sin[SEQ * 64];
__device__ __align__(16) __nv_bfloat16 g_xp  [(size_t)MROWS * KPACK];
__device__ __align__(16) __nv_bfloat16 g_wqp [(size_t)QKVN  * KPACK];
__device__ __align__(16) __nv_bfloat16 g_wop [(size_t)HID   * KPACK];
__device__ __align__(16) __nv_bfloat16 g_cxp [(size_t)MROWS * KPACK];
// attention operands: [bh*2 + plane(hi=0,lo=1)][s][128]
__device__ __align__(16) __nv_bfloat16 g_qp[(size_t)BATCH * NH * 2 * SEQ * HD];
__device__ __align__(16) __nv_bfloat16 g_kp[(size_t)BATCH * NH * 2 * SEQ * HD];
__device__ __align__(16) __nv_bfloat16 g_vp[(size_t)BATCH * NH * 2 * SEQ * HD];

// ---------------------------------------------------------------------------
// PTX helpers (arch-agnostic: cp.async / ldmatrix / mma.sync only)
// ---------------------------------------------------------------------------
__device__ __forceinline__ uint32_t s2u(const void* p) {
    uint32_t a;
    asm("{ .reg .u64 t; cvta.to.shared.u64 t, %1; cvt.u32.u64 %0, t; }"
        : "=r"(a) : "l"(p));
    return a;
}

#define CP_ASYNC16(saddr, gptr) \
    asm volatile("cp.async.cg.shared.global [%0], [%1], 16;" \
                 :: "r"(saddr), "l"(gptr))
#define CP_COMMIT()  asm volatile("cp.async.commit_group;" ::: "memory")
#define CP_WAIT1()   asm volatile("cp.async.wait_group 1;" ::: "memory")

#define LDSM4(r, addr)                                                        \
    asm volatile("ldmatrix.sync.aligned.m8n8.x4.shared.b16 {%0,%1,%2,%3}, [%4];" \
        : "=r"((r)[0]), "=r"((r)[1]), "=r"((r)[2]), "=r"((r)[3]) : "r"(addr))
#define LDSM4T(r, addr)                                                       \
    asm volatile("ldmatrix.sync.aligned.m8n8.x4.trans.shared.b16 {%0,%1,%2,%3}, [%4];" \
        : "=r"((r)[0]), "=r"((r)[1]), "=r"((r)[2]), "=r"((r)[3]) : "r"(addr))

#define MMA16816(d, a, b0, b1)                                                \
    asm volatile("mma.sync.aligned.m16n8k16.row.col.f32.bf16.bf16.f32 "       \
        "{%0,%1,%2,%3},{%4,%5,%6,%7},{%8,%9},{%0,%1,%2,%3};"                  \
        : "+f"((d)[0]), "+f"((d)[1]), "+f"((d)[2]), "+f"((d)[3])              \
        : "r"((a)[0]), "r"((a)[1]), "r"((a)[2]), "r"((a)[3]),                 \
          "r"(b0), "r"(b1))

__device__ __forceinline__ float ex2f(float x) {
    float y;
    asm("ex2.approx.ftz.f32 %0, %1;" : "=f"(y) : "f"(x));
    return y;
}
__device__ __forceinline__ uint32_t packbf(float hi, float lo) {
    uint32_t d;
    asm("cvt.rn.bf16x2.f32 %0, %1, %2;" : "=r"(d) : "f"(hi), "f"(lo));
    return d;
}

// ---------------------------------------------------------------------------
// RoPE table (reference-matching numerics)
// ---------------------------------------------------------------------------
__global__ void rope_table_kernel() {
    int idx = blockIdx.x * blockDim.x + threadIdx.x;
    if (idx >= SEQ * 64) return;
    int s = idx >> 6;
    int j = idx & 63;
    double inv = exp(-((double)j / 64.0) * log(10000.0));
    float  invf = (float)inv;
    float  ang  = (float)s * invf;
    g_cos[idx] = (float)cos((double)ang);
    g_sin[idx] = (float)sin((double)ang);
}

// ---------------------------------------------------------------------------
// fp32 -> split bf16 pack: P[row][0:2048]=hi, P[row][2048:4096]=lo
// ---------------------------------------------------------------------------
__global__ void pack_kernel(const float* __restrict__ X,
                            __nv_bfloat16* __restrict__ P, int n) {
    int i = blockIdx.x * 256 + threadIdx.x;
    if (i >= n) return;
    int row = i >> 11, col = i & 2047;
    float v = X[i];
    __nv_bfloat16 h = __float2bfloat16(v);
    float hf = __bfloat162float(h);
    P[(size_t)row * KPACK + col]        = h;
    P[(size_t)row * KPACK + 2048 + col] = __float2bfloat16(v - hf);
}

// ---------------------------------------------------------------------------
// QKV pack: RoPE on q,k + hi/lo bf16 split of q,k,v into planar layouts.
// One thread = one (row, head, j<64): handles dims j and j+64 of q,k,v.
// ---------------------------------------------------------------------------
__device__ __forceinline__ void bsplit(float v, __nv_bfloat16& h, __nv_bfloat16& l) {
    h = __float2bfloat16(v);
    l = __float2bfloat16(v - __bfloat162float(h));
}

__global__ void qkv_pack_kernel() {
    int idx = blockIdx.x * blockDim.x + threadIdx.x;   // MROWS*NH*64
    int j   = idx & 63;
    int h   = (idx >> 6) & (NH - 1);
    int row = idx >> 10;
    int s   = row & (SEQ - 1);
    int b   = row >> 11;
    int bh  = b * NH + h;
    float c  = g_cos[(s << 6) + j];
    float sn = g_sin[(s << 6) + j];
    const float* base = g_qkv + (size_t)row * QKVN + h * HD;

    float q1 = base[j], q2 = base[j + 64];
    float qa = q1 * c - q2 * sn;
    float qb = q2 * c + q1 * sn;
    float k1 = base[HID + j], k2 = base[HID + j + 64];
    float ka = k1 * c - k2 * sn;
    float kb = k2 * c + k1 * sn;
    float v1 = base[2 * HID + j], v2 = base[2 * HID + j + 64];

    size_t pb = ((size_t)(bh * 2) * SEQ + s) * HD;   // hi plane; lo = +SEQ*HD
    const size_t PL = (size_t)SEQ * HD;
    __nv_bfloat16 hi, lo;
    bsplit(qa, hi, lo); g_qp[pb + j]      = hi; g_qp[pb + PL + j]      = lo;
    bsplit(qb, hi, lo); g_qp[pb + j + 64] = hi; g_qp[pb + PL + j + 64] = lo;
    bsplit(ka, hi, lo); g_kp[pb + j]      = hi; g_kp[pb + PL + j]      = lo;
    bsplit(kb, hi, lo); g_kp[pb + j + 64] = hi; g_kp[pb + PL + j + 64] = lo;
    bsplit(v1, hi, lo); g_vp[pb + j]      = hi; g_vp[pb + PL + j]      = lo;
    bsplit(v2, hi, lo); g_vp[pb + j + 64] = hi; g_vp[pb + PL + j + 64] = lo;
}

// ---------------------------------------------------------------------------
// bf16x3 tensor-core GEMM via mma.sync (unchanged from round 3 — passing)
// ---------------------------------------------------------------------------
#define AST         40
#define STG_MAT     (128 * AST * 2)
#define STG_BYTES   (2 * STG_MAT)
#define GEMM_STAGES 3
#define GEMM_SMEM   (GEMM_STAGES * STG_BYTES)
#define GNITER      192

__device__ __forceinline__ void g_load_stage(
    uint32_t sA, uint32_t sB,
    const __nv_bfloat16* Ab, const __nv_bfloat16* Bb, int tid)
{
#pragma unroll
    for (int t = 0; t < 2; t++) {
        int c = tid + t * 256;
        int r = c >> 2, co = (c & 3) << 3;
        CP_ASYNC16(sA + (r * AST + co) * 2, Ab + (size_t)r * KPACK + co);
        CP_ASYNC16(sB + (r * AST + co) * 2, Bb + (size_t)r * KPACK + co);
    }
}

__global__ void __launch_bounds__(256, 1) tc_gemm_kernel(
    const __nv_bfloat16* __restrict__ A, const __nv_bfloat16* __restrict__ B,
    float* __restrict__ C, int ldc)
{
    extern __shared__ char smg[];
    uint32_t smb = s2u(smg);
    int tid  = threadIdx.x;
    int lane = tid & 31, wid = tid >> 5;
    int wm = (wid & 3) * 32, wn = (wid >> 2) * 64;
    int m0 = blockIdx.y * 128, n0 = blockIdx.x * 128;

    float acc[2][8][4];
#pragma unroll
    for (int i = 0; i < 2; i++)
#pragma unroll
        for (int j = 0; j < 8; j++)
#pragma unroll
            for (int k = 0; k < 4; k++) acc[i][j][k] = 0.f;

    auto chunk_off = [&](int it, int& aoff, int& boff, int& k0) {
        int pass = it >> 6;
        k0   = (it & 63) << 5;
        aoff = (pass == 2) ? 2048 : 0;
        boff = (pass == 1) ? 2048 : 0;
    };

#pragma unroll
    for (int p = 0; p < GEMM_STAGES - 1; p++) {
        int aoff, boff, k0;
        chunk_off(p, aoff, boff, k0);
        uint32_t sA = smb + p * STG_BYTES;
        g_load_stage(sA, sA + STG_MAT,
                     A + (size_t)m0 * KPACK + aoff + k0,
                     B + (size_t)n0 * KPACK + boff + k0, tid);
        CP_COMMIT();
    }

    uint32_t a_off[2][2], b_off[2][4];
#pragma unroll
    for (int ks = 0; ks < 2; ks++) {
#pragma unroll
        for (int mt = 0; mt < 2; mt++)
            a_off[ks][mt] = ((wm + mt * 16 + (lane & 15)) * AST +
                             ks * 16 + (lane >> 4) * 8) * 2;
#pragma unroll
        for (int np = 0; np < 4; np++)
            b_off[ks][np] = STG_MAT +
                ((wn + np * 16 + ((lane >> 4) & 1) * 8 + (lane & 7)) * AST +
                 ks * 16 + ((lane >> 3) & 1) * 8) * 2;
    }

    for (int it = 0; it < GNITER; ++it) {
        CP_WAIT1();
        __syncthreads();
        int nx = it + GEMM_STAGES - 1;
        if (nx < GNITER) {
            int aoff, boff, k0;
            chunk_off(nx, aoff, boff, k0);
            uint32_t sA = smb + (nx % GEMM_STAGES) * STG_BYTES;
            g_load_stage(sA, sA + STG_MAT,
                         A + (size_t)m0 * KPACK + aoff + k0,
                         B + (size_t)n0 * KPACK + boff + k0, tid);
        }
        CP_COMMIT();

        uint32_t sbase = smb + (it % GEMM_STAGES) * STG_BYTES;
#pragma unroll
        for (int ks = 0; ks < 2; ks++) {
            uint32_t afr[2][4];
#pragma unroll
            for (int mt = 0; mt < 2; mt++) LDSM4(afr[mt], sbase + a_off[ks][mt]);
#pragma unroll
            for (int np = 0; np < 4; np++) {
                uint32_t bfr[4];
                LDSM4(bfr, sbase + b_off[ks][np]);
#pragma unroll
                for (int mt = 0; mt < 2; mt++) {
                    MMA16816(acc[mt][2 * np],     afr[mt], bfr[0], bfr[1]);
                    MMA16816(acc[mt][2 * np + 1], afr[mt], bfr[2], bfr[3]);
                }
            }
        }
    }

    float* Cb = C + (size_t)(m0 + wm) * ldc + n0 + wn;
    int rq = lane >> 2, cq = (lane & 3) * 2;
#pragma unroll
    for (int mt = 0; mt < 2; mt++)
#pragma unroll
        for (int nt = 0; nt < 8; nt++) {
            *(float2*)(Cb + (size_t)(mt * 16 + rq) * ldc + nt * 8 + cq) =
                make_float2(acc[mt][nt][0], acc[mt][nt][1]);
            *(float2*)(Cb + (size_t)(mt * 16 + rq + 8) * ldc + nt * 8 + cq) =
                make_float2(acc[mt][nt][2], acc[mt][nt][3]);
        }
}

// ---------------------------------------------------------------------------
// Tensor-core flash attention (bf16x3 split, causal, online softmax).
// BQ=128 (8 warps x m16), BK=64, D=128. Q smem-resident; K/V double-buffered.
// ---------------------------------------------------------------------------
#define AKST     136                    // padded row stride (bf16 elems)
#define AROWB    (AKST * 2)             // 272 bytes
#define QPLANE   (128 * AROWB)          // 34816
#define KVPLANE  (64 * AROWB)           // 17408
#define STAGE_B  (4 * KVPLANE)          // 69632
#define ATTN_SMEM (2 * QPLANE + 2 * STAGE_B)   // 208896

__device__ __forceinline__ void load_kv_stage(
    uint32_t dst, const __nv_bfloat16* Kp, const __nv_bfloat16* Vp,
    int k0, int tid)
{
#pragma unroll
    for (int t = 0; t < 16; t++) {
        int c = tid + t * 256;
        int plane = c >> 10;          // 0:Kh 1:Kl 2:Vh 3:Vl
        int r = (c >> 4) & 63;
        int co = c & 15;
        const __nv_bfloat16* src = (plane < 2)
            ? Kp + ((size_t)plane * SEQ + k0 + r) * HD + co * 8
            : Vp + ((size_t)(plane - 2) * SEQ + k0 + r) * HD + co * 8;
        CP_ASYNC16(dst + plane * KVPLANE + r * AROWB + co * 16, src);
    }
}

__global__ void __launch_bounds__(256) attn_mma_kernel() {
    extern __shared__ char sma[];
    uint32_t smb = s2u(sma);
    int tid = threadIdx.x, lane = tid & 31, w = tid >> 5;
    int qt = (int)gridDim.x - 1 - (int)blockIdx.x;   // big tiles first
    int bh = blockIdx.y;
    int q0 = qt * 128;
    int nkt = 2 * qt + 2;

    const __nv_bfloat16* Qp = g_qp + (size_t)(bh * 2) * SEQ * HD;
    const __nv_bfloat16* Kp = g_kp + (size_t)(bh * 2) * SEQ * HD;
    const __nv_bfloat16* Vp = g_vp + (size_t)(bh * 2) * SEQ * HD;

    uint32_t sQ = smb;
    uint32_t sStage = smb + 2 * QPLANE;

    // group 0: Q (both planes) + K/V stage 0
#pragma unroll
    for (int t = 0; t < 16; t++) {
        int c = tid + t * 256;
        int plane = c >> 11, r = (c >> 4) & 127, co = c & 15;
        CP_ASYNC16(sQ + plane * QPLANE + r * AROWB + co * 16,
                   Qp + ((size_t)plane * SEQ + q0 + r) * HD + co * 8);
    }
    load_kv_stage(sStage, Kp, Vp, 0, tid);
    CP_COMMIT();

    float out[16][4];
#pragma unroll
    for (int n = 0; n < 16; n++)
#pragma unroll
        for (int e = 0; e < 4; e++) out[n][e] = 0.f;
    float m0 = -1e30f, m1 = -1e30f, l0 = 0.f, l1 = 0.f;

    int rq = lane >> 2, cq = lane & 3;
    // ldmatrix byte offsets (within plane); add kc/jj/jp terms at use
    uint32_t qoff = (uint32_t)(16 * w + (lane & 15)) * AROWB + ((lane >> 4) & 1) * 16;
    uint32_t koff = (uint32_t)(((lane >> 4) & 1) * 8 + (lane & 7)) * AROWB +
                    ((lane >> 3) & 1) * 16;
    uint32_t voff = (uint32_t)(((lane >> 3) & 1) * 8 + (lane & 7)) * AROWB +
                    ((lane >> 4) & 1) * 16;

    const float SCALE2 = 0.08838834764831845f * 1.44269504088896341f;

    for (int kt = 0; kt < nkt; kt++) {
        __syncthreads();                     // stage (kt&1)^? safe to overwrite
        if (kt + 1 < nkt)
            load_kv_stage(sStage + ((kt + 1) & 1) * STAGE_B, Kp, Vp,
                          (kt + 1) * 64, tid);
        CP_COMMIT();
        CP_WAIT1();
        __syncthreads();

        uint32_t sKh = sStage + (kt & 1) * STAGE_B;
        uint32_t sKl = sKh + KVPLANE;
        uint32_t sVh = sKh + 2 * KVPLANE;
        uint32_t sVl = sKh + 3 * KVPLANE;

        // ---- scores: S = Qh*Kh + Qh*Kl + Ql*Kh ----
        float sc[8][4];
#pragma unroll
        for (int j = 0; j < 8; j++)
#pragma unroll
            for (int e = 0; e < 4; e++) sc[j][e] = 0.f;

#pragma unroll
        for (int kc = 0; kc < 8; kc++) {
            uint32_t aqh[4], aql[4];
            LDSM4(aqh, sQ + qoff + kc * 32);
            LDSM4(aql, sQ + QPLANE + qoff + kc * 32);
#pragma unroll
            for (int jj = 0; jj < 4; jj++) {
                uint32_t bkh[4], bkl[4];
                uint32_t o = koff + (uint32_t)jj * (16 * AROWB) + kc * 32;
                LDSM4(bkh, sKh + o);
                LDSM4(bkl, sKl + o);
                MMA16816(sc[2 * jj],     aqh, bkh[0], bkh[1]);
                MMA16816(sc[2 * jj],     aqh, bkl[0], bkl[1]);
                MMA16816(sc[2 * jj],     aql, bkh[0], bkh[1]);
                MMA16816(sc[2 * jj + 1], aqh, bkh[2], bkh[3]);
                MMA16816(sc[2 * jj + 1], aqh, bkl[2], bkl[3]);
                MMA16816(sc[2 * jj + 1], aql, bkh[2], bkh[3]);
            }
        }

        // ---- scale + causal mask ----
        int k0 = kt * 64;
#pragma unroll
        for (int j = 0; j < 8; j++)
#pragma unroll
            for (int e = 0; e < 4; e++) sc[j][e] *= SCALE2;
        if (k0 + 64 > q0) {
            int rg0 = q0 + 16 * w + rq, rg1 = rg0 + 8;
#pragma unroll
            for (int j = 0; j < 8; j++) {
                int cg = k0 + 8 * j + 2 * cq;
                if (cg     > rg0) sc[j][0] = -1e30f;
                if (cg + 1 > rg0) sc[j][1] = -1e30f;
                if (cg     > rg1) sc[j][2] = -1e30f;
                if (cg + 1 > rg1) sc[j][3] = -1e30f;
            }
        }

        // ---- online softmax stats ----
        float t0 = -1e30f, t1 = -1e30f;
#pragma unroll
        for (int j = 0; j < 8; j++) {
            t0 = fmaxf(t0, fmaxf(sc[j][0], sc[j][1]));
            t1 = fmaxf(t1, fmaxf(sc[j][2], sc[j][3]));
        }
        t0 = fmaxf(t0, __shfl_xor_sync(0xffffffffu, t0, 1));
        t0 = fmaxf(t0, __shfl_xor_sync(0xffffffffu, t0, 2));
        t1 = fmaxf(t1, __shfl_xor_sync(0xffffffffu, t1, 1));
        t1 = fmaxf(t1, __shfl_xor_sync(0xffffffffu, t1, 2));
        float mn0 = fmaxf(m0, t0), mn1 = fmaxf(m1, t1);
        float al0 = ex2f(m0 - mn0), al1 = ex2f(m1 - mn1);
        m0 = mn0; m1 = mn1;
        l0 *= al0; l1 *= al1;
#pragma unroll
        for (int n = 0; n < 16; n++) {
            out[n][0] *= al0; out[n][1] *= al0;
            out[n][2] *= al1; out[n][3] *= al1;
        }

        // ---- exp + split + PV per k16 chunk ----
#pragma unroll
        for (int kc = 0; kc < 4; kc++) {
            int j0 = 2 * kc, j1 = 2 * kc + 1;
            float p00 = ex2f(sc[j0][0] - m0), p01 = ex2f(sc[j0][1] - m0);
            float p02 = ex2f(sc[j0][2] - m1), p03 = ex2f(sc[j0][3] - m1);
            float p10 = ex2f(sc[j1][0] - m0), p11 = ex2f(sc[j1][1] - m0);
            float p12 = ex2f(sc[j1][2] - m1), p13 = ex2f(sc[j1][3] - m1);
            l0 += p00 + p01 + p10 + p11;
            l1 += p02 + p03 + p12 + p13;

            uint32_t ah[4], al_[4];
            ah[0] = packbf(p01, p00);
            ah[1] = packbf(p03, p02);
            ah[2] = packbf(p11, p10);
            ah[3] = packbf(p13, p12);
            // lo residuals (bf16->f32 is a pure bit shift)
            float h;
            h = __uint_as_float(ah[0] << 16);          float q00 = p00 - h;
            h = __uint_as_float(ah[0] & 0xffff0000u);  float q01 = p01 - h;
            h = __uint_as_float(ah[1] << 16);          float q02 = p02 - h;
            h = __uint_as_float(ah[1] & 0xffff0000u);  float q03 = p03 - h;
            h = __uint_as_float(ah[2] << 16);          float q10 = p10 - h;
            h = __uint_as_float(ah[2] & 0xffff0000u);  float q11 = p11 - h;
            h = __uint_as_float(ah[3] << 16);          float q12 = p12 - h;
            h = __uint_as_float(ah[3] & 0xffff0000u);  float q13 = p13 - h;
            al_[0] = packbf(q01, q00);
            al_[1] = packbf(q03, q02);
            al_[2] = packbf(q11, q10);
            al_[3] = packbf(q13, q12);

#pragma unroll
            for (int jp = 0; jp < 8; jp++) {
                uint32_t bvh[4], bvl[4];
                uint32_t o = voff + (uint32_t)kc * (16 * AROWB) + jp * 32;
                LDSM4T(bvh, sVh + o);
                LDSM4T(bvl, sVl + o);
                MMA16816(out[2 * jp],     ah,  bvh[0], bvh[1]);
                MMA16816(out[2 * jp],     ah,  bvl[0], bvl[1]);
                MMA16816(out[2 * jp],     al_, bvh[0], bvh[1]);
                MMA16816(out[2 * jp + 1], ah,  bvh[2], bvh[3]);
                MMA16816(out[2 * jp + 1], ah,  bvl[2], bvl[3]);
                MMA16816(out[2 * jp + 1], al_, bvh[2], bvh[3]);
            }
        }
    }

    // ---- epilogue ----
    l0 += __shfl_xor_sync(0xffffffffu, l0, 1);
    l0 += __shfl_xor_sync(0xffffffffu, l0, 2);
    l1 += __shfl_xor_sync(0xffffffffu, l1, 1);
    l1 += __shfl_xor_sync(0xffffffffu, l1, 2);
    float il0 = 1.f / l0, il1 = 1.f / l1;

    int b = bh >> 4, hh = bh & 15;
    float* ob = g_ctx + ((size_t)(b * SEQ + q0 + 16 * w)) * HID + hh * HD;
#pragma unroll
    for (int nt = 0; nt < 16; nt++) {
        int col = nt * 8 + 2 * cq;
        *(float2*)(ob + (size_t)rq * HID + col) =
            make_float2(out[nt][0] * il0, out[nt][1] * il0);
        *(float2*)(ob + (size_t)(rq + 8) * HID + col) =
            make_float2(out[nt][2] * il1, out[nt][3] * il1);
    }
}

// ---------------------------------------------------------------------------
// Launch graph
// ---------------------------------------------------------------------------
extern "C" void kernel_launch(void* const* d_in, const int* in_sizes, int n_in,
                              void* d_out, int out_size) {
    const float* x    = (const float*)d_in[0];
    // d_in[1] = attn_mask (pure causal) — reproduced analytically, not read
    const float* Wqkv = (const float*)d_in[2];
    const float* Wout = (const float*)d_in[3];
    float* out = (float*)d_out;

    float *qkv_ptr = 0, *ctx_ptr = 0;
    __nv_bfloat16 *xp = 0, *wqp = 0, *wop = 0, *cxp = 0;
    cudaGetSymbolAddress((void**)&qkv_ptr, g_qkv);
    cudaGetSymbolAddress((void**)&ctx_ptr, g_ctx);
    cudaGetSymbolAddress((void**)&xp,  g_xp);
    cudaGetSymbolAddress((void**)&wqp, g_wqp);
    cudaGetSymbolAddress((void**)&wop, g_wop);
    cudaGetSymbolAddress((void**)&cxp, g_cxp);

    cudaFuncSetAttribute(tc_gemm_kernel,
                         cudaFuncAttributeMaxDynamicSharedMemorySize, GEMM_SMEM);
    cudaFuncSetAttribute(attn_mma_kernel,
                         cudaFuncAttributeMaxDynamicSharedMemorySize, ATTN_SMEM);

    rope_table_kernel<<<(SEQ * 64 + 255) / 256, 256>>>();

    pack_kernel<<<(MROWS * HID + 255) / 256, 256>>>(x, xp, MROWS * HID);
    pack_kernel<<<(QKVN  * HID + 255) / 256, 256>>>(Wqkv, wqp, QKVN * HID);
    pack_kernel<<<(HID   * HID + 255) / 256, 256>>>(Wout, wop, HID * HID);

    tc_gemm_kernel<<<dim3(QKVN / 128, MROWS / 128), 256, GEMM_SMEM>>>(
        xp, wqp, qkv_ptr, QKVN);

    qkv_pack_kernel<<<(MROWS * NH * 64) / 256, 256>>>();

    attn_mma_kernel<<<dim3(SEQ / 128, BATCH * NH), 256, ATTN_SMEM>>>();

    pack_kernel<<<(MROWS * HID + 255) / 256, 256>>>(ctx_ptr, cxp, MROWS * HID);
    tc_gemm_kernel<<<dim3(HID / 128, MROWS / 128), 256, GEMM_SMEM>>>(
        cxp, wop, out, HID);
}

// round 5
// speedup vs baseline: 5.4852x; 1.4510x over previous
#include <cuda_runtime.h>
#include <cuda_bf16.h>
#include <math.h>
#include <stdint.h>

// Problem constants
#define SEQ   2048
#define HID   2048
#define NH    16
#define HD    128
#define BATCH 2
#define MROWS (BATCH * SEQ)     // 4096
#define QKVN  (3 * HID)         // 6144
#define KPACK 4096              // packed row length: [hi(2048) | lo(2048)]

// ---------------------------------------------------------------------------
// Scratch (device globals — no runtime allocation allowed)
// ---------------------------------------------------------------------------
__device__ __align__(16) float g_qkv[(size_t)MROWS * QKVN];    // fp32 QKV
__device__ __align__(16) float g_ctx[(size_t)MROWS * HID];     // fp32 attn out
__device__ __align__(16) float g_cos[SEQ * 64];
__device__ __align__(16) float g_sin[SEQ * 64];
__device__ __align__(16) __nv_bfloat16 g_xp  [(size_t)MROWS * KPACK];
__device__ __align__(16) __nv_bfloat16 g_wqp [(size_t)QKVN  * KPACK];
__device__ __align__(16) __nv_bfloat16 g_wop [(size_t)HID   * KPACK];
__device__ __align__(16) __nv_bfloat16 g_cxp [(size_t)MROWS * KPACK];
// attention operands: [bh*2 + plane(hi=0,lo=1)][s][128]
__device__ __align__(16) __nv_bfloat16 g_qp[(size_t)BATCH * NH * 2 * SEQ * HD];
__device__ __align__(16) __nv_bfloat16 g_kp[(size_t)BATCH * NH * 2 * SEQ * HD];
__device__ __align__(16) __nv_bfloat16 g_vp[(size_t)BATCH * NH * 2 * SEQ * HD];

// ---------------------------------------------------------------------------
// PTX helpers (arch-agnostic: cp.async / ldmatrix / mma.sync only)
// ---------------------------------------------------------------------------
__device__ __forceinline__ uint32_t s2u(const void* p) {
    uint32_t a;
    asm("{ .reg .u64 t; cvta.to.shared.u64 t, %1; cvt.u32.u64 %0, t; }"
        : "=r"(a) : "l"(p));
    return a;
}

#define CP_ASYNC16(saddr, gptr) \
    asm volatile("cp.async.cg.shared.global [%0], [%1], 16;" \
                 :: "r"(saddr), "l"(gptr))
#define CP_COMMIT()  asm volatile("cp.async.commit_group;" ::: "memory")
#define CP_WAIT1()   asm volatile("cp.async.wait_group 1;" ::: "memory")
#define CP_WAIT2()   asm volatile("cp.async.wait_group 2;" ::: "memory")

#define LDSM4(r, addr)                                                        \
    asm volatile("ldmatrix.sync.aligned.m8n8.x4.shared.b16 {%0,%1,%2,%3}, [%4];" \
        : "=r"((r)[0]), "=r"((r)[1]), "=r"((r)[2]), "=r"((r)[3]) : "r"(addr))
#define LDSM4T(r, addr)                                                       \
    asm volatile("ldmatrix.sync.aligned.m8n8.x4.trans.shared.b16 {%0,%1,%2,%3}, [%4];" \
        : "=r"((r)[0]), "=r"((r)[1]), "=r"((r)[2]), "=r"((r)[3]) : "r"(addr))

#define MMA16816(d, a, b0, b1)                                                \
    asm volatile("mma.sync.aligned.m16n8k16.row.col.f32.bf16.bf16.f32 "       \
        "{%0,%1,%2,%3},{%4,%5,%6,%7},{%8,%9},{%0,%1,%2,%3};"                  \
        : "+f"((d)[0]), "+f"((d)[1]), "+f"((d)[2]), "+f"((d)[3])              \
        : "r"((a)[0]), "r"((a)[1]), "r"((a)[2]), "r"((a)[3]),                 \
          "r"(b0), "r"(b1))

__device__ __forceinline__ float ex2f(float x) {
    float y;
    asm("ex2.approx.ftz.f32 %0, %1;" : "=f"(y) : "f"(x));
    return y;
}
__device__ __forceinline__ uint32_t packbf(float hi, float lo) {
    uint32_t d;
    asm("cvt.rn.bf16x2.f32 %0, %1, %2;" : "=r"(d) : "f"(hi), "f"(lo));
    return d;
}

// ---------------------------------------------------------------------------
// RoPE table (reference-matching numerics)
// ---------------------------------------------------------------------------
__global__ void rope_table_kernel() {
    int idx = blockIdx.x * blockDim.x + threadIdx.x;
    if (idx >= SEQ * 64) return;
    int s = idx >> 6;
    int j = idx & 63;
    double inv = exp(-((double)j / 64.0) * log(10000.0));
    float  invf = (float)inv;
    float  ang  = (float)s * invf;
    g_cos[idx] = (float)cos((double)ang);
    g_sin[idx] = (float)sin((double)ang);
}

// ---------------------------------------------------------------------------
// fp32 -> split bf16 pack: P[row][0:2048]=hi, P[row][2048:4096]=lo
// ---------------------------------------------------------------------------
__global__ void pack_kernel(const float* __restrict__ X,
                            __nv_bfloat16* __restrict__ P, int n) {
    int i = blockIdx.x * 256 + threadIdx.x;
    if (i >= n) return;
    int row = i >> 11, col = i & 2047;
    float v = X[i];
    __nv_bfloat16 h = __float2bfloat16(v);
    float hf = __bfloat162float(h);
    P[(size_t)row * KPACK + col]        = h;
    P[(size_t)row * KPACK + 2048 + col] = __float2bfloat16(v - hf);
}

// ---------------------------------------------------------------------------
// QKV pack: RoPE on q,k + hi/lo bf16 split of q,k,v into planar layouts.
// ---------------------------------------------------------------------------
__device__ __forceinline__ void bsplit(float v, __nv_bfloat16& h, __nv_bfloat16& l) {
    h = __float2bfloat16(v);
    l = __float2bfloat16(v - __bfloat162float(h));
}

__global__ void qkv_pack_kernel() {
    int idx = blockIdx.x * blockDim.x + threadIdx.x;   // MROWS*NH*64
    int j   = idx & 63;
    int h   = (idx >> 6) & (NH - 1);
    int row = idx >> 10;
    int s   = row & (SEQ - 1);
    int b   = row >> 11;
    int bh  = b * NH + h;
    float c  = g_cos[(s << 6) + j];
    float sn = g_sin[(s << 6) + j];
    const float* base = g_qkv + (size_t)row * QKVN + h * HD;

    float q1 = base[j], q2 = base[j + 64];
    float qa = q1 * c - q2 * sn;
    float qb = q2 * c + q1 * sn;
    float k1 = base[HID + j], k2 = base[HID + j + 64];
    float ka = k1 * c - k2 * sn;
    float kb = k2 * c + k1 * sn;
    float v1 = base[2 * HID + j], v2 = base[2 * HID + j + 64];

    size_t pb = ((size_t)(bh * 2) * SEQ + s) * HD;   // hi plane; lo = +SEQ*HD
    const size_t PL = (size_t)SEQ * HD;
    __nv_bfloat16 hi, lo;
    bsplit(qa, hi, lo); g_qp[pb + j]      = hi; g_qp[pb + PL + j]      = lo;
    bsplit(qb, hi, lo); g_qp[pb + j + 64] = hi; g_qp[pb + PL + j + 64] = lo;
    bsplit(ka, hi, lo); g_kp[pb + j]      = hi; g_kp[pb + PL + j]      = lo;
    bsplit(kb, hi, lo); g_kp[pb + j + 64] = hi; g_kp[pb + PL + j + 64] = lo;
    bsplit(v1, hi, lo); g_vp[pb + j]      = hi; g_vp[pb + PL + j]      = lo;
    bsplit(v2, hi, lo); g_vp[pb + j + 64] = hi; g_vp[pb + PL + j + 64] = lo;
}

// ---------------------------------------------------------------------------
// bf16x3 tensor-core GEMM v2: 4 warps, 64x64 warp tiles, 4-stage cp.async
// ring, ONE __syncthreads per K-chunk.
// C[M,N] = A_f32 B_f32^T; A packed [M][4096], B packed [N][4096].
// ---------------------------------------------------------------------------
#define AST         40                   // padded smem row stride (bf16)
#define STG_MAT     (128 * AST * 2)      // 10240 B
#define STG_BYTES   (2 * STG_MAT)        // 20480 B
#define GEMM_STAGES 4
#define GEMM_SMEM   (GEMM_STAGES * STG_BYTES)   // 81920
#define GNITER      192                  // 3 passes x 64 chunks of K=32

__device__ __forceinline__ void g_load_stage(
    uint32_t sA, const __nv_bfloat16* Ab, const __nv_bfloat16* Bb, int tid)
{
#pragma unroll
    for (int t = 0; t < 4; t++) {
        int c = tid + t * 128;               // 0..511
        int r = c >> 2, co = (c & 3) << 3;   // row, col elem (8 bf16 = 16 B)
        CP_ASYNC16(sA + (r * AST + co) * 2, Ab + (size_t)r * KPACK + co);
        CP_ASYNC16(sA + STG_MAT + (r * AST + co) * 2, Bb + (size_t)r * KPACK + co);
    }
}

__global__ void __launch_bounds__(128) tc_gemm_kernel(
    const __nv_bfloat16* __restrict__ A, const __nv_bfloat16* __restrict__ B,
    float* __restrict__ C, int ldc)
{
    extern __shared__ char smg[];
    uint32_t smb = s2u(smg);
    int tid  = threadIdx.x;
    int lane = tid & 31, wid = tid >> 5;
    int wm = (wid & 1) * 64, wn = (wid >> 1) * 64;
    int m0 = blockIdx.y * 128, n0 = blockIdx.x * 128;

    float acc[4][8][4];
#pragma unroll
    for (int i = 0; i < 4; i++)
#pragma unroll
        for (int j = 0; j < 8; j++)
#pragma unroll
            for (int k = 0; k < 4; k++) acc[i][j][k] = 0.f;

    auto chunk_off = [&](int it, int& aoff, int& boff, int& k0) {
        int pass = it >> 6;
        k0   = (it & 63) << 5;
        aoff = (pass == 2) ? 2048 : 0;
        boff = (pass == 1) ? 2048 : 0;
    };

    // Prologue: stages 0..2
#pragma unroll
    for (int p = 0; p < GEMM_STAGES - 1; p++) {
        int aoff, boff, k0;
        chunk_off(p, aoff, boff, k0);
        g_load_stage(smb + p * STG_BYTES,
                     A + (size_t)m0 * KPACK + aoff + k0,
                     B + (size_t)n0 * KPACK + boff + k0, tid);
        CP_COMMIT();
    }

    // ldmatrix byte offsets (per ks / per 16-row tile)
    uint32_t a_off[2][4], b_off[2][4];
#pragma unroll
    for (int ks = 0; ks < 2; ks++) {
#pragma unroll
        for (int mt = 0; mt < 4; mt++)
            a_off[ks][mt] = ((wm + mt * 16 + (lane & 15)) * AST +
                             ks * 16 + (lane >> 4) * 8) * 2;
#pragma unroll
        for (int np = 0; np < 4; np++)
            b_off[ks][np] = STG_MAT +
                ((wn + np * 16 + ((lane >> 4) & 1) * 8 + (lane & 7)) * AST +
                 ks * 16 + ((lane >> 3) & 1) * 8) * 2;
    }

    for (int it = 0; it < GNITER; ++it) {
        CP_WAIT2();                       // stage `it` resident
        __syncthreads();                  // all warps done consuming stage it-1
        int nx = it + GEMM_STAGES - 1;
        if (nx < GNITER) {
            int aoff, boff, k0;
            chunk_off(nx, aoff, boff, k0);
            g_load_stage(smb + (nx & (GEMM_STAGES - 1)) * STG_BYTES,
                         A + (size_t)m0 * KPACK + aoff + k0,
                         B + (size_t)n0 * KPACK + boff + k0, tid);
        }
        CP_COMMIT();

        uint32_t sbase = smb + (it & (GEMM_STAGES - 1)) * STG_BYTES;
#pragma unroll
        for (int ks = 0; ks < 2; ks++) {
            uint32_t afr[4][4];
#pragma unroll
            for (int mt = 0; mt < 4; mt++) LDSM4(afr[mt], sbase + a_off[ks][mt]);
#pragma unroll
            for (int np = 0; np < 4; np++) {
                uint32_t bfr[4];
                LDSM4(bfr, sbase + b_off[ks][np]);
#pragma unroll
                for (int mt = 0; mt < 4; mt++) {
                    MMA16816(acc[mt][2 * np],     afr[mt], bfr[0], bfr[1]);
                    MMA16816(acc[mt][2 * np + 1], afr[mt], bfr[2], bfr[3]);
                }
            }
        }
    }

    // Epilogue
    float* Cb = C + (size_t)(m0 + wm) * ldc + n0 + wn;
    int rq = lane >> 2, cq = (lane & 3) * 2;
#pragma unroll
    for (int mt = 0; mt < 4; mt++)
#pragma unroll
        for (int nt = 0; nt < 8; nt++) {
            *(float2*)(Cb + (size_t)(mt * 16 + rq) * ldc + nt * 8 + cq) =
                make_float2(acc[mt][nt][0], acc[mt][nt][1]);
            *(float2*)(Cb + (size_t)(mt * 16 + rq + 8) * ldc + nt * 8 + cq) =
                make_float2(acc[mt][nt][2], acc[mt][nt][3]);
        }
}

// ---------------------------------------------------------------------------
// Tensor-core flash attention (bf16x3 split, causal, online softmax).
// Unchanged from round 4 (passing).
// ---------------------------------------------------------------------------
#define AKST     136
#define AROWB    (AKST * 2)
#define QPLANE   (128 * AROWB)
#define KVPLANE  (64 * AROWB)
#define STAGE_B  (4 * KVPLANE)
#define ATTN_SMEM (2 * QPLANE + 2 * STAGE_B)

__device__ __forceinline__ void load_kv_stage(
    uint32_t dst, const __nv_bfloat16* Kp, const __nv_bfloat16* Vp,
    int k0, int tid)
{
#pragma unroll
    for (int t = 0; t < 16; t++) {
        int c = tid + t * 256;
        int plane = c >> 10;
        int r = (c >> 4) & 63;
        int co = c & 15;
        const __nv_bfloat16* src = (plane < 2)
            ? Kp + ((size_t)plane * SEQ + k0 + r) * HD + co * 8
            : Vp + ((size_t)(plane - 2) * SEQ + k0 + r) * HD + co * 8;
        CP_ASYNC16(dst + plane * KVPLANE + r * AROWB + co * 16, src);
    }
}

__global__ void __launch_bounds__(256) attn_mma_kernel() {
    extern __shared__ char sma[];
    uint32_t smb = s2u(sma);
    int tid = threadIdx.x, lane = tid & 31, w = tid >> 5;
    int qt = (int)gridDim.x - 1 - (int)blockIdx.x;
    int bh = blockIdx.y;
    int q0 = qt * 128;
    int nkt = 2 * qt + 2;

    const __nv_bfloat16* Qp = g_qp + (size_t)(bh * 2) * SEQ * HD;
    const __nv_bfloat16* Kp = g_kp + (size_t)(bh * 2) * SEQ * HD;
    const __nv_bfloat16* Vp = g_vp + (size_t)(bh * 2) * SEQ * HD;

    uint32_t sQ = smb;
    uint32_t sStage = smb + 2 * QPLANE;

#pragma unroll
    for (int t = 0; t < 16; t++) {
        int c = tid + t * 256;
        int plane = c >> 11, r = (c >> 4) & 127, co = c & 15;
        CP_ASYNC16(sQ + plane * QPLANE + r * AROWB + co * 16,
                   Qp + ((size_t)plane * SEQ + q0 + r) * HD + co * 8);
    }
    load_kv_stage(sStage, Kp, Vp, 0, tid);
    CP_COMMIT();

    float out[16][4];
#pragma unroll
    for (int n = 0; n < 16; n++)
#pragma unroll
        for (int e = 0; e < 4; e++) out[n][e] = 0.f;
    float m0 = -1e30f, m1 = -1e30f, l0 = 0.f, l1 = 0.f;

    int rq = lane >> 2, cq = lane & 3;
    uint32_t qoff = (uint32_t)(16 * w + (lane & 15)) * AROWB + ((lane >> 4) & 1) * 16;
    uint32_t koff = (uint32_t)(((lane >> 4) & 1) * 8 + (lane & 7)) * AROWB +
                    ((lane >> 3) & 1) * 16;
    uint32_t voff = (uint32_t)(((lane >> 3) & 1) * 8 + (lane & 7)) * AROWB +
                    ((lane >> 4) & 1) * 16;

    const float SCALE2 = 0.08838834764831845f * 1.44269504088896341f;

    for (int kt = 0; kt < nkt; kt++) {
        __syncthreads();
        if (kt + 1 < nkt)
            load_kv_stage(sStage + ((kt + 1) & 1) * STAGE_B, Kp, Vp,
                          (kt + 1) * 64, tid);
        CP_COMMIT();
        CP_WAIT1();
        __syncthreads();

        uint32_t sKh = sStage + (kt & 1) * STAGE_B;
        uint32_t sKl = sKh + KVPLANE;
        uint32_t sVh = sKh + 2 * KVPLANE;
        uint32_t sVl = sKh + 3 * KVPLANE;

        float sc[8][4];
#pragma unroll
        for (int j = 0; j < 8; j++)
#pragma unroll
            for (int e = 0; e < 4; e++) sc[j][e] = 0.f;

#pragma unroll
        for (int kc = 0; kc < 8; kc++) {
            uint32_t aqh[4], aql[4];
            LDSM4(aqh, sQ + qoff + kc * 32);
            LDSM4(aql, sQ + QPLANE + qoff + kc * 32);
#pragma unroll
            for (int jj = 0; jj < 4; jj++) {
                uint32_t bkh[4], bkl[4];
                uint32_t o = koff + (uint32_t)jj * (16 * AROWB) + kc * 32;
                LDSM4(bkh, sKh + o);
                LDSM4(bkl, sKl + o);
                MMA16816(sc[2 * jj],     aqh, bkh[0], bkh[1]);
                MMA16816(sc[2 * jj],     aqh, bkl[0], bkl[1]);
                MMA16816(sc[2 * jj],     aql, bkh[0], bkh[1]);
                MMA16816(sc[2 * jj + 1], aqh, bkh[2], bkh[3]);
                MMA16816(sc[2 * jj + 1], aqh, bkl[2], bkl[3]);
                MMA16816(sc[2 * jj + 1], aql, bkh[2], bkh[3]);
            }
        }

        int k0 = kt * 64;
#pragma unroll
        for (int j = 0; j < 8; j++)
#pragma unroll
            for (int e = 0; e < 4; e++) sc[j][e] *= SCALE2;
        if (k0 + 64 > q0) {
            int rg0 = q0 + 16 * w + rq, rg1 = rg0 + 8;
#pragma unroll
            for (int j = 0; j < 8; j++) {
                int cg = k0 + 8 * j + 2 * cq;
                if (cg     > rg0) sc[j][0] = -1e30f;
                if (cg + 1 > rg0) sc[j][1] = -1e30f;
                if (cg     > rg1) sc[j][2] = -1e30f;
                if (cg + 1 > rg1) sc[j][3] = -1e30f;
            }
        }

        float t0 = -1e30f, t1 = -1e30f;
#pragma unroll
        for (int j = 0; j < 8; j++) {
            t0 = fmaxf(t0, fmaxf(sc[j][0], sc[j][1]));
            t1 = fmaxf(t1, fmaxf(sc[j][2], sc[j][3]));
        }
        t0 = fmaxf(t0, __shfl_xor_sync(0xffffffffu, t0, 1));
        t0 = fmaxf(t0, __shfl_xor_sync(0xffffffffu, t0, 2));
        t1 = fmaxf(t1, __shfl_xor_sync(0xffffffffu, t1, 1));
        t1 = fmaxf(t1, __shfl_xor_sync(0xffffffffu, t1, 2));
        float mn0 = fmaxf(m0, t0), mn1 = fmaxf(m1, t1);
        float al0 = ex2f(m0 - mn0), al1 = ex2f(m1 - mn1);
        m0 = mn0; m1 = mn1;
        l0 *= al0; l1 *= al1;
#pragma unroll
        for (int n = 0; n < 16; n++) {
            out[n][0] *= al0; out[n][1] *= al0;
            out[n][2] *= al1; out[n][3] *= al1;
        }

#pragma unroll
        for (int kc = 0; kc < 4; kc++) {
            int j0 = 2 * kc, j1 = 2 * kc + 1;
            float p00 = ex2f(sc[j0][0] - m0), p01 = ex2f(sc[j0][1] - m0);
            float p02 = ex2f(sc[j0][2] - m1), p03 = ex2f(sc[j0][3] - m1);
            float p10 = ex2f(sc[j1][0] - m0), p11 = ex2f(sc[j1][1] - m0);
            float p12 = ex2f(sc[j1][2] - m1), p13 = ex2f(sc[j1][3] - m1);
            l0 += p00 + p01 + p10 + p11;
            l1 += p02 + p03 + p12 + p13;

            uint32_t ah[4], al_[4];
            ah[0] = packbf(p01, p00);
            ah[1] = packbf(p03, p02);
            ah[2] = packbf(p11, p10);
            ah[3] = packbf(p13, p12);
            float h;
            h = __uint_as_float(ah[0] << 16);          float q00 = p00 - h;
            h = __uint_as_float(ah[0] & 0xffff0000u);  float q01 = p01 - h;
            h = __uint_as_float(ah[1] << 16);          float q02 = p02 - h;
            h = __uint_as_float(ah[1] & 0xffff0000u);  float q03 = p03 - h;
            h = __uint_as_float(ah[2] << 16);          float q10 = p10 - h;
            h = __uint_as_float(ah[2] & 0xffff0000u);  float q11 = p11 - h;
            h = __uint_as_float(ah[3] << 16);          float q12 = p12 - h;
            h = __uint_as_float(ah[3] & 0xffff0000u);  float q13 = p13 - h;
            al_[0] = packbf(q01, q00);
            al_[1] = packbf(q03, q02);
            al_[2] = packbf(q11, q10);
            al_[3] = packbf(q13, q12);

#pragma unroll
            for (int jp = 0; jp < 8; jp++) {
                uint32_t bvh[4], bvl[4];
                uint32_t o = voff + (uint32_t)kc * (16 * AROWB) + jp * 32;
                LDSM4T(bvh, sVh + o);
                LDSM4T(bvl, sVl + o);
                MMA16816(out[2 * jp],     ah,  bvh[0], bvh[1]);
                MMA16816(out[2 * jp],     ah,  bvl[0], bvl[1]);
                MMA16816(out[2 * jp],     al_, bvh[0], bvh[1]);
                MMA16816(out[2 * jp + 1], ah,  bvh[2], bvh[3]);
                MMA16816(out[2 * jp + 1], ah,  bvl[2], bvl[3]);
                MMA16816(out[2 * jp + 1], al_, bvh[2], bvh[3]);
            }
        }
    }

    l0 += __shfl_xor_sync(0xffffffffu, l0, 1);
    l0 += __shfl_xor_sync(0xffffffffu, l0, 2);
    l1 += __shfl_xor_sync(0xffffffffu, l1, 1);
    l1 += __shfl_xor_sync(0xffffffffu, l1, 2);
    float il0 = 1.f / l0, il1 = 1.f / l1;

    int b = bh >> 4, hh = bh & 15;
    float* ob = g_ctx + ((size_t)(b * SEQ + q0 + 16 * w)) * HID + hh * HD;
#pragma unroll
    for (int nt = 0; nt < 16; nt++) {
        int col = nt * 8 + 2 * cq;
        *(float2*)(ob + (size_t)rq * HID + col) =
            make_float2(out[nt][0] * il0, out[nt][1] * il0);
        *(float2*)(ob + (size_t)(rq + 8) * HID + col) =
            make_float2(out[nt][2] * il1, out[nt][3] * il1);
    }
}

// ---------------------------------------------------------------------------
// Launch graph. Order chosen so launch idx 3 (the ncu capture slot) is the
// QKV tc_gemm — we need its roofline next round.
// ---------------------------------------------------------------------------
extern "C" void kernel_launch(void* const* d_in, const int* in_sizes, int n_in,
                              void* d_out, int out_size) {
    const float* x    = (const float*)d_in[0];
    // d_in[1] = attn_mask (pure causal) — reproduced analytically, not read
    const float* Wqkv = (const float*)d_in[2];
    const float* Wout = (const float*)d_in[3];
    float* out = (float*)d_out;

    float *qkv_ptr = 0, *ctx_ptr = 0;
    __nv_bfloat16 *xp = 0, *wqp = 0, *wop = 0, *cxp = 0;
    cudaGetSymbolAddress((void**)&qkv_ptr, g_qkv);
    cudaGetSymbolAddress((void**)&ctx_ptr, g_ctx);
    cudaGetSymbolAddress((void**)&xp,  g_xp);
    cudaGetSymbolAddress((void**)&wqp, g_wqp);
    cudaGetSymbolAddress((void**)&wop, g_wop);
    cudaGetSymbolAddress((void**)&cxp, g_cxp);

    cudaFuncSetAttribute(tc_gemm_kernel,
                         cudaFuncAttributeMaxDynamicSharedMemorySize, GEMM_SMEM);
    cudaFuncSetAttribute(attn_mma_kernel,
                         cudaFuncAttributeMaxDynamicSharedMemorySize, ATTN_SMEM);

    // idx 0..2: packs
    pack_kernel<<<(MROWS * HID + 255) / 256, 256>>>(x, xp, MROWS * HID);
    pack_kernel<<<(QKVN  * HID + 255) / 256, 256>>>(Wqkv, wqp, QKVN * HID);
    pack_kernel<<<(HID   * HID + 255) / 256, 256>>>(Wout, wop, HID * HID);

    // idx 3: QKV GEMM (ncu capture slot)
    tc_gemm_kernel<<<dim3(QKVN / 128, MROWS / 128), 128, GEMM_SMEM>>>(
        xp, wqp, qkv_ptr, QKVN);

    // idx 4..5: RoPE table + qkv pack
    rope_table_kernel<<<(SEQ * 64 + 255) / 256, 256>>>();
    qkv_pack_kernel<<<(MROWS * NH * 64) / 256, 256>>>();

    // idx 6: attention
    attn_mma_kernel<<<dim3(SEQ / 128, BATCH * NH), 256, ATTN_SMEM>>>();

    // idx 7..8: ctx pack + output GEMM
    pack_kernel<<<(MROWS * HID + 255) / 256, 256>>>(ctx_ptr, cxp, MROWS * HID);
    tc_gemm_kernel<<<dim3(HID / 128, MROWS / 128), 128, GEMM_SMEM>>>(
        cxp, wop, out, HID);
}

// round 6
// speedup vs baseline: 5.8902x; 1.0738x over previous
#include <cuda_runtime.h>
#include <cuda_bf16.h>
#include <math.h>
#include <stdint.h>

// Problem constants
#define SEQ   2048
#define HID   2048
#define NH    16
#define HD    128
#define BATCH 2
#define MROWS (BATCH * SEQ)     // 4096
#define QKVN  (3 * HID)         // 6144
#define KPACK 4096              // packed row length: [hi(2048) | lo(2048)]

// ---------------------------------------------------------------------------
// Scratch (device globals — no runtime allocation allowed)
// ---------------------------------------------------------------------------
__device__ __align__(16) float g_qkv[(size_t)MROWS * QKVN];    // fp32 QKV
__device__ __align__(16) float g_ctx[(size_t)MROWS * HID];     // fp32 attn out
__device__ __align__(16) float g_cos[SEQ * 64];
__device__ __align__(16) float g_sin[SEQ * 64];
__device__ __align__(16) __nv_bfloat16 g_xp  [(size_t)MROWS * KPACK];
__device__ __align__(16) __nv_bfloat16 g_wqp [(size_t)QKVN  * KPACK];
__device__ __align__(16) __nv_bfloat16 g_wop [(size_t)HID   * KPACK];
__device__ __align__(16) __nv_bfloat16 g_cxp [(size_t)MROWS * KPACK];
// attention operands: [bh*2 + plane(hi=0,lo=1)][s][128]
__device__ __align__(16) __nv_bfloat16 g_qp[(size_t)BATCH * NH * 2 * SEQ * HD];
__device__ __align__(16) __nv_bfloat16 g_kp[(size_t)BATCH * NH * 2 * SEQ * HD];
__device__ __align__(16) __nv_bfloat16 g_vp[(size_t)BATCH * NH * 2 * SEQ * HD];

// ---------------------------------------------------------------------------
// PTX helpers (arch-agnostic: cp.async / ldmatrix / mma.sync only)
// ---------------------------------------------------------------------------
__device__ __forceinline__ uint32_t s2u(const void* p) {
    uint32_t a;
    asm("{ .reg .u64 t; cvta.to.shared.u64 t, %1; cvt.u32.u64 %0, t; }"
        : "=r"(a) : "l"(p));
    return a;
}

#define CP_ASYNC16(saddr, gptr) \
    asm volatile("cp.async.cg.shared.global [%0], [%1], 16;" \
                 :: "r"(saddr), "l"(gptr))
#define CP_COMMIT()  asm volatile("cp.async.commit_group;" ::: "memory")
#define CP_WAIT1()   asm volatile("cp.async.wait_group 1;" ::: "memory")
#define CP_WAIT2()   asm volatile("cp.async.wait_group 2;" ::: "memory")

#define LDSM4(r, addr)                                                        \
    asm volatile("ldmatrix.sync.aligned.m8n8.x4.shared.b16 {%0,%1,%2,%3}, [%4];" \
        : "=r"((r)[0]), "=r"((r)[1]), "=r"((r)[2]), "=r"((r)[3]) : "r"(addr))
#define LDSM4T(r, addr)                                                       \
    asm volatile("ldmatrix.sync.aligned.m8n8.x4.trans.shared.b16 {%0,%1,%2,%3}, [%4];" \
        : "=r"((r)[0]), "=r"((r)[1]), "=r"((r)[2]), "=r"((r)[3]) : "r"(addr))

#define MMA16816(d, a, b0, b1)                                                \
    asm volatile("mma.sync.aligned.m16n8k16.row.col.f32.bf16.bf16.f32 "       \
        "{%0,%1,%2,%3},{%4,%5,%6,%7},{%8,%9},{%0,%1,%2,%3};"                  \
        : "+f"((d)[0]), "+f"((d)[1]), "+f"((d)[2]), "+f"((d)[3])              \
        : "r"((a)[0]), "r"((a)[1]), "r"((a)[2]), "r"((a)[3]),                 \
          "r"(b0), "r"(b1))

__device__ __forceinline__ float ex2f(float x) {
    float y;
    asm("ex2.approx.ftz.f32 %0, %1;" : "=f"(y) : "f"(x));
    return y;
}
__device__ __forceinline__ uint32_t packbf(float hi, float lo) {
    uint32_t d;
    asm("cvt.rn.bf16x2.f32 %0, %1, %2;" : "=r"(d) : "f"(hi), "f"(lo));
    return d;
}

// ---------------------------------------------------------------------------
// RoPE table (reference-matching numerics)
// ---------------------------------------------------------------------------
__global__ void rope_table_kernel() {
    int idx = blockIdx.x * blockDim.x + threadIdx.x;
    if (idx >= SEQ * 64) return;
    int s = idx >> 6;
    int j = idx & 63;
    double inv = exp(-((double)j / 64.0) * log(10000.0));
    float  invf = (float)inv;
    float  ang  = (float)s * invf;
    g_cos[idx] = (float)cos((double)ang);
    g_sin[idx] = (float)sin((double)ang);
}

// ---------------------------------------------------------------------------
// fp32 -> split bf16 pack: P[row][0:2048]=hi, P[row][2048:4096]=lo
// ---------------------------------------------------------------------------
__global__ void pack_kernel(const float* __restrict__ X,
                            __nv_bfloat16* __restrict__ P, int n) {
    int i = blockIdx.x * 256 + threadIdx.x;
    if (i >= n) return;
    int row = i >> 11, col = i & 2047;
    float v = X[i];
    __nv_bfloat16 h = __float2bfloat16(v);
    float hf = __bfloat162float(h);
    P[(size_t)row * KPACK + col]        = h;
    P[(size_t)row * KPACK + 2048 + col] = __float2bfloat16(v - hf);
}

// ---------------------------------------------------------------------------
// QKV pack: RoPE on q,k + hi/lo bf16 split of q,k,v into planar layouts.
// ---------------------------------------------------------------------------
__device__ __forceinline__ void bsplit(float v, __nv_bfloat16& h, __nv_bfloat16& l) {
    h = __float2bfloat16(v);
    l = __float2bfloat16(v - __bfloat162float(h));
}

__global__ void qkv_pack_kernel() {
    int idx = blockIdx.x * blockDim.x + threadIdx.x;   // MROWS*NH*64
    int j   = idx & 63;
    int h   = (idx >> 6) & (NH - 1);
    int row = idx >> 10;
    int s   = row & (SEQ - 1);
    int b   = row >> 11;
    int bh  = b * NH + h;
    float c  = g_cos[(s << 6) + j];
    float sn = g_sin[(s << 6) + j];
    const float* base = g_qkv + (size_t)row * QKVN + h * HD;

    float q1 = base[j], q2 = base[j + 64];
    float qa = q1 * c - q2 * sn;
    float qb = q2 * c + q1 * sn;
    float k1 = base[HID + j], k2 = base[HID + j + 64];
    float ka = k1 * c - k2 * sn;
    float kb = k2 * c + k1 * sn;
    float v1 = base[2 * HID + j], v2 = base[2 * HID + j + 64];

    size_t pb = ((size_t)(bh * 2) * SEQ + s) * HD;   // hi plane; lo = +SEQ*HD
    const size_t PL = (size_t)SEQ * HD;
    __nv_bfloat16 hi, lo;
    bsplit(qa, hi, lo); g_qp[pb + j]      = hi; g_qp[pb + PL + j]      = lo;
    bsplit(qb, hi, lo); g_qp[pb + j + 64] = hi; g_qp[pb + PL + j + 64] = lo;
    bsplit(ka, hi, lo); g_kp[pb + j]      = hi; g_kp[pb + PL + j]      = lo;
    bsplit(kb, hi, lo); g_kp[pb + j + 64] = hi; g_kp[pb + PL + j + 64] = lo;
    bsplit(v1, hi, lo); g_vp[pb + j]      = hi; g_vp[pb + PL + j]      = lo;
    bsplit(v2, hi, lo); g_vp[pb + j + 64] = hi; g_vp[pb + PL + j + 64] = lo;
}

// ---------------------------------------------------------------------------
// bf16x3 tensor-core GEMM v3: 4 warps, 64x64 warp tiles, 4-stage cp.async
// ring, canonical software-pipelined fragments (frag double-buffer across
// k-steps AND across the stage boundary so LDSM overlaps MMA).
// C[M,N] = A_f32 B_f32^T; A packed [M][4096], B packed [N][4096].
// ---------------------------------------------------------------------------
#define AST         40                   // padded smem row stride (bf16)
#define STG_MAT     (128 * AST * 2)      // 10240 B
#define STG_BYTES   (2 * STG_MAT)        // 20480 B
#define GEMM_STAGES 4
#define GEMM_SMEM   (GEMM_STAGES * STG_BYTES)   // 81920
#define GNITER      192                  // 3 passes x 64 chunks of K=32

__device__ __forceinline__ void g_load_stage(
    uint32_t sA, const __nv_bfloat16* Ab, const __nv_bfloat16* Bb, int tid)
{
#pragma unroll
    for (int t = 0; t < 4; t++) {
        int c = tid + t * 128;               // 0..511
        int r = c >> 2, co = (c & 3) << 3;   // row, col elem (8 bf16 = 16 B)
        CP_ASYNC16(sA + (r * AST + co) * 2, Ab + (size_t)r * KPACK + co);
        CP_ASYNC16(sA + STG_MAT + (r * AST + co) * 2, Bb + (size_t)r * KPACK + co);
    }
}

__global__ void __launch_bounds__(128, 2) tc_gemm_kernel(
    const __nv_bfloat16* __restrict__ A, const __nv_bfloat16* __restrict__ B,
    float* __restrict__ C, int ldc)
{
    extern __shared__ char smg[];
    uint32_t smb = s2u(smg);
    int tid  = threadIdx.x;
    int lane = tid & 31, wid = tid >> 5;
    int wm = (wid & 1) * 64, wn = (wid >> 1) * 64;
    int m0 = blockIdx.y * 128, n0 = blockIdx.x * 128;

    float acc[4][8][4];
#pragma unroll
    for (int i = 0; i < 4; i++)
#pragma unroll
        for (int j = 0; j < 8; j++)
#pragma unroll
            for (int k = 0; k < 4; k++) acc[i][j][k] = 0.f;

    auto chunk_off = [&](int it, int& aoff, int& boff, int& k0) {
        int pass = it >> 6;
        k0   = (it & 63) << 5;
        aoff = (pass == 2) ? 2048 : 0;
        boff = (pass == 1) ? 2048 : 0;
    };

    // ldmatrix byte offsets (per ks / per 16-row tile)
    uint32_t a_off[2][4], b_off[2][4];
#pragma unroll
    for (int ks = 0; ks < 2; ks++) {
#pragma unroll
        for (int mt = 0; mt < 4; mt++)
            a_off[ks][mt] = ((wm + mt * 16 + (lane & 15)) * AST +
                             ks * 16 + (lane >> 4) * 8) * 2;
#pragma unroll
        for (int np = 0; np < 4; np++)
            b_off[ks][np] = STG_MAT +
                ((wn + np * 16 + ((lane >> 4) & 1) * 8 + (lane & 7)) * AST +
                 ks * 16 + ((lane >> 3) & 1) * 8) * 2;
    }

    // Prologue: stages 0..2 in flight
#pragma unroll
    for (int p = 0; p < GEMM_STAGES - 1; p++) {
        int aoff, boff, k0;
        chunk_off(p, aoff, boff, k0);
        g_load_stage(smb + p * STG_BYTES,
                     A + (size_t)m0 * KPACK + aoff + k0,
                     B + (size_t)n0 * KPACK + boff + k0, tid);
        CP_COMMIT();
    }
    CP_WAIT2();                 // stage 0 resident
    __syncthreads();

    // Fragment double buffers: (af0,bf0) = even k-step, (af1,bf1) = odd
    uint32_t af0[4][4], af1[4][4], bf0[4], bf1[4];
#pragma unroll
    for (int mt = 0; mt < 4; mt++) LDSM4(af0[mt], smb + a_off[0][mt]);
    LDSM4(bf0, smb + b_off[0][0]);

    for (int it = 0; it < GNITER; ++it) {
        uint32_t sbase = smb + (it & (GEMM_STAGES - 1)) * STG_BYTES;

        // ---- k-step 0 (consume af0/bf0; prefetch af1/bf1 from same stage) ----
        {
            int nx = it + GEMM_STAGES - 1;
            if (nx < GNITER) {
                int aoff, boff, k0;
                chunk_off(nx, aoff, boff, k0);
                g_load_stage(smb + (nx & (GEMM_STAGES - 1)) * STG_BYTES,
                             A + (size_t)m0 * KPACK + aoff + k0,
                             B + (size_t)n0 * KPACK + boff + k0, tid);
            }
            CP_COMMIT();

            uint32_t bb[2][4];
#pragma unroll
            for (int e = 0; e < 4; e++) bb[0][e] = bf0[e];
#pragma unroll
            for (int np = 0; np < 4; np++) {
                if (np < 3) LDSM4(bb[(np + 1) & 1], sbase + b_off[0][np + 1]);
#pragma unroll
                for (int mt = 0; mt < 4; mt++) {
                    MMA16816(acc[mt][2 * np],     af0[mt], bb[np & 1][0], bb[np & 1][1]);
                    MMA16816(acc[mt][2 * np + 1], af0[mt], bb[np & 1][2], bb[np & 1][3]);
                }
            }
            // prefetch odd k-step frags (same stage)
#pragma unroll
            for (int mt = 0; mt < 4; mt++) LDSM4(af1[mt], sbase + a_off[1][mt]);
            LDSM4(bf1, sbase + b_off[1][0]);
        }

        // ---- k-step 1 (consume af1/bf1; prefetch af0/bf0 from NEXT stage) ----
        {
            uint32_t bb[2][4];
#pragma unroll
            for (int e = 0; e < 4; e++) bb[0][e] = bf1[e];
#pragma unroll
            for (int np = 0; np < 4; np++) {
                if (np < 3) LDSM4(bb[(np + 1) & 1], sbase + b_off[1][np + 1]);
#pragma unroll
                for (int mt = 0; mt < 4; mt++) {
                    MMA16816(acc[mt][2 * np],     af1[mt], bb[np & 1][0], bb[np & 1][1]);
                    MMA16816(acc[mt][2 * np + 1], af1[mt], bb[np & 1][2], bb[np & 1][3]);
                }
            }
            // cross-stage prefetch: stage it+1 resident after wait; sync
            // guarantees all warps finished reading stage `it` before the
            // loads issued at (it+1,ks0) overwrite it.
            CP_WAIT2();
            __syncthreads();
            uint32_t nbase = smb + ((it + 1) & (GEMM_STAGES - 1)) * STG_BYTES;
#pragma unroll
            for (int mt = 0; mt < 4; mt++) LDSM4(af0[mt], nbase + a_off[0][mt]);
            LDSM4(bf0, nbase + b_off[0][0]);
        }
    }

    // Epilogue
    float* Cb = C + (size_t)(m0 + wm) * ldc + n0 + wn;
    int rq = lane >> 2, cq = (lane & 3) * 2;
#pragma unroll
    for (int mt = 0; mt < 4; mt++)
#pragma unroll
        for (int nt = 0; nt < 8; nt++) {
            *(float2*)(Cb + (size_t)(mt * 16 + rq) * ldc + nt * 8 + cq) =
                make_float2(acc[mt][nt][0], acc[mt][nt][1]);
            *(float2*)(Cb + (size_t)(mt * 16 + rq + 8) * ldc + nt * 8 + cq) =
                make_float2(acc[mt][nt][2], acc[mt][nt][3]);
        }
}

// ---------------------------------------------------------------------------
// Tensor-core flash attention (bf16x3 split, causal, online softmax).
// Unchanged from round 4/5 (passing).
// ---------------------------------------------------------------------------
#define AKST     136
#define AROWB    (AKST * 2)
#define QPLANE   (128 * AROWB)
#define KVPLANE  (64 * AROWB)
#define STAGE_B  (4 * KVPLANE)
#define ATTN_SMEM (2 * QPLANE + 2 * STAGE_B)

__device__ __forceinline__ void load_kv_stage(
    uint32_t dst, const __nv_bfloat16* Kp, const __nv_bfloat16* Vp,
    int k0, int tid)
{
#pragma unroll
    for (int t = 0; t < 16; t++) {
        int c = tid + t * 256;
        int plane = c >> 10;
        int r = (c >> 4) & 63;
        int co = c & 15;
        const __nv_bfloat16* src = (plane < 2)
            ? Kp + ((size_t)plane * SEQ + k0 + r) * HD + co * 8
            : Vp + ((size_t)(plane - 2) * SEQ + k0 + r) * HD + co * 8;
        CP_ASYNC16(dst + plane * KVPLANE + r * AROWB + co * 16, src);
    }
}

__global__ void __launch_bounds__(256) attn_mma_kernel() {
    extern __shared__ char sma[];
    uint32_t smb = s2u(sma);
    int tid = threadIdx.x, lane = tid & 31, w = tid >> 5;
    int qt = (int)gridDim.x - 1 - (int)blockIdx.x;
    int bh = blockIdx.y;
    int q0 = qt * 128;
    int nkt = 2 * qt + 2;

    const __nv_bfloat16* Qp = g_qp + (size_t)(bh * 2) * SEQ * HD;
    const __nv_bfloat16* Kp = g_kp + (size_t)(bh * 2) * SEQ * HD;
    const __nv_bfloat16* Vp = g_vp + (size_t)(bh * 2) * SEQ * HD;

    uint32_t sQ = smb;
    uint32_t sStage = smb + 2 * QPLANE;

#pragma unroll
    for (int t = 0; t < 16; t++) {
        int c = tid + t * 256;
        int plane = c >> 11, r = (c >> 4) & 127, co = c & 15;
        CP_ASYNC16(sQ + plane * QPLANE + r * AROWB + co * 16,
                   Qp + ((size_t)plane * SEQ + q0 + r) * HD + co * 8);
    }
    load_kv_stage(sStage, Kp, Vp, 0, tid);
    CP_COMMIT();

    float out[16][4];
#pragma unroll
    for (int n = 0; n < 16; n++)
#pragma unroll
        for (int e = 0; e < 4; e++) out[n][e] = 0.f;
    float m0 = -1e30f, m1 = -1e30f, l0 = 0.f, l1 = 0.f;

    int rq = lane >> 2, cq = lane & 3;
    uint32_t qoff = (uint32_t)(16 * w + (lane & 15)) * AROWB + ((lane >> 4) & 1) * 16;
    uint32_t koff = (uint32_t)(((lane >> 4) & 1) * 8 + (lane & 7)) * AROWB +
                    ((lane >> 3) & 1) * 16;
    uint32_t voff = (uint32_t)(((lane >> 3) & 1) * 8 + (lane & 7)) * AROWB +
                    ((lane >> 4) & 1) * 16;

    const float SCALE2 = 0.08838834764831845f * 1.44269504088896341f;

    for (int kt = 0; kt < nkt; kt++) {
        __syncthreads();
        if (kt + 1 < nkt)
            load_kv_stage(sStage + ((kt + 1) & 1) * STAGE_B, Kp, Vp,
                          (kt + 1) * 64, tid);
        CP_COMMIT();
        CP_WAIT1();
        __syncthreads();

        uint32_t sKh = sStage + (kt & 1) * STAGE_B;
        uint32_t sKl = sKh + KVPLANE;
        uint32_t sVh = sKh + 2 * KVPLANE;
        uint32_t sVl = sKh + 3 * KVPLANE;

        float sc[8][4];
#pragma unroll
        for (int j = 0; j < 8; j++)
#pragma unroll
            for (int e = 0; e < 4; e++) sc[j][e] = 0.f;

#pragma unroll
        for (int kc = 0; kc < 8; kc++) {
            uint32_t aqh[4], aql[4];
            LDSM4(aqh, sQ + qoff + kc * 32);
            LDSM4(aql, sQ + QPLANE + qoff + kc * 32);
#pragma unroll
            for (int jj = 0; jj < 4; jj++) {
                uint32_t bkh[4], bkl[4];
                uint32_t o = koff + (uint32_t)jj * (16 * AROWB) + kc * 32;
                LDSM4(bkh, sKh + o);
                LDSM4(bkl, sKl + o);
                MMA16816(sc[2 * jj],     aqh, bkh[0], bkh[1]);
                MMA16816(sc[2 * jj],     aqh, bkl[0], bkl[1]);
                MMA16816(sc[2 * jj],     aql, bkh[0], bkh[1]);
                MMA16816(sc[2 * jj + 1], aqh, bkh[2], bkh[3]);
                MMA16816(sc[2 * jj + 1], aqh, bkl[2], bkl[3]);
                MMA16816(sc[2 * jj + 1], aql, bkh[2], bkh[3]);
            }
        }

        int k0 = kt * 64;
#pragma unroll
        for (int j = 0; j < 8; j++)
#pragma unroll
            for (int e = 0; e < 4; e++) sc[j][e] *= SCALE2;
        if (k0 + 64 > q0) {
            int rg0 = q0 + 16 * w + rq, rg1 = rg0 + 8;
#pragma unroll
            for (int j = 0; j < 8; j++) {
                int cg = k0 + 8 * j + 2 * cq;
                if (cg     > rg0) sc[j][0] = -1e30f;
                if (cg + 1 > rg0) sc[j][1] = -1e30f;
                if (cg     > rg1) sc[j][2] = -1e30f;
                if (cg + 1 > rg1) sc[j][3] = -1e30f;
            }
        }

        float t0 = -1e30f, t1 = -1e30f;
#pragma unroll
        for (int j = 0; j < 8; j++) {
            t0 = fmaxf(t0, fmaxf(sc[j][0], sc[j][1]));
            t1 = fmaxf(t1, fmaxf(sc[j][2], sc[j][3]));
        }
        t0 = fmaxf(t0, __shfl_xor_sync(0xffffffffu, t0, 1));
        t0 = fmaxf(t0, __shfl_xor_sync(0xffffffffu, t0, 2));
        t1 = fmaxf(t1, __shfl_xor_sync(0xffffffffu, t1, 1));
        t1 = fmaxf(t1, __shfl_xor_sync(0xffffffffu, t1, 2));
        float mn0 = fmaxf(m0, t0), mn1 = fmaxf(m1, t1);
        float al0 = ex2f(m0 - mn0), al1 = ex2f(m1 - mn1);
        m0 = mn0; m1 = mn1;
        l0 *= al0; l1 *= al1;
#pragma unroll
        for (int n = 0; n < 16; n++) {
            out[n][0] *= al0; out[n][1] *= al0;
            out[n][2] *= al1; out[n][3] *= al1;
        }

#pragma unroll
        for (int kc = 0; kc < 4; kc++) {
            int j0 = 2 * kc, j1 = 2 * kc + 1;
            float p00 = ex2f(sc[j0][0] - m0), p01 = ex2f(sc[j0][1] - m0);
            float p02 = ex2f(sc[j0][2] - m1), p03 = ex2f(sc[j0][3] - m1);
            float p10 = ex2f(sc[j1][0] - m0), p11 = ex2f(sc[j1][1] - m0);
            float p12 = ex2f(sc[j1][2] - m1), p13 = ex2f(sc[j1][3] - m1);
            l0 += p00 + p01 + p10 + p11;
            l1 += p02 + p03 + p12 + p13;

            uint32_t ah[4], al_[4];
            ah[0] = packbf(p01, p00);
            ah[1] = packbf(p03, p02);
            ah[2] = packbf(p11, p10);
            ah[3] = packbf(p13, p12);
            float h;
            h = __uint_as_float(ah[0] << 16);          float q00 = p00 - h;
            h = __uint_as_float(ah[0] & 0xffff0000u);  float q01 = p01 - h;
            h = __uint_as_float(ah[1] << 16);          float q02 = p02 - h;
            h = __uint_as_float(ah[1] & 0xffff0000u);  float q03 = p03 - h;
            h = __uint_as_float(ah[2] << 16);          float q10 = p10 - h;
            h = __uint_as_float(ah[2] & 0xffff0000u);  float q11 = p11 - h;
            h = __uint_as_float(ah[3] << 16);          float q12 = p12 - h;
            h = __uint_as_float(ah[3] & 0xffff0000u);  float q13 = p13 - h;
            al_[0] = packbf(q01, q00);
            al_[1] = packbf(q03, q02);
            al_[2] = packbf(q11, q10);
            al_[3] = packbf(q13, q12);

#pragma unroll
            for (int jp = 0; jp < 8; jp++) {
                uint32_t bvh[4], bvl[4];
                uint32_t o = voff + (uint32_t)kc * (16 * AROWB) + jp * 32;
                LDSM4T(bvh, sVh + o);
                LDSM4T(bvl, sVl + o);
                MMA16816(out[2 * jp],     ah,  bvh[0], bvh[1]);
                MMA16816(out[2 * jp],     ah,  bvl[0], bvl[1]);
                MMA16816(out[2 * jp],     al_, bvh[0], bvh[1]);
                MMA16816(out[2 * jp + 1], ah,  bvh[2], bvh[3]);
                MMA16816(out[2 * jp + 1], ah,  bvl[2], bvl[3]);
                MMA16816(out[2 * jp + 1], al_, bvh[2], bvh[3]);
            }
        }
    }

    l0 += __shfl_xor_sync(0xffffffffu, l0, 1);
    l0 += __shfl_xor_sync(0xffffffffu, l0, 2);
    l1 += __shfl_xor_sync(0xffffffffu, l1, 1);
    l1 += __shfl_xor_sync(0xffffffffu, l1, 2);
    float il0 = 1.f / l0, il1 = 1.f / l1;

    int b = bh >> 4, hh = bh & 15;
    float* ob = g_ctx + ((size_t)(b * SEQ + q0 + 16 * w)) * HID + hh * HD;
#pragma unroll
    for (int nt = 0; nt < 16; nt++) {
        int col = nt * 8 + 2 * cq;
        *(float2*)(ob + (size_t)rq * HID + col) =
            make_float2(out[nt][0] * il0, out[nt][1] * il0);
        *(float2*)(ob + (size_t)(rq + 8) * HID + col) =
            make_float2(out[nt][2] * il1, out[nt][3] * il1);
    }
}

// ---------------------------------------------------------------------------
// Launch graph (idx 3 = QKV GEMM, the ncu capture slot)
// ---------------------------------------------------------------------------
extern "C" void kernel_launch(void* const* d_in, const int* in_sizes, int n_in,
                              void* d_out, int out_size) {
    const float* x    = (const float*)d_in[0];
    // d_in[1] = attn_mask (pure causal) — reproduced analytically, not read
    const float* Wqkv = (const float*)d_in[2];
    const float* Wout = (const float*)d_in[3];
    float* out = (float*)d_out;

    float *qkv_ptr = 0, *ctx_ptr = 0;
    __nv_bfloat16 *xp = 0, *wqp = 0, *wop = 0, *cxp = 0;
    cudaGetSymbolAddress((void**)&qkv_ptr, g_qkv);
    cudaGetSymbolAddress((void**)&ctx_ptr, g_ctx);
    cudaGetSymbolAddress((void**)&xp,  g_xp);
    cudaGetSymbolAddress((void**)&wqp, g_wqp);
    cudaGetSymbolAddress((void**)&wop, g_wop);
    cudaGetSymbolAddress((void**)&cxp, g_cxp);

    cudaFuncSetAttribute(tc_gemm_kernel,
                         cudaFuncAttributeMaxDynamicSharedMemorySize, GEMM_SMEM);
    cudaFuncSetAttribute(attn_mma_kernel,
                         cudaFuncAttributeMaxDynamicSharedMemorySize, ATTN_SMEM);

    // idx 0..2: packs
    pack_kernel<<<(MROWS * HID + 255) / 256, 256>>>(x, xp, MROWS * HID);
    pack_kernel<<<(QKVN  * HID + 255) / 256, 256>>>(Wqkv, wqp, QKVN * HID);
    pack_kernel<<<(HID   * HID + 255) / 256, 256>>>(Wout, wop, HID * HID);

    // idx 3: QKV GEMM (ncu capture slot)
    tc_gemm_kernel<<<dim3(QKVN / 128, MROWS / 128), 128, GEMM_SMEM>>>(
        xp, wqp, qkv_ptr, QKVN);

    // idx 4..5: RoPE table + qkv pack
    rope_table_kernel<<<(SEQ * 64 + 255) / 256, 256>>>();
    qkv_pack_kernel<<<(MROWS * NH * 64) / 256, 256>>>();

    // idx 6: attention
    attn_mma_kernel<<<dim3(SEQ / 128, BATCH * NH), 256, ATTN_SMEM>>>();

    // idx 7..8: ctx pack + output GEMM
    pack_kernel<<<(MROWS * HID + 255) / 256, 256>>>(ctx_ptr, cxp, MROWS * HID);
    tc_gemm_kernel<<<dim3(HID / 128, MROWS / 128), 128, GEMM_SMEM>>>(
        cxp, wop, out, HID);
}

// round 7
// speedup vs baseline: 6.2161x; 1.0553x over previous
#include <cuda_runtime.h>
#include <cuda_bf16.h>
#include <math.h>
#include <stdint.h>

// Problem constants
#define SEQ   2048
#define HID   2048
#define NH    16
#define HD    128
#define BATCH 2
#define MROWS (BATCH * SEQ)     // 4096
#define QKVN  (3 * HID)         // 6144
#define KPACK 4096              // packed row length: [hi(2048) | lo(2048)]

// ---------------------------------------------------------------------------
// Scratch (device globals — no runtime allocation allowed)
// ---------------------------------------------------------------------------
__device__ __align__(16) float g_qkv[(size_t)MROWS * QKVN];    // fp32 QKV
__device__ __align__(16) float g_ctx[(size_t)MROWS * HID];     // fp32 attn out
__device__ __align__(16) float g_cos[SEQ * 64];
__device__ __align__(16) float g_sin[SEQ * 64];
__device__ __align__(16) __nv_bfloat16 g_xp  [(size_t)MROWS * KPACK];
__device__ __align__(16) __nv_bfloat16 g_wqp [(size_t)QKVN  * KPACK];
__device__ __align__(16) __nv_bfloat16 g_wop [(size_t)HID   * KPACK];
__device__ __align__(16) __nv_bfloat16 g_cxp [(size_t)MROWS * KPACK];
// attention operands: [bh*2 + plane(hi=0,lo=1)][s][128]
__device__ __align__(16) __nv_bfloat16 g_qp[(size_t)BATCH * NH * 2 * SEQ * HD];
__device__ __align__(16) __nv_bfloat16 g_kp[(size_t)BATCH * NH * 2 * SEQ * HD];
__device__ __align__(16) __nv_bfloat16 g_vp[(size_t)BATCH * NH * 2 * SEQ * HD];

// ---------------------------------------------------------------------------
// PTX helpers (arch-agnostic: cp.async / ldmatrix / mma.sync only)
// ---------------------------------------------------------------------------
__device__ __forceinline__ uint32_t s2u(const void* p) {
    uint32_t a;
    asm("{ .reg .u64 t; cvta.to.shared.u64 t, %1; cvt.u32.u64 %0, t; }"
        : "=r"(a) : "l"(p));
    return a;
}

#define CP_ASYNC16(saddr, gptr) \
    asm volatile("cp.async.cg.shared.global [%0], [%1], 16;" \
                 :: "r"(saddr), "l"(gptr))
#define CP_COMMIT()  asm volatile("cp.async.commit_group;" ::: "memory")
#define CP_WAIT1()   asm volatile("cp.async.wait_group 1;" ::: "memory")

#define LDSM4(r, addr)                                                        \
    asm volatile("ldmatrix.sync.aligned.m8n8.x4.shared.b16 {%0,%1,%2,%3}, [%4];" \
        : "=r"((r)[0]), "=r"((r)[1]), "=r"((r)[2]), "=r"((r)[3]) : "r"(addr))
#define LDSM4T(r, addr)                                                       \
    asm volatile("ldmatrix.sync.aligned.m8n8.x4.trans.shared.b16 {%0,%1,%2,%3}, [%4];" \
        : "=r"((r)[0]), "=r"((r)[1]), "=r"((r)[2]), "=r"((r)[3]) : "r"(addr))

#define MMA16816(d, a, b0, b1)                                                \
    asm volatile("mma.sync.aligned.m16n8k16.row.col.f32.bf16.bf16.f32 "       \
        "{%0,%1,%2,%3},{%4,%5,%6,%7},{%8,%9},{%0,%1,%2,%3};"                  \
        : "+f"((d)[0]), "+f"((d)[1]), "+f"((d)[2]), "+f"((d)[3])              \
        : "r"((a)[0]), "r"((a)[1]), "r"((a)[2]), "r"((a)[3]),                 \
          "r"(b0), "r"(b1))

__device__ __forceinline__ float ex2f(float x) {
    float y;
    asm("ex2.approx.ftz.f32 %0, %1;" : "=f"(y) : "f"(x));
    return y;
}
__device__ __forceinline__ uint32_t packbf(float hi, float lo) {
    uint32_t d;
    asm("cvt.rn.bf16x2.f32 %0, %1, %2;" : "=r"(d) : "f"(hi), "f"(lo));
    return d;
}

// split 4 fp32 -> 4 bf16 hi (uint2) + 4 bf16 lo residuals (uint2)
__device__ __forceinline__ void pack4(const float* x, uint2& hi, uint2& lo) {
    uint32_t h0 = packbf(x[1], x[0]);
    uint32_t h1 = packbf(x[3], x[2]);
    float f0 = __uint_as_float(h0 << 16);
    float f1 = __uint_as_float(h0 & 0xffff0000u);
    float f2 = __uint_as_float(h1 << 16);
    float f3 = __uint_as_float(h1 & 0xffff0000u);
    hi.x = h0; hi.y = h1;
    lo.x = packbf(x[1] - f1, x[0] - f0);
    lo.y = packbf(x[3] - f3, x[2] - f2);
}

// ---------------------------------------------------------------------------
// RoPE table (reference-matching numerics)
// ---------------------------------------------------------------------------
__global__ void rope_table_kernel() {
    int idx = blockIdx.x * blockDim.x + threadIdx.x;
    if (idx >= SEQ * 64) return;
    int s = idx >> 6;
    int j = idx & 63;
    double inv = exp(-((double)j / 64.0) * log(10000.0));
    float  invf = (float)inv;
    float  ang  = (float)s * invf;
    g_cos[idx] = (float)cos((double)ang);
    g_sin[idx] = (float)sin((double)ang);
}

// ---------------------------------------------------------------------------
// fp32 -> split bf16 pack (vectorized: 8 elems/thread, uint4 stores)
// ---------------------------------------------------------------------------
__global__ void pack_kernel(const float* __restrict__ X,
                            __nv_bfloat16* __restrict__ P, int n) {
    int i = (blockIdx.x * 256 + threadIdx.x) * 8;
    if (i >= n) return;
    int row = i >> 11, col = i & 2047;
    float4 a = *(const float4*)(X + i);
    float4 b = *(const float4*)(X + i + 4);
    float v0[4] = {a.x, a.y, a.z, a.w};
    float v1[4] = {b.x, b.y, b.z, b.w};
    uint2 h0, l0, h1, l1;
    pack4(v0, h0, l0);
    pack4(v1, h1, l1);
    uint4* Ph = (uint4*)(P + (size_t)row * KPACK + col);
    uint4* Pl = (uint4*)(P + (size_t)row * KPACK + 2048 + col);
    *Ph = make_uint4(h0.x, h0.y, h1.x, h1.y);
    *Pl = make_uint4(l0.x, l0.y, l1.x, l1.y);
}

// ---------------------------------------------------------------------------
// QKV pack: RoPE on q,k + hi/lo bf16 split of q,k,v (vectorized, 4 j/thread)
// ---------------------------------------------------------------------------
__global__ void qkv_pack_kernel() {
    int idx = blockIdx.x * blockDim.x + threadIdx.x;   // MROWS*NH*16
    int jq  = (idx & 15) << 2;                          // 0,4,...,60
    int h   = (idx >> 4) & (NH - 1);
    int row = idx >> 8;
    int s   = row & (SEQ - 1);
    int b   = row >> 11;
    int bh  = b * NH + h;

    float4 c4 = *(const float4*)&g_cos[(s << 6) + jq];
    float4 s4 = *(const float4*)&g_sin[(s << 6) + jq];
    float cc[4] = {c4.x, c4.y, c4.z, c4.w};
    float ss[4] = {s4.x, s4.y, s4.z, s4.w};

    const float* base = g_qkv + (size_t)row * QKVN + h * HD;
    float4 qa4 = *(const float4*)(base + jq);
    float4 qb4 = *(const float4*)(base + jq + 64);
    float4 ka4 = *(const float4*)(base + HID + jq);
    float4 kb4 = *(const float4*)(base + HID + jq + 64);
    float4 va4 = *(const float4*)(base + 2 * HID + jq);
    float4 vb4 = *(const float4*)(base + 2 * HID + jq + 64);
    float q1[4] = {qa4.x, qa4.y, qa4.z, qa4.w};
    float q2[4] = {qb4.x, qb4.y, qb4.z, qb4.w};
    float k1[4] = {ka4.x, ka4.y, ka4.z, ka4.w};
    float k2[4] = {kb4.x, kb4.y, kb4.z, kb4.w};
    float v1[4] = {va4.x, va4.y, va4.z, va4.w};
    float v2[4] = {vb4.x, vb4.y, vb4.z, vb4.w};

    float qa[4], qb[4], ka[4], kb[4];
#pragma unroll
    for (int e = 0; e < 4; e++) {
        qa[e] = q1[e] * cc[e] - q2[e] * ss[e];
        qb[e] = q2[e] * cc[e] + q1[e] * ss[e];
        ka[e] = k1[e] * cc[e] - k2[e] * ss[e];
        kb[e] = k2[e] * cc[e] + k1[e] * ss[e];
    }

    size_t pb = ((size_t)(bh * 2) * SEQ + s) * HD;   // hi plane; lo = +SEQ*HD
    const size_t PL = (size_t)SEQ * HD;
    uint2 hi, lo;
    pack4(qa, hi, lo);
    *(uint2*)(g_qp + pb + jq)           = hi; *(uint2*)(g_qp + pb + PL + jq)           = lo;
    pack4(qb, hi, lo);
    *(uint2*)(g_qp + pb + jq + 64)      = hi; *(uint2*)(g_qp + pb + PL + jq + 64)      = lo;
    pack4(ka, hi, lo);
    *(uint2*)(g_kp + pb + jq)           = hi; *(uint2*)(g_kp + pb + PL + jq)           = lo;
    pack4(kb, hi, lo);
    *(uint2*)(g_kp + pb + jq + 64)      = hi; *(uint2*)(g_kp + pb + PL + jq + 64)      = lo;
    pack4(v1, hi, lo);
    *(uint2*)(g_vp + pb + jq)           = hi; *(uint2*)(g_vp + pb + PL + jq)           = lo;
    pack4(v2, hi, lo);
    *(uint2*)(g_vp + pb + jq + 64)      = hi; *(uint2*)(g_vp + pb + PL + jq + 64)      = lo;
}

// ---------------------------------------------------------------------------
// bf16x3 tensor-core GEMM v4: 4 warps, 64x64 warp tiles, K=64 stages,
// 3-stage cp.async ring (one sync per K=64 -> half the barriers of v3),
// software-pipelined fragments.
// C[M,N] = A_f32 B_f32^T; A packed [M][4096], B packed [N][4096].
// ---------------------------------------------------------------------------
#define AST         72                   // padded smem row stride (bf16); 144B % 128B = 16 -> conflict-free
#define STG_MAT     (128 * AST * 2)      // 18432 B
#define STG_BYTES   (2 * STG_MAT)        // 36864 B
#define GEMM_STAGES 3
#define GEMM_SMEM   (GEMM_STAGES * STG_BYTES)   // 110592 (2 CTAs/SM)
#define GNITER      96                   // 3 passes x 32 chunks of K=64

__device__ __forceinline__ void g_load_stage(
    uint32_t sA, const __nv_bfloat16* Ab, const __nv_bfloat16* Bb, int tid)
{
#pragma unroll
    for (int t = 0; t < 8; t++) {
        int c = tid + t * 128;               // 0..1023
        int r = c >> 3, co = (c & 7) << 3;   // row, col elem (8 bf16 = 16 B)
        CP_ASYNC16(sA + (r * AST + co) * 2, Ab + (size_t)r * KPACK + co);
        CP_ASYNC16(sA + STG_MAT + (r * AST + co) * 2, Bb + (size_t)r * KPACK + co);
    }
}

__global__ void __launch_bounds__(128, 2) tc_gemm_kernel(
    const __nv_bfloat16* __restrict__ A, const __nv_bfloat16* __restrict__ B,
    float* __restrict__ C, int ldc)
{
    extern __shared__ char smg[];
    uint32_t smb = s2u(smg);
    int tid  = threadIdx.x;
    int lane = tid & 31, wid = tid >> 5;
    int wm = (wid & 1) * 64, wn = (wid >> 1) * 64;
    int m0 = blockIdx.y * 128, n0 = blockIdx.x * 128;

    float acc[4][8][4];
#pragma unroll
    for (int i = 0; i < 4; i++)
#pragma unroll
        for (int j = 0; j < 8; j++)
#pragma unroll
            for (int k = 0; k < 4; k++) acc[i][j][k] = 0.f;

    auto chunk_off = [&](int it, int& aoff, int& boff, int& k0) {
        int pass = it >> 5;                 // 32 chunks of K=64 per pass
        k0   = (it & 31) << 6;
        aoff = (pass == 2) ? 2048 : 0;
        boff = (pass == 1) ? 2048 : 0;
    };

    // ldmatrix byte offsets (ks = 0..3 k-steps of 16 within the K=64 stage)
    uint32_t a_off[4][4], b_off[4][4];
#pragma unroll
    for (int ks = 0; ks < 4; ks++) {
#pragma unroll
        for (int mt = 0; mt < 4; mt++)
            a_off[ks][mt] = ((wm + mt * 16 + (lane & 15)) * AST +
                             ks * 16 + (lane >> 4) * 8) * 2;
#pragma unroll
        for (int np = 0; np < 4; np++)
            b_off[ks][np] = STG_MAT +
                ((wn + np * 16 + ((lane >> 4) & 1) * 8 + (lane & 7)) * AST +
                 ks * 16 + ((lane >> 3) & 1) * 8) * 2;
    }

    // Prologue: stages 0,1 in flight
#pragma unroll
    for (int p = 0; p < GEMM_STAGES - 1; p++) {
        int aoff, boff, k0;
        chunk_off(p, aoff, boff, k0);
        g_load_stage(smb + p * STG_BYTES,
                     A + (size_t)m0 * KPACK + aoff + k0,
                     B + (size_t)n0 * KPACK + boff + k0, tid);
        CP_COMMIT();
    }
    CP_WAIT1();                 // stage 0 resident
    __syncthreads();

    // Fragment double buffers (index ks&1)
    uint32_t af[2][4][4], bf[2][4];
#pragma unroll
    for (int mt = 0; mt < 4; mt++) LDSM4(af[0][mt], smb + a_off[0][mt]);
    LDSM4(bf[0], smb + b_off[0][0]);

    for (int it = 0; it < GNITER; ++it) {
        uint32_t sbase = smb + (it % GEMM_STAGES) * STG_BYTES;

        // issue next-stage loads (slot (it+2)%3 = stage it-1's slot, consumed)
        int nx = it + GEMM_STAGES - 1;
        if (nx < GNITER) {
            int aoff, boff, k0;
            chunk_off(nx, aoff, boff, k0);
            g_load_stage(smb + (nx % GEMM_STAGES) * STG_BYTES,
                         A + (size_t)m0 * KPACK + aoff + k0,
                         B + (size_t)n0 * KPACK + boff + k0, tid);
        }
        CP_COMMIT();

#pragma unroll
        for (int ks = 0; ks < 4; ks++) {
            int cur = ks & 1, nxt = cur ^ 1;
            uint32_t bb[2][4];
#pragma unroll
            for (int e = 0; e < 4; e++) bb[0][e] = bf[cur][e];
#pragma unroll
            for (int np = 0; np < 4; np++) {
                if (np < 3) LDSM4(bb[(np + 1) & 1], sbase + b_off[ks][np + 1]);
#pragma unroll
                for (int mt = 0; mt < 4; mt++) {
                    MMA16816(acc[mt][2 * np],     af[cur][mt], bb[np & 1][0], bb[np & 1][1]);
                    MMA16816(acc[mt][2 * np + 1], af[cur][mt], bb[np & 1][2], bb[np & 1][3]);
                }
            }
            if (ks < 3) {
#pragma unroll
                for (int mt = 0; mt < 4; mt++)
                    LDSM4(af[nxt][mt], sbase + a_off[ks + 1][mt]);
                LDSM4(bf[nxt], sbase + b_off[ks + 1][0]);
            }
        }

        // stage it+1 resident; sync makes other threads' cp.async data visible
        CP_WAIT1();
        __syncthreads();
        uint32_t nbase = smb + ((it + 1) % GEMM_STAGES) * STG_BYTES;
#pragma unroll
        for (int mt = 0; mt < 4; mt++) LDSM4(af[0][mt], nbase + a_off[0][mt]);
        LDSM4(bf[0], nbase + b_off[0][0]);
    }

    // Epilogue
    float* Cb = C + (size_t)(m0 + wm) * ldc + n0 + wn;
    int rq = lane >> 2, cq = (lane & 3) * 2;
#pragma unroll
    for (int mt = 0; mt < 4; mt++)
#pragma unroll
        for (int nt = 0; nt < 8; nt++) {
            *(float2*)(Cb + (size_t)(mt * 16 + rq) * ldc + nt * 8 + cq) =
                make_float2(acc[mt][nt][0], acc[mt][nt][1]);
            *(float2*)(Cb + (size_t)(mt * 16 + rq + 8) * ldc + nt * 8 + cq) =
                make_float2(acc[mt][nt][2], acc[mt][nt][3]);
        }
}

// ---------------------------------------------------------------------------
// Tensor-core flash attention (bf16x3 split, causal, online softmax).
// Unchanged from rounds 4-6 (passing).
// ---------------------------------------------------------------------------
#define AKST     136
#define AROWB    (AKST * 2)
#define QPLANE   (128 * AROWB)
#define KVPLANE  (64 * AROWB)
#define STAGE_B  (4 * KVPLANE)
#define ATTN_SMEM (2 * QPLANE + 2 * STAGE_B)

__device__ __forceinline__ void load_kv_stage(
    uint32_t dst, const __nv_bfloat16* Kp, const __nv_bfloat16* Vp,
    int k0, int tid)
{
#pragma unroll
    for (int t = 0; t < 16; t++) {
        int c = tid + t * 256;
        int plane = c >> 10;
        int r = (c >> 4) & 63;
        int co = c & 15;
        const __nv_bfloat16* src = (plane < 2)
            ? Kp + ((size_t)plane * SEQ + k0 + r) * HD + co * 8
            : Vp + ((size_t)(plane - 2) * SEQ + k0 + r) * HD + co * 8;
        CP_ASYNC16(dst + plane * KVPLANE + r * AROWB + co * 16, src);
    }
}

__global__ void __launch_bounds__(256) attn_mma_kernel() {
    extern __shared__ char sma[];
    uint32_t smb = s2u(sma);
    int tid = threadIdx.x, lane = tid & 31, w = tid >> 5;
    int qt = (int)gridDim.x - 1 - (int)blockIdx.x;
    int bh = blockIdx.y;
    int q0 = qt * 128;
    int nkt = 2 * qt + 2;

    const __nv_bfloat16* Qp = g_qp + (size_t)(bh * 2) * SEQ * HD;
    const __nv_bfloat16* Kp = g_kp + (size_t)(bh * 2) * SEQ * HD;
    const __nv_bfloat16* Vp = g_vp + (size_t)(bh * 2) * SEQ * HD;

    uint32_t sQ = smb;
    uint32_t sStage = smb + 2 * QPLANE;

#pragma unroll
    for (int t = 0; t < 16; t++) {
        int c = tid + t * 256;
        int plane = c >> 11, r = (c >> 4) & 127, co = c & 15;
        CP_ASYNC16(sQ + plane * QPLANE + r * AROWB + co * 16,
                   Qp + ((size_t)plane * SEQ + q0 + r) * HD + co * 8);
    }
    load_kv_stage(sStage, Kp, Vp, 0, tid);
    CP_COMMIT();

    float out[16][4];
#pragma unroll
    for (int n = 0; n < 16; n++)
#pragma unroll
        for (int e = 0; e < 4; e++) out[n][e] = 0.f;
    float m0 = -1e30f, m1 = -1e30f, l0 = 0.f, l1 = 0.f;

    int rq = lane >> 2, cq = lane & 3;
    uint32_t qoff = (uint32_t)(16 * w + (lane & 15)) * AROWB + ((lane >> 4) & 1) * 16;
    uint32_t koff = (uint32_t)(((lane >> 4) & 1) * 8 + (lane & 7)) * AROWB +
                    ((lane >> 3) & 1) * 16;
    uint32_t voff = (uint32_t)(((lane >> 3) & 1) * 8 + (lane & 7)) * AROWB +
                    ((lane >> 4) & 1) * 16;

    const float SCALE2 = 0.08838834764831845f * 1.44269504088896341f;

    for (int kt = 0; kt < nkt; kt++) {
        __syncthreads();
        if (kt + 1 < nkt)
            load_kv_stage(sStage + ((kt + 1) & 1) * STAGE_B, Kp, Vp,
                          (kt + 1) * 64, tid);
        CP_COMMIT();
        CP_WAIT1();
        __syncthreads();

        uint32_t sKh = sStage + (kt & 1) * STAGE_B;
        uint32_t sKl = sKh + KVPLANE;
        uint32_t sVh = sKh + 2 * KVPLANE;
        uint32_t sVl = sKh + 3 * KVPLANE;

        float sc[8][4];
#pragma unroll
        for (int j = 0; j < 8; j++)
#pragma unroll
            for (int e = 0; e < 4; e++) sc[j][e] = 0.f;

#pragma unroll
        for (int kc = 0; kc < 8; kc++) {
            uint32_t aqh[4], aql[4];
            LDSM4(aqh, sQ + qoff + kc * 32);
            LDSM4(aql, sQ + QPLANE + qoff + kc * 32);
#pragma unroll
            for (int jj = 0; jj < 4; jj++) {
                uint32_t bkh[4], bkl[4];
                uint32_t o = koff + (uint32_t)jj * (16 * AROWB) + kc * 32;
                LDSM4(bkh, sKh + o);
                LDSM4(bkl, sKl + o);
                MMA16816(sc[2 * jj],     aqh, bkh[0], bkh[1]);
                MMA16816(sc[2 * jj],     aqh, bkl[0], bkl[1]);
                MMA16816(sc[2 * jj],     aql, bkh[0], bkh[1]);
                MMA16816(sc[2 * jj + 1], aqh, bkh[2], bkh[3]);
                MMA16816(sc[2 * jj + 1], aqh, bkl[2], bkl[3]);
                MMA16816(sc[2 * jj + 1], aql, bkh[2], bkh[3]);
            }
        }

        int k0 = kt * 64;
#pragma unroll
        for (int j = 0; j < 8; j++)
#pragma unroll
            for (int e = 0; e < 4; e++) sc[j][e] *= SCALE2;
        if (k0 + 64 > q0) {
            int rg0 = q0 + 16 * w + rq, rg1 = rg0 + 8;
#pragma unroll
            for (int j = 0; j < 8; j++) {
                int cg = k0 + 8 * j + 2 * cq;
                if (cg     > rg0) sc[j][0] = -1e30f;
                if (cg + 1 > rg0) sc[j][1] = -1e30f;
                if (cg     > rg1) sc[j][2] = -1e30f;
                if (cg + 1 > rg1) sc[j][3] = -1e30f;
            }
        }

        float t0 = -1e30f, t1 = -1e30f;
#pragma unroll
        for (int j = 0; j < 8; j++) {
            t0 = fmaxf(t0, fmaxf(sc[j][0], sc[j][1]));
            t1 = fmaxf(t1, fmaxf(sc[j][2], sc[j][3]));
        }
        t0 = fmaxf(t0, __shfl_xor_sync(0xffffffffu, t0, 1));
        t0 = fmaxf(t0, __shfl_xor_sync(0xffffffffu, t0, 2));
        t1 = fmaxf(t1, __shfl_xor_sync(0xffffffffu, t1, 1));
        t1 = fmaxf(t1, __shfl_xor_sync(0xffffffffu, t1, 2));
        float mn0 = fmaxf(m0, t0), mn1 = fmaxf(m1, t1);
        float al0 = ex2f(m0 - mn0), al1 = ex2f(m1 - mn1);
        m0 = mn0; m1 = mn1;
        l0 *= al0; l1 *= al1;
#pragma unroll
        for (int n = 0; n < 16; n++) {
            out[n][0] *= al0; out[n][1] *= al0;
            out[n][2] *= al1; out[n][3] *= al1;
        }

#pragma unroll
        for (int kc = 0; kc < 4; kc++) {
            int j0 = 2 * kc, j1 = 2 * kc + 1;
            float p00 = ex2f(sc[j0][0] - m0), p01 = ex2f(sc[j0][1] - m0);
            float p02 = ex2f(sc[j0][2] - m1), p03 = ex2f(sc[j0][3] - m1);
            float p10 = ex2f(sc[j1][0] - m0), p11 = ex2f(sc[j1][1] - m0);
            float p12 = ex2f(sc[j1][2] - m1), p13 = ex2f(sc[j1][3] - m1);
            l0 += p00 + p01 + p10 + p11;
            l1 += p02 + p03 + p12 + p13;

            uint32_t ah[4], al_[4];
            ah[0] = packbf(p01, p00);
            ah[1] = packbf(p03, p02);
            ah[2] = packbf(p11, p10);
            ah[3] = packbf(p13, p12);
            float h;
            h = __uint_as_float(ah[0] << 16);          float q00 = p00 - h;
            h = __uint_as_float(ah[0] & 0xffff0000u);  float q01 = p01 - h;
            h = __uint_as_float(ah[1] << 16);          float q02 = p02 - h;
            h = __uint_as_float(ah[1] & 0xffff0000u);  float q03 = p03 - h;
            h = __uint_as_float(ah[2] << 16);          float q10 = p10 - h;
            h = __uint_as_float(ah[2] & 0xffff0000u);  float q11 = p11 - h;
            h = __uint_as_float(ah[3] << 16);          float q12 = p12 - h;
            h = __uint_as_float(ah[3] & 0xffff0000u);  float q13 = p13 - h;
            al_[0] = packbf(q01, q00);
            al_[1] = packbf(q03, q02);
            al_[2] = packbf(q11, q10);
            al_[3] = packbf(q13, q12);

#pragma unroll
            for (int jp = 0; jp < 8; jp++) {
                uint32_t bvh[4], bvl[4];
                uint32_t o = voff + (uint32_t)kc * (16 * AROWB) + jp * 32;
                LDSM4T(bvh, sVh + o);
                LDSM4T(bvl, sVl + o);
                MMA16816(out[2 * jp],     ah,  bvh[0], bvh[1]);
                MMA16816(out[2 * jp],     ah,  bvl[0], bvl[1]);
                MMA16816(out[2 * jp],     al_, bvh[0], bvh[1]);
                MMA16816(out[2 * jp + 1], ah,  bvh[2], bvh[3]);
                MMA16816(out[2 * jp + 1], ah,  bvl[2], bvl[3]);
                MMA16816(out[2 * jp + 1], al_, bvh[2], bvh[3]);
            }
        }
    }

    l0 += __shfl_xor_sync(0xffffffffu, l0, 1);
    l0 += __shfl_xor_sync(0xffffffffu, l0, 2);
    l1 += __shfl_xor_sync(0xffffffffu, l1, 1);
    l1 += __shfl_xor_sync(0xffffffffu, l1, 2);
    float il0 = 1.f / l0, il1 = 1.f / l1;

    int b = bh >> 4, hh = bh & 15;
    float* ob = g_ctx + ((size_t)(b * SEQ + q0 + 16 * w)) * HID + hh * HD;
#pragma unroll
    for (int nt = 0; nt < 16; nt++) {
        int col = nt * 8 + 2 * cq;
        *(float2*)(ob + (size_t)rq * HID + col) =
            make_float2(out[nt][0] * il0, out[nt][1] * il0);
        *(float2*)(ob + (size_t)(rq + 8) * HID + col) =
            make_float2(out[nt][2] * il1, out[nt][3] * il1);
    }
}

// ---------------------------------------------------------------------------
// Launch graph (idx 3 = QKV GEMM, the ncu capture slot)
// ---------------------------------------------------------------------------
extern "C" void kernel_launch(void* const* d_in, const int* in_sizes, int n_in,
                              void* d_out, int out_size) {
    const float* x    = (const float*)d_in[0];
    // d_in[1] = attn_mask (pure causal) — reproduced analytically, not read
    const float* Wqkv = (const float*)d_in[2];
    const float* Wout = (const float*)d_in[3];
    float* out = (float*)d_out;

    float *qkv_ptr = 0, *ctx_ptr = 0;
    __nv_bfloat16 *xp = 0, *wqp = 0, *wop = 0, *cxp = 0;
    cudaGetSymbolAddress((void**)&qkv_ptr, g_qkv);
    cudaGetSymbolAddress((void**)&ctx_ptr, g_ctx);
    cudaGetSymbolAddress((void**)&xp,  g_xp);
    cudaGetSymbolAddress((void**)&wqp, g_wqp);
    cudaGetSymbolAddress((void**)&wop, g_wop);
    cudaGetSymbolAddress((void**)&cxp, g_cxp);

    cudaFuncSetAttribute(tc_gemm_kernel,
                         cudaFuncAttributeMaxDynamicSharedMemorySize, GEMM_SMEM);
    cudaFuncSetAttribute(attn_mma_kernel,
                         cudaFuncAttributeMaxDynamicSharedMemorySize, ATTN_SMEM);

    // idx 0..2: packs (vectorized, 8 elems/thread)
    pack_kernel<<<MROWS * HID / 2048, 256>>>(x, xp, MROWS * HID);
    pack_kernel<<<QKVN  * HID / 2048, 256>>>(Wqkv, wqp, QKVN * HID);
    pack_kernel<<<HID   * HID / 2048, 256>>>(Wout, wop, HID * HID);

    // idx 3: QKV GEMM (ncu capture slot)
    tc_gemm_kernel<<<dim3(QKVN / 128, MROWS / 128), 128, GEMM_SMEM>>>(
        xp, wqp, qkv_ptr, QKVN);

    // idx 4..5: RoPE table + qkv pack
    rope_table_kernel<<<(SEQ * 64 + 255) / 256, 256>>>();
    qkv_pack_kernel<<<MROWS * NH * 16 / 256, 256>>>();

    // idx 6: attention
    attn_mma_kernel<<<dim3(SEQ / 128, BATCH * NH), 256, ATTN_SMEM>>>();

    // idx 7..8: ctx pack + output GEMM
    pack_kernel<<<MROWS * HID / 2048, 256>>>(ctx_ptr, cxp, MROWS * HID);
    tc_gemm_kernel<<<dim3(HID / 128, MROWS / 128), 128, GEMM_SMEM>>>(
        cxp, wop, out, HID);
}

// round 8
// speedup vs baseline: 6.2965x; 1.0129x over previous
#include <cuda_runtime.h>
#include <cuda_bf16.h>
#include <math.h>
#include <stdint.h>

// Problem constants
#define SEQ   2048
#define HID   2048
#define NH    16
#define HD    128
#define BATCH 2
#define MROWS (BATCH * SEQ)     // 4096
#define QKVN  (3 * HID)         // 6144
#define KPACK 4096              // packed row length: [hi(2048) | lo(2048)]

// ---------------------------------------------------------------------------
// Scratch (device globals — no runtime allocation allowed)
// ---------------------------------------------------------------------------
__device__ __align__(16) float g_qkv[(size_t)MROWS * QKVN];    // fp32 QKV
__device__ __align__(16) float g_ctx[(size_t)MROWS * HID];     // fp32 attn out
__device__ __align__(16) float g_cos[SEQ * 64];
__device__ __align__(16) float g_sin[SEQ * 64];
__device__ __align__(16) __nv_bfloat16 g_xp  [(size_t)MROWS * KPACK];
__device__ __align__(16) __nv_bfloat16 g_wqp [(size_t)QKVN  * KPACK];
__device__ __align__(16) __nv_bfloat16 g_wop [(size_t)HID   * KPACK];
__device__ __align__(16) __nv_bfloat16 g_cxp [(size_t)MROWS * KPACK];
// attention operands: [bh*2 + plane(hi=0,lo=1)][s][128]
__device__ __align__(16) __nv_bfloat16 g_qp[(size_t)BATCH * NH * 2 * SEQ * HD];
__device__ __align__(16) __nv_bfloat16 g_kp[(size_t)BATCH * NH * 2 * SEQ * HD];
__device__ __align__(16) __nv_bfloat16 g_vp[(size_t)BATCH * NH * 2 * SEQ * HD];

// ---------------------------------------------------------------------------
// PTX helpers (arch-agnostic: cp.async / ldmatrix / mma.sync only)
// ---------------------------------------------------------------------------
__device__ __forceinline__ uint32_t s2u(const void* p) {
    uint32_t a;
    asm("{ .reg .u64 t; cvta.to.shared.u64 t, %1; cvt.u32.u64 %0, t; }"
        : "=r"(a) : "l"(p));
    return a;
}

#define CP_ASYNC16(saddr, gptr) \
    asm volatile("cp.async.cg.shared.global [%0], [%1], 16;" \
                 :: "r"(saddr), "l"(gptr))
#define CP_COMMIT()  asm volatile("cp.async.commit_group;" ::: "memory")
#define CP_WAIT1()   asm volatile("cp.async.wait_group 1;" ::: "memory")
#define CP_WAIT2()   asm volatile("cp.async.wait_group 2;" ::: "memory")

#define LDSM4(r, addr)                                                        \
    asm volatile("ldmatrix.sync.aligned.m8n8.x4.shared.b16 {%0,%1,%2,%3}, [%4];" \
        : "=r"((r)[0]), "=r"((r)[1]), "=r"((r)[2]), "=r"((r)[3]) : "r"(addr))
#define LDSM4T(r, addr)                                                       \
    asm volatile("ldmatrix.sync.aligned.m8n8.x4.trans.shared.b16 {%0,%1,%2,%3}, [%4];" \
        : "=r"((r)[0]), "=r"((r)[1]), "=r"((r)[2]), "=r"((r)[3]) : "r"(addr))

#define MMA16816(d, a, b0, b1)                                                \
    asm volatile("mma.sync.aligned.m16n8k16.row.col.f32.bf16.bf16.f32 "       \
        "{%0,%1,%2,%3},{%4,%5,%6,%7},{%8,%9},{%0,%1,%2,%3};"                  \
        : "+f"((d)[0]), "+f"((d)[1]), "+f"((d)[2]), "+f"((d)[3])              \
        : "r"((a)[0]), "r"((a)[1]), "r"((a)[2]), "r"((a)[3]),                 \
          "r"(b0), "r"(b1))

__device__ __forceinline__ float ex2f(float x) {
    float y;
    asm("ex2.approx.ftz.f32 %0, %1;" : "=f"(y) : "f"(x));
    return y;
}
__device__ __forceinline__ uint32_t packbf(float hi, float lo) {
    uint32_t d;
    asm("cvt.rn.bf16x2.f32 %0, %1, %2;" : "=r"(d) : "f"(hi), "f"(lo));
    return d;
}

// split 4 fp32 -> 4 bf16 hi (uint2) + 4 bf16 lo residuals (uint2)
__device__ __forceinline__ void pack4(const float* x, uint2& hi, uint2& lo) {
    uint32_t h0 = packbf(x[1], x[0]);
    uint32_t h1 = packbf(x[3], x[2]);
    float f0 = __uint_as_float(h0 << 16);
    float f1 = __uint_as_float(h0 & 0xffff0000u);
    float f2 = __uint_as_float(h1 << 16);
    float f3 = __uint_as_float(h1 & 0xffff0000u);
    hi.x = h0; hi.y = h1;
    lo.x = packbf(x[1] - f1, x[0] - f0);
    lo.y = packbf(x[3] - f3, x[2] - f2);
}

// ---------------------------------------------------------------------------
// RoPE table (reference-matching numerics)
// ---------------------------------------------------------------------------
__global__ void rope_table_kernel() {
    int idx = blockIdx.x * blockDim.x + threadIdx.x;
    if (idx >= SEQ * 64) return;
    int s = idx >> 6;
    int j = idx & 63;
    double inv = exp(-((double)j / 64.0) * log(10000.0));
    float  invf = (float)inv;
    float  ang  = (float)s * invf;
    g_cos[idx] = (float)cos((double)ang);
    g_sin[idx] = (float)sin((double)ang);
}

// ---------------------------------------------------------------------------
// fp32 -> split bf16 pack (vectorized: 8 elems/thread, uint4 stores)
// ---------------------------------------------------------------------------
__global__ void pack_kernel(const float* __restrict__ X,
                            __nv_bfloat16* __restrict__ P, int n) {
    int i = (blockIdx.x * 256 + threadIdx.x) * 8;
    if (i >= n) return;
    int row = i >> 11, col = i & 2047;
    float4 a = *(const float4*)(X + i);
    float4 b = *(const float4*)(X + i + 4);
    float v0[4] = {a.x, a.y, a.z, a.w};
    float v1[4] = {b.x, b.y, b.z, b.w};
    uint2 h0, l0, h1, l1;
    pack4(v0, h0, l0);
    pack4(v1, h1, l1);
    uint4* Ph = (uint4*)(P + (size_t)row * KPACK + col);
    uint4* Pl = (uint4*)(P + (size_t)row * KPACK + 2048 + col);
    *Ph = make_uint4(h0.x, h0.y, h1.x, h1.y);
    *Pl = make_uint4(l0.x, l0.y, l1.x, l1.y);
}

// ---------------------------------------------------------------------------
// QKV pack: RoPE on q,k + hi/lo bf16 split of q,k,v (vectorized, 4 j/thread)
// ---------------------------------------------------------------------------
__global__ void qkv_pack_kernel() {
    int idx = blockIdx.x * blockDim.x + threadIdx.x;   // MROWS*NH*16
    int jq  = (idx & 15) << 2;                          // 0,4,...,60
    int h   = (idx >> 4) & (NH - 1);
    int row = idx >> 8;
    int s   = row & (SEQ - 1);
    int b   = row >> 11;
    int bh  = b * NH + h;

    float4 c4 = *(const float4*)&g_cos[(s << 6) + jq];
    float4 s4 = *(const float4*)&g_sin[(s << 6) + jq];
    float cc[4] = {c4.x, c4.y, c4.z, c4.w};
    float ss[4] = {s4.x, s4.y, s4.z, s4.w};

    const float* base = g_qkv + (size_t)row * QKVN + h * HD;
    float4 qa4 = *(const float4*)(base + jq);
    float4 qb4 = *(const float4*)(base + jq + 64);
    float4 ka4 = *(const float4*)(base + HID + jq);
    float4 kb4 = *(const float4*)(base + HID + jq + 64);
    float4 va4 = *(const float4*)(base + 2 * HID + jq);
    float4 vb4 = *(const float4*)(base + 2 * HID + jq + 64);
    float q1[4] = {qa4.x, qa4.y, qa4.z, qa4.w};
    float q2[4] = {qb4.x, qb4.y, qb4.z, qb4.w};
    float k1[4] = {ka4.x, ka4.y, ka4.z, ka4.w};
    float k2[4] = {kb4.x, kb4.y, kb4.z, kb4.w};
    float v1[4] = {va4.x, va4.y, va4.z, va4.w};
    float v2[4] = {vb4.x, vb4.y, vb4.z, vb4.w};

    float qa[4], qb[4], ka[4], kb[4];
#pragma unroll
    for (int e = 0; e < 4; e++) {
        qa[e] = q1[e] * cc[e] - q2[e] * ss[e];
        qb[e] = q2[e] * cc[e] + q1[e] * ss[e];
        ka[e] = k1[e] * cc[e] - k2[e] * ss[e];
        kb[e] = k2[e] * cc[e] + k1[e] * ss[e];
    }

    size_t pb = ((size_t)(bh * 2) * SEQ + s) * HD;   // hi plane; lo = +SEQ*HD
    const size_t PL = (size_t)SEQ * HD;
    uint2 hi, lo;
    pack4(qa, hi, lo);
    *(uint2*)(g_qp + pb + jq)           = hi; *(uint2*)(g_qp + pb + PL + jq)           = lo;
    pack4(qb, hi, lo);
    *(uint2*)(g_qp + pb + jq + 64)      = hi; *(uint2*)(g_qp + pb + PL + jq + 64)      = lo;
    pack4(ka, hi, lo);
    *(uint2*)(g_kp + pb + jq)           = hi; *(uint2*)(g_kp + pb + PL + jq)           = lo;
    pack4(kb, hi, lo);
    *(uint2*)(g_kp + pb + jq + 64)      = hi; *(uint2*)(g_kp + pb + PL + jq + 64)      = lo;
    pack4(v1, hi, lo);
    *(uint2*)(g_vp + pb + jq)           = hi; *(uint2*)(g_vp + pb + PL + jq)           = lo;
    pack4(v2, hi, lo);
    *(uint2*)(g_vp + pb + jq + 64)      = hi; *(uint2*)(g_vp + pb + PL + jq + 64)      = lo;
}

// ---------------------------------------------------------------------------
// bf16x3 tensor-core GEMM v4 (unchanged from round 7 — passing).
// ---------------------------------------------------------------------------
#define AST         72
#define STG_MAT     (128 * AST * 2)
#define STG_BYTES   (2 * STG_MAT)
#define GEMM_STAGES 3
#define GEMM_SMEM   (GEMM_STAGES * STG_BYTES)
#define GNITER      96

__device__ __forceinline__ void g_load_stage(
    uint32_t sA, const __nv_bfloat16* Ab, const __nv_bfloat16* Bb, int tid)
{
#pragma unroll
    for (int t = 0; t < 8; t++) {
        int c = tid + t * 128;
        int r = c >> 3, co = (c & 7) << 3;
        CP_ASYNC16(sA + (r * AST + co) * 2, Ab + (size_t)r * KPACK + co);
        CP_ASYNC16(sA + STG_MAT + (r * AST + co) * 2, Bb + (size_t)r * KPACK + co);
    }
}

__global__ void __launch_bounds__(128, 2) tc_gemm_kernel(
    const __nv_bfloat16* __restrict__ A, const __nv_bfloat16* __restrict__ B,
    float* __restrict__ C, int ldc)
{
    extern __shared__ char smg[];
    uint32_t smb = s2u(smg);
    int tid  = threadIdx.x;
    int lane = tid & 31, wid = tid >> 5;
    int wm = (wid & 1) * 64, wn = (wid >> 1) * 64;
    int m0 = blockIdx.y * 128, n0 = blockIdx.x * 128;

    float acc[4][8][4];
#pragma unroll
    for (int i = 0; i < 4; i++)
#pragma unroll
        for (int j = 0; j < 8; j++)
#pragma unroll
            for (int k = 0; k < 4; k++) acc[i][j][k] = 0.f;

    auto chunk_off = [&](int it, int& aoff, int& boff, int& k0) {
        int pass = it >> 5;
        k0   = (it & 31) << 6;
        aoff = (pass == 2) ? 2048 : 0;
        boff = (pass == 1) ? 2048 : 0;
    };

    uint32_t a_off[4][4], b_off[4][4];
#pragma unroll
    for (int ks = 0; ks < 4; ks++) {
#pragma unroll
        for (int mt = 0; mt < 4; mt++)
            a_off[ks][mt] = ((wm + mt * 16 + (lane & 15)) * AST +
                             ks * 16 + (lane >> 4) * 8) * 2;
#pragma unroll
        for (int np = 0; np < 4; np++)
            b_off[ks][np] = STG_MAT +
                ((wn + np * 16 + ((lane >> 4) & 1) * 8 + (lane & 7)) * AST +
                 ks * 16 + ((lane >> 3) & 1) * 8) * 2;
    }

#pragma unroll
    for (int p = 0; p < GEMM_STAGES - 1; p++) {
        int aoff, boff, k0;
        chunk_off(p, aoff, boff, k0);
        g_load_stage(smb + p * STG_BYTES,
                     A + (size_t)m0 * KPACK + aoff + k0,
                     B + (size_t)n0 * KPACK + boff + k0, tid);
        CP_COMMIT();
    }
    CP_WAIT1();
    __syncthreads();

    uint32_t af[2][4][4], bf[2][4];
#pragma unroll
    for (int mt = 0; mt < 4; mt++) LDSM4(af[0][mt], smb + a_off[0][mt]);
    LDSM4(bf[0], smb + b_off[0][0]);

    for (int it = 0; it < GNITER; ++it) {
        uint32_t sbase = smb + (it % GEMM_STAGES) * STG_BYTES;

        int nx = it + GEMM_STAGES - 1;
        if (nx < GNITER) {
            int aoff, boff, k0;
            chunk_off(nx, aoff, boff, k0);
            g_load_stage(smb + (nx % GEMM_STAGES) * STG_BYTES,
                         A + (size_t)m0 * KPACK + aoff + k0,
                         B + (size_t)n0 * KPACK + boff + k0, tid);
        }
        CP_COMMIT();

#pragma unroll
        for (int ks = 0; ks < 4; ks++) {
            int cur = ks & 1, nxt = cur ^ 1;
            uint32_t bb[2][4];
#pragma unroll
            for (int e = 0; e < 4; e++) bb[0][e] = bf[cur][e];
#pragma unroll
            for (int np = 0; np < 4; np++) {
                if (np < 3) LDSM4(bb[(np + 1) & 1], sbase + b_off[ks][np + 1]);
#pragma unroll
                for (int mt = 0; mt < 4; mt++) {
                    MMA16816(acc[mt][2 * np],     af[cur][mt], bb[np & 1][0], bb[np & 1][1]);
                    MMA16816(acc[mt][2 * np + 1], af[cur][mt], bb[np & 1][2], bb[np & 1][3]);
                }
            }
            if (ks < 3) {
#pragma unroll
                for (int mt = 0; mt < 4; mt++)
                    LDSM4(af[nxt][mt], sbase + a_off[ks + 1][mt]);
                LDSM4(bf[nxt], sbase + b_off[ks + 1][0]);
            }
        }

        CP_WAIT1();
        __syncthreads();
        uint32_t nbase = smb + ((it + 1) % GEMM_STAGES) * STG_BYTES;
#pragma unroll
        for (int mt = 0; mt < 4; mt++) LDSM4(af[0][mt], nbase + a_off[0][mt]);
        LDSM4(bf[0], nbase + b_off[0][0]);
    }

    float* Cb = C + (size_t)(m0 + wm) * ldc + n0 + wn;
    int rq = lane >> 2, cq = (lane & 3) * 2;
#pragma unroll
    for (int mt = 0; mt < 4; mt++)
#pragma unroll
        for (int nt = 0; nt < 8; nt++) {
            *(float2*)(Cb + (size_t)(mt * 16 + rq) * ldc + nt * 8 + cq) =
                make_float2(acc[mt][nt][0], acc[mt][nt][1]);
            *(float2*)(Cb + (size_t)(mt * 16 + rq + 8) * ldc + nt * 8 + cq) =
                make_float2(acc[mt][nt][2], acc[mt][nt][3]);
        }
}

// ---------------------------------------------------------------------------
// Tensor-core flash attention v2 (bf16x3 split, causal, online softmax).
// Q fragments register-resident (loaded once); 3-stage KV cp.async ring;
// ONE __syncthreads per K-tile (wait-before-sync pattern).
// ---------------------------------------------------------------------------
#define AKST     136
#define AROWB    (AKST * 2)                 // 272 B
#define QPLANE   (128 * AROWB)              // 34816
#define KVPLANE  (64 * AROWB)               // 17408
#define STAGE_B  (4 * KVPLANE)              // 69632
#define KVSTAGES 3
#define ATTN_SMEM (KVSTAGES * STAGE_B)      // 208896

__device__ __forceinline__ void load_kv_stage(
    uint32_t dst, const __nv_bfloat16* Kp, const __nv_bfloat16* Vp,
    int k0, int tid)
{
#pragma unroll
    for (int t = 0; t < 16; t++) {
        int c = tid + t * 256;
        int plane = c >> 10;                // 0:Kh 1:Kl 2:Vh 3:Vl
        int r = (c >> 4) & 63;
        int co = c & 15;
        const __nv_bfloat16* src = (plane < 2)
            ? Kp + ((size_t)plane * SEQ + k0 + r) * HD + co * 8
            : Vp + ((size_t)(plane - 2) * SEQ + k0 + r) * HD + co * 8;
        CP_ASYNC16(dst + plane * KVPLANE + r * AROWB + co * 16, src);
    }
}

__global__ void __launch_bounds__(256) attn_mma_kernel() {
    extern __shared__ char sma[];
    uint32_t smb = s2u(sma);
    int tid = threadIdx.x, lane = tid & 31, w = tid >> 5;
    int qt = (int)gridDim.x - 1 - (int)blockIdx.x;
    int bh = blockIdx.y;
    int q0 = qt * 128;
    int nkt = 2 * qt + 2;

    const __nv_bfloat16* Qp = g_qp + (size_t)(bh * 2) * SEQ * HD;
    const __nv_bfloat16* Kp = g_kp + (size_t)(bh * 2) * SEQ * HD;
    const __nv_bfloat16* Vp = g_vp + (size_t)(bh * 2) * SEQ * HD;

    // group 0: Q tile staged into ring slot 2 (2 planes x 128 rows = STAGE_B)
    uint32_t sQstage = smb + 2 * STAGE_B;
#pragma unroll
    for (int t = 0; t < 16; t++) {
        int c = tid + t * 256;
        int plane = c >> 11, r = (c >> 4) & 127, co = c & 15;
        CP_ASYNC16(sQstage + plane * QPLANE + r * AROWB + co * 16,
                   Qp + ((size_t)plane * SEQ + q0 + r) * HD + co * 8);
    }
    CP_COMMIT();
    // groups 1,2: KV tiles 0,1 into slots 0,1 (nkt >= 2 always)
    load_kv_stage(smb, Kp, Vp, 0, tid);
    CP_COMMIT();
    load_kv_stage(smb + STAGE_B, Kp, Vp, 64, tid);
    CP_COMMIT();

    int rq = lane >> 2, cq = lane & 3;
    uint32_t qoff = (uint32_t)(16 * w + (lane & 15)) * AROWB + ((lane >> 4) & 1) * 16;
    uint32_t koff = (uint32_t)(((lane >> 4) & 1) * 8 + (lane & 7)) * AROWB +
                    ((lane >> 3) & 1) * 16;
    uint32_t voff = (uint32_t)(((lane >> 3) & 1) * 8 + (lane & 7)) * AROWB +
                    ((lane >> 4) & 1) * 16;

    // Q fragments -> registers (once)
    CP_WAIT2();                 // group 0 (Q) complete
    __syncthreads();
    uint32_t qfh[8][4], qfl[8][4];
#pragma unroll
    for (int kc = 0; kc < 8; kc++) {
        LDSM4(qfh[kc], sQstage + qoff + kc * 32);
        LDSM4(qfl[kc], sQstage + QPLANE + qoff + kc * 32);
    }

    float out[16][4];
#pragma unroll
    for (int n = 0; n < 16; n++)
#pragma unroll
        for (int e = 0; e < 4; e++) out[n][e] = 0.f;
    float m0 = -1e30f, m1 = -1e30f, l0 = 0.f, l1 = 0.f;

    const float SCALE2 = 0.08838834764831845f * 1.44269504088896341f;

    // stage kt loaded by cp.async group kt+1; at iter kt groups <= kt+2
    // are committed, so wait_group 1 drains group kt+1 -> stage kt ready.
    for (int kt = 0; kt < nkt; kt++) {
        CP_WAIT1();             // own writes for stage kt complete
        __syncthreads();        // publish stage kt; all warps past stage kt-1
                                // (and past Q-frag loads when kt==0)
        if (kt + 2 < nkt)
            load_kv_stage(smb + ((kt + 2) % KVSTAGES) * STAGE_B, Kp, Vp,
                          (kt + 2) * 64, tid);
        CP_COMMIT();            // commit every iter to keep group counting

        uint32_t sKh = smb + (kt % KVSTAGES) * STAGE_B;
        uint32_t sKl = sKh + KVPLANE;
        uint32_t sVh = sKh + 2 * KVPLANE;
        uint32_t sVl = sKh + 3 * KVPLANE;

        // ---- scores: S = Qh*Kh + Qh*Kl + Ql*Kh ----
        float sc[8][4];
#pragma unroll
        for (int j = 0; j < 8; j++)
#pragma unroll
            for (int e = 0; e < 4; e++) sc[j][e] = 0.f;

#pragma unroll
        for (int kc = 0; kc < 8; kc++) {
#pragma unroll
            for (int jj = 0; jj < 4; jj++) {
                uint32_t bkh[4], bkl[4];
                uint32_t o = koff + (uint32_t)jj * (16 * AROWB) + kc * 32;
                LDSM4(bkh, sKh + o);
                LDSM4(bkl, sKl + o);
                MMA16816(sc[2 * jj],     qfh[kc], bkh[0], bkh[1]);
                MMA16816(sc[2 * jj],     qfh[kc], bkl[0], bkl[1]);
                MMA16816(sc[2 * jj],     qfl[kc], bkh[0], bkh[1]);
                MMA16816(sc[2 * jj + 1], qfh[kc], bkh[2], bkh[3]);
                MMA16816(sc[2 * jj + 1], qfh[kc], bkl[2], bkl[3]);
                MMA16816(sc[2 * jj + 1], qfl[kc], bkh[2], bkh[3]);
            }
        }

        int k0 = kt * 64;
#pragma unroll
        for (int j = 0; j < 8; j++)
#pragma unroll
            for (int e = 0; e < 4; e++) sc[j][e] *= SCALE2;
        if (k0 + 64 > q0) {
            int rg0 = q0 + 16 * w + rq, rg1 = rg0 + 8;
#pragma unroll
            for (int j = 0; j < 8; j++) {
                int cg = k0 + 8 * j + 2 * cq;
                if (cg     > rg0) sc[j][0] = -1e30f;
                if (cg + 1 > rg0) sc[j][1] = -1e30f;
                if (cg     > rg1) sc[j][2] = -1e30f;
                if (cg + 1 > rg1) sc[j][3] = -1e30f;
            }
        }

        float t0 = -1e30f, t1 = -1e30f;
#pragma unroll
        for (int j = 0; j < 8; j++) {
            t0 = fmaxf(t0, fmaxf(sc[j][0], sc[j][1]));
            t1 = fmaxf(t1, fmaxf(sc[j][2], sc[j][3]));
        }
        t0 = fmaxf(t0, __shfl_xor_sync(0xffffffffu, t0, 1));
        t0 = fmaxf(t0, __shfl_xor_sync(0xffffffffu, t0, 2));
        t1 = fmaxf(t1, __shfl_xor_sync(0xffffffffu, t1, 1));
        t1 = fmaxf(t1, __shfl_xor_sync(0xffffffffu, t1, 2));
        float mn0 = fmaxf(m0, t0), mn1 = fmaxf(m1, t1);
        float al0 = ex2f(m0 - mn0), al1 = ex2f(m1 - mn1);
        m0 = mn0; m1 = mn1;
        l0 *= al0; l1 *= al1;
#pragma unroll
        for (int n = 0; n < 16; n++) {
            out[n][0] *= al0; out[n][1] *= al0;
            out[n][2] *= al1; out[n][3] *= al1;
        }

#pragma unroll
        for (int kc = 0; kc < 4; kc++) {
            int j0 = 2 * kc, j1 = 2 * kc + 1;
            float p00 = ex2f(sc[j0][0] - m0), p01 = ex2f(sc[j0][1] - m0);
            float p02 = ex2f(sc[j0][2] - m1), p03 = ex2f(sc[j0][3] - m1);
            float p10 = ex2f(sc[j1][0] - m0), p11 = ex2f(sc[j1][1] - m0);
            float p12 = ex2f(sc[j1][2] - m1), p13 = ex2f(sc[j1][3] - m1);
            l0 += p00 + p01 + p10 + p11;
            l1 += p02 + p03 + p12 + p13;

            uint32_t ah[4], al_[4];
            ah[0] = packbf(p01, p00);
            ah[1] = packbf(p03, p02);
            ah[2] = packbf(p11, p10);
            ah[3] = packbf(p13, p12);
            float h;
            h = __uint_as_float(ah[0] << 16);          float q00 = p00 - h;
            h = __uint_as_float(ah[0] & 0xffff0000u);  float q01 = p01 - h;
            h = __uint_as_float(ah[1] << 16);          float q02 = p02 - h;
            h = __uint_as_float(ah[1] & 0xffff0000u);  float q03 = p03 - h;
            h = __uint_as_float(ah[2] << 16);          float q10 = p10 - h;
            h = __uint_as_float(ah[2] & 0xffff0000u);  float q11 = p11 - h;
            h = __uint_as_float(ah[3] << 16);          float q12 = p12 - h;
            h = __uint_as_float(ah[3] & 0xffff0000u);  float q13 = p13 - h;
            al_[0] = packbf(q01, q00);
            al_[1] = packbf(q03, q02);
            al_[2] = packbf(q11, q10);
            al_[3] = packbf(q13, q12);

#pragma unroll
            for (int jp = 0; jp < 8; jp++) {
                uint32_t bvh[4], bvl[4];
                uint32_t o = voff + (uint32_t)kc * (16 * AROWB) + jp * 32;
                LDSM4T(bvh, sVh + o);
                LDSM4T(bvl, sVl + o);
                MMA16816(out[2 * jp],     ah,  bvh[0], bvh[1]);
                MMA16816(out[2 * jp],     ah,  bvl[0], bvl[1]);
                MMA16816(out[2 * jp],     al_, bvh[0], bvh[1]);
                MMA16816(out[2 * jp + 1], ah,  bvh[2], bvh[3]);
                MMA16816(out[2 * jp + 1], ah,  bvl[2], bvl[3]);
                MMA16816(out[2 * jp + 1], al_, bvh[2], bvh[3]);
            }
        }
    }

    l0 += __shfl_xor_sync(0xffffffffu, l0, 1);
    l0 += __shfl_xor_sync(0xffffffffu, l0, 2);
    l1 += __shfl_xor_sync(0xffffffffu, l1, 1);
    l1 += __shfl_xor_sync(0xffffffffu, l1, 2);
    float il0 = 1.f / l0, il1 = 1.f / l1;

    int b = bh >> 4, hh = bh & 15;
    float* ob = g_ctx + ((size_t)(b * SEQ + q0 + 16 * w)) * HID + hh * HD;
#pragma unroll
    for (int nt = 0; nt < 16; nt++) {
        int col = nt * 8 + 2 * cq;
        *(float2*)(ob + (size_t)rq * HID + col) =
            make_float2(out[nt][0] * il0, out[nt][1] * il0);
        *(float2*)(ob + (size_t)(rq + 8) * HID + col) =
            make_float2(out[nt][2] * il1, out[nt][3] * il1);
    }
}

// ---------------------------------------------------------------------------
// Launch graph (idx 3 = QKV GEMM, the ncu capture slot)
// ---------------------------------------------------------------------------
extern "C" void kernel_launch(void* const* d_in, const int* in_sizes, int n_in,
                              void* d_out, int out_size) {
    const float* x    = (const float*)d_in[0];
    // d_in[1] = attn_mask (pure causal) — reproduced analytically, not read
    const float* Wqkv = (const float*)d_in[2];
    const float* Wout = (const float*)d_in[3];
    float* out = (float*)d_out;

    float *qkv_ptr = 0, *ctx_ptr = 0;
    __nv_bfloat16 *xp = 0, *wqp = 0, *wop = 0, *cxp = 0;
    cudaGetSymbolAddress((void**)&qkv_ptr, g_qkv);
    cudaGetSymbolAddress((void**)&ctx_ptr, g_ctx);
    cudaGetSymbolAddress((void**)&xp,  g_xp);
    cudaGetSymbolAddress((void**)&wqp, g_wqp);
    cudaGetSymbolAddress((void**)&wop, g_wop);
    cudaGetSymbolAddress((void**)&cxp, g_cxp);

    cudaFuncSetAttribute(tc_gemm_kernel,
                         cudaFuncAttributeMaxDynamicSharedMemorySize, GEMM_SMEM);
    cudaFuncSetAttribute(attn_mma_kernel,
                         cudaFuncAttributeMaxDynamicSharedMemorySize, ATTN_SMEM);

    // idx 0..2: packs (vectorized, 8 elems/thread)
    pack_kernel<<<MROWS * HID / 2048, 256>>>(x, xp, MROWS * HID);
    pack_kernel<<<QKVN  * HID / 2048, 256>>>(Wqkv, wqp, QKVN * HID);
    pack_kernel<<<HID   * HID / 2048, 256>>>(Wout, wop, HID * HID);

    // idx 3: QKV GEMM (ncu capture slot)
    tc_gemm_kernel<<<dim3(QKVN / 128, MROWS / 128), 128, GEMM_SMEM>>>(
        xp, wqp, qkv_ptr, QKVN);

    // idx 4..5: RoPE table + qkv pack
    rope_table_kernel<<<(SEQ * 64 + 255) / 256, 256>>>();
    qkv_pack_kernel<<<MROWS * NH * 16 / 256, 256>>>();

    // idx 6: attention
    attn_mma_kernel<<<dim3(SEQ / 128, BATCH * NH), 256, ATTN_SMEM>>>();

    // idx 7..8: ctx pack + output GEMM
    pack_kernel<<<MROWS * HID / 2048, 256>>>(ctx_ptr, cxp, MROWS * HID);
    tc_gemm_kernel<<<dim3(HID / 128, MROWS / 128), 128, GEMM_SMEM>>>(
        cxp, wop, out, HID);
}

// round 9
// speedup vs baseline: 6.7232x; 1.0678x over previous
#include <cuda_runtime.h>
#include <cuda_bf16.h>
#include <math.h>
#include <stdint.h>

// Problem constants
#define SEQ   2048
#define HID   2048
#define NH    16
#define HD    128
#define BATCH 2
#define MROWS (BATCH * SEQ)     // 4096
#define QKVN  (3 * HID)         // 6144
#define KPACK 4096              // packed row length: [hi(2048) | lo(2048)]

// ---------------------------------------------------------------------------
// Scratch (device globals — no runtime allocation allowed)
// ---------------------------------------------------------------------------
__device__ __align__(16) float g_qkv[(size_t)MROWS * QKVN];    // fp32 QKV
__device__ __align__(16) float g_cos[SEQ * 64];
__device__ __align__(16) float g_sin[SEQ * 64];
__device__ __align__(16) __nv_bfloat16 g_xp  [(size_t)MROWS * KPACK];
__device__ __align__(16) __nv_bfloat16 g_wqp [(size_t)QKVN  * KPACK];
__device__ __align__(16) __nv_bfloat16 g_wop [(size_t)HID   * KPACK];
__device__ __align__(16) __nv_bfloat16 g_cxp [(size_t)MROWS * KPACK];
// attention operands: [bh*2 + plane(hi=0,lo=1)][s][128]
__device__ __align__(16) __nv_bfloat16 g_qp[(size_t)BATCH * NH * 2 * SEQ * HD];
__device__ __align__(16) __nv_bfloat16 g_kp[(size_t)BATCH * NH * 2 * SEQ * HD];
__device__ __align__(16) __nv_bfloat16 g_vp[(size_t)BATCH * NH * 2 * SEQ * HD];

// ---------------------------------------------------------------------------
// PTX helpers (arch-agnostic: cp.async / ldmatrix / mma.sync only)
// ---------------------------------------------------------------------------
__device__ __forceinline__ uint32_t s2u(const void* p) {
    uint32_t a;
    asm("{ .reg .u64 t; cvta.to.shared.u64 t, %1; cvt.u32.u64 %0, t; }"
        : "=r"(a) : "l"(p));
    return a;
}

#define CP_ASYNC16(saddr, gptr) \
    asm volatile("cp.async.cg.shared.global [%0], [%1], 16;" \
                 :: "r"(saddr), "l"(gptr))
#define CP_COMMIT()  asm volatile("cp.async.commit_group;" ::: "memory")
#define CP_WAIT1()   asm volatile("cp.async.wait_group 1;" ::: "memory")
#define CP_WAIT2()   asm volatile("cp.async.wait_group 2;" ::: "memory")

#define LDSM4(r, addr)                                                        \
    asm volatile("ldmatrix.sync.aligned.m8n8.x4.shared.b16 {%0,%1,%2,%3}, [%4];" \
        : "=r"((r)[0]), "=r"((r)[1]), "=r"((r)[2]), "=r"((r)[3]) : "r"(addr))
#define LDSM4T(r, addr)                                                       \
    asm volatile("ldmatrix.sync.aligned.m8n8.x4.trans.shared.b16 {%0,%1,%2,%3}, [%4];" \
        : "=r"((r)[0]), "=r"((r)[1]), "=r"((r)[2]), "=r"((r)[3]) : "r"(addr))

#define MMA16816(d, a, b0, b1)                                                \
    asm volatile("mma.sync.aligned.m16n8k16.row.col.f32.bf16.bf16.f32 "       \
        "{%0,%1,%2,%3},{%4,%5,%6,%7},{%8,%9},{%0,%1,%2,%3};"                  \
        : "+f"((d)[0]), "+f"((d)[1]), "+f"((d)[2]), "+f"((d)[3])              \
        : "r"((a)[0]), "r"((a)[1]), "r"((a)[2]), "r"((a)[3]),                 \
          "r"(b0), "r"(b1))

__device__ __forceinline__ float ex2f(float x) {
    float y;
    asm("ex2.approx.ftz.f32 %0, %1;" : "=f"(y) : "f"(x));
    return y;
}
__device__ __forceinline__ uint32_t packbf(float hi, float lo) {
    uint32_t d;
    asm("cvt.rn.bf16x2.f32 %0, %1, %2;" : "=r"(d) : "f"(hi), "f"(lo));
    return d;
}

// split 4 fp32 -> 4 bf16 hi (uint2) + 4 bf16 lo residuals (uint2)
__device__ __forceinline__ void pack4(const float* x, uint2& hi, uint2& lo) {
    uint32_t h0 = packbf(x[1], x[0]);
    uint32_t h1 = packbf(x[3], x[2]);
    float f0 = __uint_as_float(h0 << 16);
    float f1 = __uint_as_float(h0 & 0xffff0000u);
    float f2 = __uint_as_float(h1 << 16);
    float f3 = __uint_as_float(h1 & 0xffff0000u);
    hi.x = h0; hi.y = h1;
    lo.x = packbf(x[1] - f1, x[0] - f0);
    lo.y = packbf(x[3] - f3, x[2] - f2);
}

// split 2 fp32 -> bf16x2 hi word + bf16x2 lo-residual word
__device__ __forceinline__ void pack2(float a0, float a1, uint32_t& h, uint32_t& l) {
    h = packbf(a1, a0);
    float f0 = __uint_as_float(h << 16);
    float f1 = __uint_as_float(h & 0xffff0000u);
    l = packbf(a1 - f1, a0 - f0);
}

// ---------------------------------------------------------------------------
// RoPE table (reference-matching numerics)
// ---------------------------------------------------------------------------
__global__ void rope_table_kernel() {
    int idx = blockIdx.x * blockDim.x + threadIdx.x;
    if (idx >= SEQ * 64) return;
    int s = idx >> 6;
    int j = idx & 63;
    double inv = exp(-((double)j / 64.0) * log(10000.0));
    float  invf = (float)inv;
    float  ang  = (float)s * invf;
    g_cos[idx] = (float)cos((double)ang);
    g_sin[idx] = (float)sin((double)ang);
}

// ---------------------------------------------------------------------------
// fp32 -> split bf16 pack (vectorized: 8 elems/thread, uint4 stores)
// ---------------------------------------------------------------------------
__global__ void pack_kernel(const float* __restrict__ X,
                            __nv_bfloat16* __restrict__ P, int n) {
    int i = (blockIdx.x * 256 + threadIdx.x) * 8;
    if (i >= n) return;
    int row = i >> 11, col = i & 2047;
    float4 a = *(const float4*)(X + i);
    float4 b = *(const float4*)(X + i + 4);
    float v0[4] = {a.x, a.y, a.z, a.w};
    float v1[4] = {b.x, b.y, b.z, b.w};
    uint2 h0, l0, h1, l1;
    pack4(v0, h0, l0);
    pack4(v1, h1, l1);
    uint4* Ph = (uint4*)(P + (size_t)row * KPACK + col);
    uint4* Pl = (uint4*)(P + (size_t)row * KPACK + 2048 + col);
    *Ph = make_uint4(h0.x, h0.y, h1.x, h1.y);
    *Pl = make_uint4(l0.x, l0.y, l1.x, l1.y);
}

// ---------------------------------------------------------------------------
// QKV pack: RoPE on q,k + hi/lo bf16 split of q,k,v (vectorized, 4 j/thread)
// ---------------------------------------------------------------------------
__global__ void qkv_pack_kernel() {
    int idx = blockIdx.x * blockDim.x + threadIdx.x;   // MROWS*NH*16
    int jq  = (idx & 15) << 2;                          // 0,4,...,60
    int h   = (idx >> 4) & (NH - 1);
    int row = idx >> 8;
    int s   = row & (SEQ - 1);
    int b   = row >> 11;
    int bh  = b * NH + h;

    float4 c4 = *(const float4*)&g_cos[(s << 6) + jq];
    float4 s4 = *(const float4*)&g_sin[(s << 6) + jq];
    float cc[4] = {c4.x, c4.y, c4.z, c4.w};
    float ss[4] = {s4.x, s4.y, s4.z, s4.w};

    const float* base = g_qkv + (size_t)row * QKVN + h * HD;
    float4 qa4 = *(const float4*)(base + jq);
    float4 qb4 = *(const float4*)(base + jq + 64);
    float4 ka4 = *(const float4*)(base + HID + jq);
    float4 kb4 = *(const float4*)(base + HID + jq + 64);
    float4 va4 = *(const float4*)(base + 2 * HID + jq);
    float4 vb4 = *(const float4*)(base + 2 * HID + jq + 64);
    float q1[4] = {qa4.x, qa4.y, qa4.z, qa4.w};
    float q2[4] = {qb4.x, qb4.y, qb4.z, qb4.w};
    float k1[4] = {ka4.x, ka4.y, ka4.z, ka4.w};
    float k2[4] = {kb4.x, kb4.y, kb4.z, kb4.w};
    float v1[4] = {va4.x, va4.y, va4.z, va4.w};
    float v2[4] = {vb4.x, vb4.y, vb4.z, vb4.w};

    float qa[4], qb[4], ka[4], kb[4];
#pragma unroll
    for (int e = 0; e < 4; e++) {
        qa[e] = q1[e] * cc[e] - q2[e] * ss[e];
        qb[e] = q2[e] * cc[e] + q1[e] * ss[e];
        ka[e] = k1[e] * cc[e] - k2[e] * ss[e];
        kb[e] = k2[e] * cc[e] + k1[e] * ss[e];
    }

    size_t pb = ((size_t)(bh * 2) * SEQ + s) * HD;   // hi plane; lo = +SEQ*HD
    const size_t PL = (size_t)SEQ * HD;
    uint2 hi, lo;
    pack4(qa, hi, lo);
    *(uint2*)(g_qp + pb + jq)           = hi; *(uint2*)(g_qp + pb + PL + jq)           = lo;
    pack4(qb, hi, lo);
    *(uint2*)(g_qp + pb + jq + 64)      = hi; *(uint2*)(g_qp + pb + PL + jq + 64)      = lo;
    pack4(ka, hi, lo);
    *(uint2*)(g_kp + pb + jq)           = hi; *(uint2*)(g_kp + pb + PL + jq)           = lo;
    pack4(kb, hi, lo);
    *(uint2*)(g_kp + pb + jq + 64)      = hi; *(uint2*)(g_kp + pb + PL + jq + 64)      = lo;
    pack4(v1, hi, lo);
    *(uint2*)(g_vp + pb + jq)           = hi; *(uint2*)(g_vp + pb + PL + jq)           = lo;
    pack4(v2, hi, lo);
    *(uint2*)(g_vp + pb + jq + 64)      = hi; *(uint2*)(g_vp + pb + PL + jq + 64)      = lo;
}

// ---------------------------------------------------------------------------
// bf16x3 tensor-core GEMM v4 (unchanged — control kernel at ncu idx 3).
// ---------------------------------------------------------------------------
#define AST         72
#define STG_MAT     (128 * AST * 2)
#define STG_BYTES   (2 * STG_MAT)
#define GEMM_STAGES 3
#define GEMM_SMEM   (GEMM_STAGES * STG_BYTES)
#define GNITER      96

__device__ __forceinline__ void g_load_stage(
    uint32_t sA, const __nv_bfloat16* Ab, const __nv_bfloat16* Bb, int tid)
{
#pragma unroll
    for (int t = 0; t < 8; t++) {
        int c = tid + t * 128;
        int r = c >> 3, co = (c & 7) << 3;
        CP_ASYNC16(sA + (r * AST + co) * 2, Ab + (size_t)r * KPACK + co);
        CP_ASYNC16(sA + STG_MAT + (r * AST + co) * 2, Bb + (size_t)r * KPACK + co);
    }
}

__global__ void __launch_bounds__(128, 2) tc_gemm_kernel(
    const __nv_bfloat16* __restrict__ A, const __nv_bfloat16* __restrict__ B,
    float* __restrict__ C, int ldc)
{
    extern __shared__ char smg[];
    uint32_t smb = s2u(smg);
    int tid  = threadIdx.x;
    int lane = tid & 31, wid = tid >> 5;
    int wm = (wid & 1) * 64, wn = (wid >> 1) * 64;
    int m0 = blockIdx.y * 128, n0 = blockIdx.x * 128;

    float acc[4][8][4];
#pragma unroll
    for (int i = 0; i < 4; i++)
#pragma unroll
        for (int j = 0; j < 8; j++)
#pragma unroll
            for (int k = 0; k < 4; k++) acc[i][j][k] = 0.f;

    auto chunk_off = [&](int it, int& aoff, int& boff, int& k0) {
        int pass = it >> 5;
        k0   = (it & 31) << 6;
        aoff = (pass == 2) ? 2048 : 0;
        boff = (pass == 1) ? 2048 : 0;
    };

    uint32_t a_off[4][4], b_off[4][4];
#pragma unroll
    for (int ks = 0; ks < 4; ks++) {
#pragma unroll
        for (int mt = 0; mt < 4; mt++)
            a_off[ks][mt] = ((wm + mt * 16 + (lane & 15)) * AST +
                             ks * 16 + (lane >> 4) * 8) * 2;
#pragma unroll
        for (int np = 0; np < 4; np++)
            b_off[ks][np] = STG_MAT +
                ((wn + np * 16 + ((lane >> 4) & 1) * 8 + (lane & 7)) * AST +
                 ks * 16 + ((lane >> 3) & 1) * 8) * 2;
    }

#pragma unroll
    for (int p = 0; p < GEMM_STAGES - 1; p++) {
        int aoff, boff, k0;
        chunk_off(p, aoff, boff, k0);
        g_load_stage(smb + p * STG_BYTES,
                     A + (size_t)m0 * KPACK + aoff + k0,
                     B + (size_t)n0 * KPACK + boff + k0, tid);
        CP_COMMIT();
    }
    CP_WAIT1();
    __syncthreads();

    uint32_t af[2][4][4], bf[2][4];
#pragma unroll
    for (int mt = 0; mt < 4; mt++) LDSM4(af[0][mt], smb + a_off[0][mt]);
    LDSM4(bf[0], smb + b_off[0][0]);

    for (int it = 0; it < GNITER; ++it) {
        uint32_t sbase = smb + (it % GEMM_STAGES) * STG_BYTES;

        int nx = it + GEMM_STAGES - 1;
        if (nx < GNITER) {
            int aoff, boff, k0;
            chunk_off(nx, aoff, boff, k0);
            g_load_stage(smb + (nx % GEMM_STAGES) * STG_BYTES,
                         A + (size_t)m0 * KPACK + aoff + k0,
                         B + (size_t)n0 * KPACK + boff + k0, tid);
        }
        CP_COMMIT();

#pragma unroll
        for (int ks = 0; ks < 4; ks++) {
            int cur = ks & 1, nxt = cur ^ 1;
            uint32_t bb[2][4];
#pragma unroll
            for (int e = 0; e < 4; e++) bb[0][e] = bf[cur][e];
#pragma unroll
            for (int np = 0; np < 4; np++) {
                if (np < 3) LDSM4(bb[(np + 1) & 1], sbase + b_off[ks][np + 1]);
#pragma unroll
                for (int mt = 0; mt < 4; mt++) {
                    MMA16816(acc[mt][2 * np],     af[cur][mt], bb[np & 1][0], bb[np & 1][1]);
                    MMA16816(acc[mt][2 * np + 1], af[cur][mt], bb[np & 1][2], bb[np & 1][3]);
                }
            }
            if (ks < 3) {
#pragma unroll
                for (int mt = 0; mt < 4; mt++)
                    LDSM4(af[nxt][mt], sbase + a_off[ks + 1][mt]);
                LDSM4(bf[nxt], sbase + b_off[ks + 1][0]);
            }
        }

        CP_WAIT1();
        __syncthreads();
        uint32_t nbase = smb + ((it + 1) % GEMM_STAGES) * STG_BYTES;
#pragma unroll
        for (int mt = 0; mt < 4; mt++) LDSM4(af[0][mt], nbase + a_off[0][mt]);
        LDSM4(bf[0], nbase + b_off[0][0]);
    }

    float* Cb = C + (size_t)(m0 + wm) * ldc + n0 + wn;
    int rq = lane >> 2, cq = (lane & 3) * 2;
#pragma unroll
    for (int mt = 0; mt < 4; mt++)
#pragma unroll
        for (int nt = 0; nt < 8; nt++) {
            *(float2*)(Cb + (size_t)(mt * 16 + rq) * ldc + nt * 8 + cq) =
                make_float2(acc[mt][nt][0], acc[mt][nt][1]);
            *(float2*)(Cb + (size_t)(mt * 16 + rq + 8) * ldc + nt * 8 + cq) =
                make_float2(acc[mt][nt][2], acc[mt][nt][3]);
        }
}

// ---------------------------------------------------------------------------
// Tensor-core flash attention v3 (bf16x3 split, causal, online softmax).
// - 1-D grid ordered by DESCENDING work (LPT load balance)
// - Q fragments register-resident; 3-stage KV cp.async ring; 1 sync/K-tile
// - B-fragment double-buffering in score and PV loops
// - epilogue writes the hi/lo bf16 planes of g_cxp directly (ctx pack fused)
// ---------------------------------------------------------------------------
#define AKST     136
#define AROWB    (AKST * 2)                 // 272 B
#define QPLANE   (128 * AROWB)              // 34816
#define KVPLANE  (64 * AROWB)               // 17408
#define STAGE_B  (4 * KVPLANE)              // 69632
#define KVSTAGES 3
#define ATTN_SMEM (KVSTAGES * STAGE_B)      // 208896

__device__ __forceinline__ void load_kv_stage(
    uint32_t dst, const __nv_bfloat16* Kp, const __nv_bfloat16* Vp,
    int k0, int tid)
{
#pragma unroll
    for (int t = 0; t < 16; t++) {
        int c = tid + t * 256;
        int plane = c >> 10;                // 0:Kh 1:Kl 2:Vh 3:Vl
        int r = (c >> 4) & 63;
        int co = c & 15;
        const __nv_bfloat16* src = (plane < 2)
            ? Kp + ((size_t)plane * SEQ + k0 + r) * HD + co * 8
            : Vp + ((size_t)(plane - 2) * SEQ + k0 + r) * HD + co * 8;
        CP_ASYNC16(dst + plane * KVPLANE + r * AROWB + co * 16, src);
    }
}

__global__ void __launch_bounds__(256) attn_mma_kernel() {
    extern __shared__ char sma[];
    uint32_t smb = s2u(sma);
    int tid = threadIdx.x, lane = tid & 31, w = tid >> 5;
    // LPT: heaviest q-tiles (qt=15) dispatch first across all 32 (b,h)
    int qt = 15 - ((int)blockIdx.x >> 5);
    int bh = (int)blockIdx.x & 31;
    int q0 = qt * 128;
    int nkt = 2 * qt + 2;

    const __nv_bfloat16* Qp = g_qp + (size_t)(bh * 2) * SEQ * HD;
    const __nv_bfloat16* Kp = g_kp + (size_t)(bh * 2) * SEQ * HD;
    const __nv_bfloat16* Vp = g_vp + (size_t)(bh * 2) * SEQ * HD;

    // group 0: Q tile staged into ring slot 2 (2 planes x 128 rows = STAGE_B)
    uint32_t sQstage = smb + 2 * STAGE_B;
#pragma unroll
    for (int t = 0; t < 16; t++) {
        int c = tid + t * 256;
        int plane = c >> 11, r = (c >> 4) & 127, co = c & 15;
        CP_ASYNC16(sQstage + plane * QPLANE + r * AROWB + co * 16,
                   Qp + ((size_t)plane * SEQ + q0 + r) * HD + co * 8);
    }
    CP_COMMIT();
    // groups 1,2: KV tiles 0,1 into slots 0,1 (nkt >= 2 always)
    load_kv_stage(smb, Kp, Vp, 0, tid);
    CP_COMMIT();
    load_kv_stage(smb + STAGE_B, Kp, Vp, 64, tid);
    CP_COMMIT();

    int rq = lane >> 2, cq = lane & 3;
    uint32_t qoff = (uint32_t)(16 * w + (lane & 15)) * AROWB + ((lane >> 4) & 1) * 16;
    uint32_t koff = (uint32_t)(((lane >> 4) & 1) * 8 + (lane & 7)) * AROWB +
                    ((lane >> 3) & 1) * 16;
    uint32_t voff = (uint32_t)(((lane >> 3) & 1) * 8 + (lane & 7)) * AROWB +
                    ((lane >> 4) & 1) * 16;

    // Q fragments -> registers (once)
    CP_WAIT2();                 // group 0 (Q) complete
    __syncthreads();
    uint32_t qfh[8][4], qfl[8][4];
#pragma unroll
    for (int kc = 0; kc < 8; kc++) {
        LDSM4(qfh[kc], sQstage + qoff + kc * 32);
        LDSM4(qfl[kc], sQstage + QPLANE + qoff + kc * 32);
    }

    float out[16][4];
#pragma unroll
    for (int n = 0; n < 16; n++)
#pragma unroll
        for (int e = 0; e < 4; e++) out[n][e] = 0.f;
    float m0 = -1e30f, m1 = -1e30f, l0 = 0.f, l1 = 0.f;

    const float SCALE2 = 0.08838834764831845f * 1.44269504088896341f;

    // stage kt loaded by cp.async group kt+1; at iter kt groups <= kt+2
    // committed, so wait_group 1 drains group kt+1 -> stage kt ready.
    for (int kt = 0; kt < nkt; kt++) {
        CP_WAIT1();
        __syncthreads();
        if (kt + 2 < nkt)
            load_kv_stage(smb + ((kt + 2) % KVSTAGES) * STAGE_B, Kp, Vp,
                          (kt + 2) * 64, tid);
        CP_COMMIT();

        uint32_t sKh = smb + (kt % KVSTAGES) * STAGE_B;
        uint32_t sKl = sKh + KVPLANE;
        uint32_t sVh = sKh + 2 * KVPLANE;
        uint32_t sVl = sKh + 3 * KVPLANE;

        // ---- scores: S = Qh*Kh + Qh*Kl + Ql*Kh, double-buffered B frags ----
        float sc[8][4];
#pragma unroll
        for (int j = 0; j < 8; j++)
#pragma unroll
            for (int e = 0; e < 4; e++) sc[j][e] = 0.f;

        {
            uint32_t bkh[2][4], bkl[2][4];
            LDSM4(bkh[0], sKh + koff);
            LDSM4(bkl[0], sKl + koff);
#pragma unroll
            for (int t = 0; t < 32; t++) {
                int kc = t >> 2, jj = t & 3;
                int cur = t & 1;
                if (t < 31) {
                    int tn = t + 1;
                    uint32_t on = koff + (uint32_t)(tn & 3) * (16 * AROWB) +
                                  (tn >> 2) * 32;
                    LDSM4(bkh[cur ^ 1], sKh + on);
                    LDSM4(bkl[cur ^ 1], sKl + on);
                }
                MMA16816(sc[2 * jj],     qfh[kc], bkh[cur][0], bkh[cur][1]);
                MMA16816(sc[2 * jj],     qfh[kc], bkl[cur][0], bkl[cur][1]);
                MMA16816(sc[2 * jj],     qfl[kc], bkh[cur][0], bkh[cur][1]);
                MMA16816(sc[2 * jj + 1], qfh[kc], bkh[cur][2], bkh[cur][3]);
                MMA16816(sc[2 * jj + 1], qfh[kc], bkl[cur][2], bkl[cur][3]);
                MMA16816(sc[2 * jj + 1], qfl[kc], bkh[cur][2], bkh[cur][3]);
            }
        }

        int k0 = kt * 64;
#pragma unroll
        for (int j = 0; j < 8; j++)
#pragma unroll
            for (int e = 0; e < 4; e++) sc[j][e] *= SCALE2;
        if (k0 + 64 > q0) {
            int rg0 = q0 + 16 * w + rq, rg1 = rg0 + 8;
#pragma unroll
            for (int j = 0; j < 8; j++) {
                int cg = k0 + 8 * j + 2 * cq;
                if (cg     > rg0) sc[j][0] = -1e30f;
                if (cg + 1 > rg0) sc[j][1] = -1e30f;
                if (cg     > rg1) sc[j][2] = -1e30f;
                if (cg + 1 > rg1) sc[j][3] = -1e30f;
            }
        }

        float t0 = -1e30f, t1 = -1e30f;
#pragma unroll
        for (int j = 0; j < 8; j++) {
            t0 = fmaxf(t0, fmaxf(sc[j][0], sc[j][1]));
            t1 = fmaxf(t1, fmaxf(sc[j][2], sc[j][3]));
        }
        t0 = fmaxf(t0, __shfl_xor_sync(0xffffffffu, t0, 1));
        t0 = fmaxf(t0, __shfl_xor_sync(0xffffffffu, t0, 2));
        t1 = fmaxf(t1, __shfl_xor_sync(0xffffffffu, t1, 1));
        t1 = fmaxf(t1, __shfl_xor_sync(0xffffffffu, t1, 2));
        float mn0 = fmaxf(m0, t0), mn1 = fmaxf(m1, t1);
        float al0 = ex2f(m0 - mn0), al1 = ex2f(m1 - mn1);
        m0 = mn0; m1 = mn1;
        l0 *= al0; l1 *= al1;
#pragma unroll
        for (int n = 0; n < 16; n++) {
            out[n][0] *= al0; out[n][1] *= al0;
            out[n][2] *= al1; out[n][3] *= al1;
        }

#pragma unroll
        for (int kc = 0; kc < 4; kc++) {
            int j0 = 2 * kc, j1 = 2 * kc + 1;
            float p00 = ex2f(sc[j0][0] - m0), p01 = ex2f(sc[j0][1] - m0);
            float p02 = ex2f(sc[j0][2] - m1), p03 = ex2f(sc[j0][3] - m1);
            float p10 = ex2f(sc[j1][0] - m0), p11 = ex2f(sc[j1][1] - m0);
            float p12 = ex2f(sc[j1][2] - m1), p13 = ex2f(sc[j1][3] - m1);
            l0 += p00 + p01 + p10 + p11;
            l1 += p02 + p03 + p12 + p13;

            uint32_t ah[4], al_[4];
            ah[0] = packbf(p01, p00);
            ah[1] = packbf(p03, p02);
            ah[2] = packbf(p11, p10);
            ah[3] = packbf(p13, p12);
            float h;
            h = __uint_as_float(ah[0] << 16);          float q00 = p00 - h;
            h = __uint_as_float(ah[0] & 0xffff0000u);  float q01 = p01 - h;
            h = __uint_as_float(ah[1] << 16);          float q02 = p02 - h;
            h = __uint_as_float(ah[1] & 0xffff0000u);  float q03 = p03 - h;
            h = __uint_as_float(ah[2] << 16);          float q10 = p10 - h;
            h = __uint_as_float(ah[2] & 0xffff0000u);  float q11 = p11 - h;
            h = __uint_as_float(ah[3] << 16);          float q12 = p12 - h;
            h = __uint_as_float(ah[3] & 0xffff0000u);  float q13 = p13 - h;
            al_[0] = packbf(q01, q00);
            al_[1] = packbf(q03, q02);
            al_[2] = packbf(q11, q10);
            al_[3] = packbf(q13, q12);

            // PV with double-buffered V frags
            uint32_t bvh[2][4], bvl[2][4];
            uint32_t o0 = voff + (uint32_t)kc * (16 * AROWB);
            LDSM4T(bvh[0], sVh + o0);
            LDSM4T(bvl[0], sVl + o0);
#pragma unroll
            for (int jp = 0; jp < 8; jp++) {
                int cur = jp & 1;
                if (jp < 7) {
                    LDSM4T(bvh[cur ^ 1], sVh + o0 + (jp + 1) * 32);
                    LDSM4T(bvl[cur ^ 1], sVl + o0 + (jp + 1) * 32);
                }
                MMA16816(out[2 * jp],     ah,  bvh[cur][0], bvh[cur][1]);
                MMA16816(out[2 * jp],     ah,  bvl[cur][0], bvl[cur][1]);
                MMA16816(out[2 * jp],     al_, bvh[cur][0], bvh[cur][1]);
                MMA16816(out[2 * jp + 1], ah,  bvh[cur][2], bvh[cur][3]);
                MMA16816(out[2 * jp + 1], ah,  bvl[cur][2], bvl[cur][3]);
                MMA16816(out[2 * jp + 1], al_, bvh[cur][2], bvh[cur][3]);
            }
        }
    }

    l0 += __shfl_xor_sync(0xffffffffu, l0, 1);
    l0 += __shfl_xor_sync(0xffffffffu, l0, 2);
    l1 += __shfl_xor_sync(0xffffffffu, l1, 1);
    l1 += __shfl_xor_sync(0xffffffffu, l1, 2);
    float il0 = 1.f / l0, il1 = 1.f / l1;

    // Epilogue: write hi/lo bf16 planes of g_cxp directly (pack fused)
    int b = bh >> 4, hh = bh & 15;
    int grow0 = b * SEQ + q0 + 16 * w + rq;
    __nv_bfloat16* cb0 = g_cxp + (size_t)grow0 * KPACK + hh * HD + 2 * cq;
    __nv_bfloat16* cb1 = cb0 + (size_t)8 * KPACK;
#pragma unroll
    for (int nt = 0; nt < 16; nt++) {
        uint32_t hw, lw;
        pack2(out[nt][0] * il0, out[nt][1] * il0, hw, lw);
        *(uint32_t*)(cb0 + nt * 8)        = hw;
        *(uint32_t*)(cb0 + 2048 + nt * 8) = lw;
        pack2(out[nt][2] * il1, out[nt][3] * il1, hw, lw);
        *(uint32_t*)(cb1 + nt * 8)        = hw;
        *(uint32_t*)(cb1 + 2048 + nt * 8) = lw;
    }
}

// ---------------------------------------------------------------------------
// Launch graph (idx 3 = QKV GEMM, the ncu capture slot)
// ---------------------------------------------------------------------------
extern "C" void kernel_launch(void* const* d_in, const int* in_sizes, int n_in,
                              void* d_out, int out_size) {
    const float* x    = (const float*)d_in[0];
    // d_in[1] = attn_mask (pure causal) — reproduced analytically, not read
    const float* Wqkv = (const float*)d_in[2];
    const float* Wout = (const float*)d_in[3];
    float* out = (float*)d_out;

    float* qkv_ptr = 0;
    __nv_bfloat16 *xp = 0, *wqp = 0, *wop = 0, *cxp = 0;
    cudaGetSymbolAddress((void**)&qkv_ptr, g_qkv);
    cudaGetSymbolAddress((void**)&xp,  g_xp);
    cudaGetSymbolAddress((void**)&wqp, g_wqp);
    cudaGetSymbolAddress((void**)&wop, g_wop);
    cudaGetSymbolAddress((void**)&cxp, g_cxp);

    cudaFuncSetAttribute(tc_gemm_kernel,
                         cudaFuncAttributeMaxDynamicSharedMemorySize, GEMM_SMEM);
    cudaFuncSetAttribute(attn_mma_kernel,
                         cudaFuncAttributeMaxDynamicSharedMemorySize, ATTN_SMEM);

    // idx 0..2: packs (vectorized, 8 elems/thread)
    pack_kernel<<<MROWS * HID / 2048, 256>>>(x, xp, MROWS * HID);
    pack_kernel<<<QKVN  * HID / 2048, 256>>>(Wqkv, wqp, QKVN * HID);
    pack_kernel<<<HID   * HID / 2048, 256>>>(Wout, wop, HID * HID);

    // idx 3: QKV GEMM (ncu capture slot)
    tc_gemm_kernel<<<dim3(QKVN / 128, MROWS / 128), 128, GEMM_SMEM>>>(
        xp, wqp, qkv_ptr, QKVN);

    // idx 4..5: RoPE table + qkv pack
    rope_table_kernel<<<(SEQ * 64 + 255) / 256, 256>>>();
    qkv_pack_kernel<<<MROWS * NH * 16 / 256, 256>>>();

    // idx 6: attention (LPT 1-D grid; epilogue writes packed ctx)
    attn_mma_kernel<<<(SEQ / 128) * BATCH * NH, 256, ATTN_SMEM>>>();

    // idx 7: output GEMM (reads packed ctx directly)
    tc_gemm_kernel<<<dim3(HID / 128, MROWS / 128), 128, GEMM_SMEM>>>(
        cxp, wop, out, HID);
}

// round 10
// speedup vs baseline: 8.7980x; 1.3086x over previous
#include <cuda_runtime.h>
#include <cuda_bf16.h>
#include <cuda_fp16.h>
#include <math.h>
#include <stdint.h>

// Problem constants
#define SEQ   2048
#define HID   2048
#define NH    16
#define HD    128
#define BATCH 2
#define MROWS (BATCH * SEQ)     // 4096
#define QKVN  (3 * HID)         // 6144
#define KA    2048              // activation row length (fp16 hi only)
#define KB    4096              // weight row length (fp16 hi | lo)

// ---------------------------------------------------------------------------
// Scratch (device globals — no runtime allocation allowed)
// ---------------------------------------------------------------------------
__device__ __align__(16) float g_qkv[(size_t)MROWS * QKVN];    // fp32 QKV
__device__ __align__(16) float g_cos[SEQ * 64];
__device__ __align__(16) float g_sin[SEQ * 64];
__device__ __align__(16) __half g_xh [(size_t)MROWS * KA];     // x, fp16 hi
__device__ __align__(16) __half g_wqp[(size_t)QKVN  * KB];     // Wqkv hi|lo
__device__ __align__(16) __half g_wop[(size_t)HID   * KB];     // Wout hi|lo
__device__ __align__(16) __half g_cxh[(size_t)MROWS * KA];     // ctx, fp16 hi
// attention operands (bf16x3 path, unchanged): [bh*2 + plane][s][128]
__device__ __align__(16) __nv_bfloat16 g_qp[(size_t)BATCH * NH * 2 * SEQ * HD];
__device__ __align__(16) __nv_bfloat16 g_kp[(size_t)BATCH * NH * 2 * SEQ * HD];
__device__ __align__(16) __nv_bfloat16 g_vp[(size_t)BATCH * NH * 2 * SEQ * HD];

// ---------------------------------------------------------------------------
// PTX helpers (arch-agnostic: cp.async / ldmatrix / mma.sync only)
// ---------------------------------------------------------------------------
__device__ __forceinline__ uint32_t s2u(const void* p) {
    uint32_t a;
    asm("{ .reg .u64 t; cvta.to.shared.u64 t, %1; cvt.u32.u64 %0, t; }"
        : "=r"(a) : "l"(p));
    return a;
}

#define CP_ASYNC16(saddr, gptr) \
    asm volatile("cp.async.cg.shared.global [%0], [%1], 16;" \
                 :: "r"(saddr), "l"(gptr))
#define CP_COMMIT()  asm volatile("cp.async.commit_group;" ::: "memory")
#define CP_WAIT1()   asm volatile("cp.async.wait_group 1;" ::: "memory")
#define CP_WAIT2()   asm volatile("cp.async.wait_group 2;" ::: "memory")

#define LDSM4(r, addr)                                                        \
    asm volatile("ldmatrix.sync.aligned.m8n8.x4.shared.b16 {%0,%1,%2,%3}, [%4];" \
        : "=r"((r)[0]), "=r"((r)[1]), "=r"((r)[2]), "=r"((r)[3]) : "r"(addr))
#define LDSM4T(r, addr)                                                       \
    asm volatile("ldmatrix.sync.aligned.m8n8.x4.trans.shared.b16 {%0,%1,%2,%3}, [%4];" \
        : "=r"((r)[0]), "=r"((r)[1]), "=r"((r)[2]), "=r"((r)[3]) : "r"(addr))

// bf16 MMA (attention)
#define MMA16816(d, a, b0, b1)                                                \
    asm volatile("mma.sync.aligned.m16n8k16.row.col.f32.bf16.bf16.f32 "       \
        "{%0,%1,%2,%3},{%4,%5,%6,%7},{%8,%9},{%0,%1,%2,%3};"                  \
        : "+f"((d)[0]), "+f"((d)[1]), "+f"((d)[2]), "+f"((d)[3])              \
        : "r"((a)[0]), "r"((a)[1]), "r"((a)[2]), "r"((a)[3]),                 \
          "r"(b0), "r"(b1))

// fp16 MMA (projection GEMMs)
#define MMA16816H(d, a, b0, b1)                                               \
    asm volatile("mma.sync.aligned.m16n8k16.row.col.f32.f16.f16.f32 "         \
        "{%0,%1,%2,%3},{%4,%5,%6,%7},{%8,%9},{%0,%1,%2,%3};"                  \
        : "+f"((d)[0]), "+f"((d)[1]), "+f"((d)[2]), "+f"((d)[3])              \
        : "r"((a)[0]), "r"((a)[1]), "r"((a)[2]), "r"((a)[3]),                 \
          "r"(b0), "r"(b1))

__device__ __forceinline__ float ex2f(float x) {
    float y;
    asm("ex2.approx.ftz.f32 %0, %1;" : "=f"(y) : "f"(x));
    return y;
}
__device__ __forceinline__ uint32_t packbf(float hi, float lo) {
    uint32_t d;
    asm("cvt.rn.bf16x2.f32 %0, %1, %2;" : "=r"(d) : "f"(hi), "f"(lo));
    return d;
}
__device__ __forceinline__ uint32_t h2u(__half2 h) {
    return *(uint32_t*)&h;
}

// ---------------------------------------------------------------------------
// RoPE table (reference-matching numerics)
// ---------------------------------------------------------------------------
__global__ void rope_table_kernel() {
    int idx = blockIdx.x * blockDim.x + threadIdx.x;
    if (idx >= SEQ * 64) return;
    int s = idx >> 6;
    int j = idx & 63;
    double inv = exp(-((double)j / 64.0) * log(10000.0));
    float  invf = (float)inv;
    float  ang  = (float)s * invf;
    g_cos[idx] = (float)cos((double)ang);
    g_sin[idx] = (float)sin((double)ang);
}

// ---------------------------------------------------------------------------
// Activation pack: fp32 -> fp16 hi plane only (8 elems/thread, uint4 store)
// ---------------------------------------------------------------------------
__global__ void pack_x_kernel(const float* __restrict__ X,
                              __half* __restrict__ P, int n) {
    int i = (blockIdx.x * 256 + threadIdx.x) * 8;
    if (i >= n) return;
    float4 a = *(const float4*)(X + i);
    float4 b = *(const float4*)(X + i + 4);
    __half2 h0 = __float22half2_rn(make_float2(a.x, a.y));
    __half2 h1 = __float22half2_rn(make_float2(a.z, a.w));
    __half2 h2 = __float22half2_rn(make_float2(b.x, b.y));
    __half2 h3 = __float22half2_rn(make_float2(b.z, b.w));
    *(uint4*)(P + i) = make_uint4(h2u(h0), h2u(h1), h2u(h2), h2u(h3));
}

// ---------------------------------------------------------------------------
// Weight pack: fp32 [N][2048] -> fp16 [N][4096] hi|lo (8 elems/thread)
// ---------------------------------------------------------------------------
__global__ void pack_w_kernel(const float* __restrict__ X,
                              __half* __restrict__ P, int n) {
    int i = (blockIdx.x * 256 + threadIdx.x) * 8;
    if (i >= n) return;
    int row = i >> 11, col = i & 2047;
    float4 a = *(const float4*)(X + i);
    float4 b = *(const float4*)(X + i + 4);
    float v[8] = {a.x, a.y, a.z, a.w, b.x, b.y, b.z, b.w};
    uint32_t hw[4], lw[4];
#pragma unroll
    for (int p = 0; p < 4; p++) {
        __half2 h = __float22half2_rn(make_float2(v[2 * p], v[2 * p + 1]));
        float2 hf = __half22float2(h);
        __half2 l = __float22half2_rn(make_float2(v[2 * p] - hf.x,
                                                  v[2 * p + 1] - hf.y));
        hw[p] = h2u(h); lw[p] = h2u(l);
    }
    *(uint4*)(P + (size_t)row * KB + col) =
        make_uint4(hw[0], hw[1], hw[2], hw[3]);
    *(uint4*)(P + (size_t)row * KB + 2048 + col) =
        make_uint4(lw[0], lw[1], lw[2], lw[3]);
}

// ---------------------------------------------------------------------------
// QKV pack: RoPE on q,k + hi/lo bf16 split of q,k,v (attention operands)
// ---------------------------------------------------------------------------
__device__ __forceinline__ void pack4bf(const float* x, uint2& hi, uint2& lo) {
    uint32_t h0 = packbf(x[1], x[0]);
    uint32_t h1 = packbf(x[3], x[2]);
    float f0 = __uint_as_float(h0 << 16);
    float f1 = __uint_as_float(h0 & 0xffff0000u);
    float f2 = __uint_as_float(h1 << 16);
    float f3 = __uint_as_float(h1 & 0xffff0000u);
    hi.x = h0; hi.y = h1;
    lo.x = packbf(x[1] - f1, x[0] - f0);
    lo.y = packbf(x[3] - f3, x[2] - f2);
}

__global__ void qkv_pack_kernel() {
    int idx = blockIdx.x * blockDim.x + threadIdx.x;   // MROWS*NH*16
    int jq  = (idx & 15) << 2;
    int h   = (idx >> 4) & (NH - 1);
    int row = idx >> 8;
    int s   = row & (SEQ - 1);
    int b   = row >> 11;
    int bh  = b * NH + h;

    float4 c4 = *(const float4*)&g_cos[(s << 6) + jq];
    float4 s4 = *(const float4*)&g_sin[(s << 6) + jq];
    float cc[4] = {c4.x, c4.y, c4.z, c4.w};
    float ss[4] = {s4.x, s4.y, s4.z, s4.w};

    const float* base = g_qkv + (size_t)row * QKVN + h * HD;
    float4 qa4 = *(const float4*)(base + jq);
    float4 qb4 = *(const float4*)(base + jq + 64);
    float4 ka4 = *(const float4*)(base + HID + jq);
    float4 kb4 = *(const float4*)(base + HID + jq + 64);
    float4 va4 = *(const float4*)(base + 2 * HID + jq);
    float4 vb4 = *(const float4*)(base + 2 * HID + jq + 64);
    float q1[4] = {qa4.x, qa4.y, qa4.z, qa4.w};
    float q2[4] = {qb4.x, qb4.y, qb4.z, qb4.w};
    float k1[4] = {ka4.x, ka4.y, ka4.z, ka4.w};
    float k2[4] = {kb4.x, kb4.y, kb4.z, kb4.w};
    float v1[4] = {va4.x, va4.y, va4.z, va4.w};
    float v2[4] = {vb4.x, vb4.y, vb4.z, vb4.w};

    float qa[4], qb[4], ka[4], kb[4];
#pragma unroll
    for (int e = 0; e < 4; e++) {
        qa[e] = q1[e] * cc[e] - q2[e] * ss[e];
        qb[e] = q2[e] * cc[e] + q1[e] * ss[e];
        ka[e] = k1[e] * cc[e] - k2[e] * ss[e];
        kb[e] = k2[e] * cc[e] + k1[e] * ss[e];
    }

    size_t pb = ((size_t)(bh * 2) * SEQ + s) * HD;
    const size_t PL = (size_t)SEQ * HD;
    uint2 hi, lo;
    pack4bf(qa, hi, lo);
    *(uint2*)(g_qp + pb + jq)      = hi; *(uint2*)(g_qp + pb + PL + jq)      = lo;
    pack4bf(qb, hi, lo);
    *(uint2*)(g_qp + pb + jq + 64) = hi; *(uint2*)(g_qp + pb + PL + jq + 64) = lo;
    pack4bf(ka, hi, lo);
    *(uint2*)(g_kp + pb + jq)      = hi; *(uint2*)(g_kp + pb + PL + jq)      = lo;
    pack4bf(kb, hi, lo);
    *(uint2*)(g_kp + pb + jq + 64) = hi; *(uint2*)(g_kp + pb + PL + jq + 64) = lo;
    pack4bf(v1, hi, lo);
    *(uint2*)(g_vp + pb + jq)      = hi; *(uint2*)(g_vp + pb + PL + jq)      = lo;
    pack4bf(v2, hi, lo);
    *(uint2*)(g_vp + pb + jq + 64) = hi; *(uint2*)(g_vp + pb + PL + jq + 64) = lo;
}

// ---------------------------------------------------------------------------
// fp16 2-pass tensor-core GEMM: C = A_f32 B_f32^T approximated by
// Ah*Bh + Ah*Bl (weights split hi/lo; activation residual dropped).
// A: __half [M][2048], B: __half [N][4096]. Same pipeline as v4.
// ---------------------------------------------------------------------------
#define AST         72
#define STG_MAT     (128 * AST * 2)
#define STG_BYTES   (2 * STG_MAT)
#define GEMM_STAGES 3
#define GEMM_SMEM   (GEMM_STAGES * STG_BYTES)
#define GNITER      64                   // 2 passes x 32 chunks of K=64

__device__ __forceinline__ void g_load_stage(
    uint32_t sA, const __half* Ab, const __half* Bb, int tid)
{
#pragma unroll
    for (int t = 0; t < 8; t++) {
        int c = tid + t * 128;
        int r = c >> 3, co = (c & 7) << 3;
        CP_ASYNC16(sA + (r * AST + co) * 2, Ab + (size_t)r * KA + co);
        CP_ASYNC16(sA + STG_MAT + (r * AST + co) * 2, Bb + (size_t)r * KB + co);
    }
}

__global__ void __launch_bounds__(128, 2) tc_gemm_kernel(
    const __half* __restrict__ A, const __half* __restrict__ B,
    float* __restrict__ C, int ldc)
{
    extern __shared__ char smg[];
    uint32_t smb = s2u(smg);
    int tid  = threadIdx.x;
    int lane = tid & 31, wid = tid >> 5;
    int wm = (wid & 1) * 64, wn = (wid >> 1) * 64;
    int m0 = blockIdx.y * 128, n0 = blockIdx.x * 128;

    float acc[4][8][4];
#pragma unroll
    for (int i = 0; i < 4; i++)
#pragma unroll
        for (int j = 0; j < 8; j++)
#pragma unroll
            for (int k = 0; k < 4; k++) acc[i][j][k] = 0.f;

    auto chunk_off = [&](int it, int& boff, int& k0) {
        k0   = (it & 31) << 6;
        boff = (it >> 5) ? 2048 : 0;     // pass 1 reads weight lo plane
    };

    uint32_t a_off[4][4], b_off[4][4];
#pragma unroll
    for (int ks = 0; ks < 4; ks++) {
#pragma unroll
        for (int mt = 0; mt < 4; mt++)
            a_off[ks][mt] = ((wm + mt * 16 + (lane & 15)) * AST +
                             ks * 16 + (lane >> 4) * 8) * 2;
#pragma unroll
        for (int np = 0; np < 4; np++)
            b_off[ks][np] = STG_MAT +
                ((wn + np * 16 + ((lane >> 4) & 1) * 8 + (lane & 7)) * AST +
                 ks * 16 + ((lane >> 3) & 1) * 8) * 2;
    }

#pragma unroll
    for (int p = 0; p < GEMM_STAGES - 1; p++) {
        int boff, k0;
        chunk_off(p, boff, k0);
        g_load_stage(smb + p * STG_BYTES,
                     A + (size_t)m0 * KA + k0,
                     B + (size_t)n0 * KB + boff + k0, tid);
        CP_COMMIT();
    }
    CP_WAIT1();
    __syncthreads();

    uint32_t af[2][4][4], bf[2][4];
#pragma unroll
    for (int mt = 0; mt < 4; mt++) LDSM4(af[0][mt], smb + a_off[0][mt]);
    LDSM4(bf[0], smb + b_off[0][0]);

    for (int it = 0; it < GNITER; ++it) {
        uint32_t sbase = smb + (it % GEMM_STAGES) * STG_BYTES;

        int nx = it + GEMM_STAGES - 1;
        if (nx < GNITER) {
            int boff, k0;
            chunk_off(nx, boff, k0);
            g_load_stage(smb + (nx % GEMM_STAGES) * STG_BYTES,
                         A + (size_t)m0 * KA + k0,
                         B + (size_t)n0 * KB + boff + k0, tid);
        }
        CP_COMMIT();

#pragma unroll
        for (int ks = 0; ks < 4; ks++) {
            int cur = ks & 1, nxt = cur ^ 1;
            uint32_t bb[2][4];
#pragma unroll
            for (int e = 0; e < 4; e++) bb[0][e] = bf[cur][e];
#pragma unroll
            for (int np = 0; np < 4; np++) {
                if (np < 3) LDSM4(bb[(np + 1) & 1], sbase + b_off[ks][np + 1]);
#pragma unroll
                for (int mt = 0; mt < 4; mt++) {
                    MMA16816H(acc[mt][2 * np],     af[cur][mt], bb[np & 1][0], bb[np & 1][1]);
                    MMA16816H(acc[mt][2 * np + 1], af[cur][mt], bb[np & 1][2], bb[np & 1][3]);
                }
            }
            if (ks < 3) {
#pragma unroll
                for (int mt = 0; mt < 4; mt++)
                    LDSM4(af[nxt][mt], sbase + a_off[ks + 1][mt]);
                LDSM4(bf[nxt], sbase + b_off[ks + 1][0]);
            }
        }

        CP_WAIT1();
        __syncthreads();
        uint32_t nbase = smb + ((it + 1) % GEMM_STAGES) * STG_BYTES;
#pragma unroll
        for (int mt = 0; mt < 4; mt++) LDSM4(af[0][mt], nbase + a_off[0][mt]);
        LDSM4(bf[0], nbase + b_off[0][0]);
    }

    float* Cb = C + (size_t)(m0 + wm) * ldc + n0 + wn;
    int rq = lane >> 2, cq = (lane & 3) * 2;
#pragma unroll
    for (int mt = 0; mt < 4; mt++)
#pragma unroll
        for (int nt = 0; nt < 8; nt++) {
            *(float2*)(Cb + (size_t)(mt * 16 + rq) * ldc + nt * 8 + cq) =
                make_float2(acc[mt][nt][0], acc[mt][nt][1]);
            *(float2*)(Cb + (size_t)(mt * 16 + rq + 8) * ldc + nt * 8 + cq) =
                make_float2(acc[mt][nt][2], acc[mt][nt][3]);
        }
}

// ---------------------------------------------------------------------------
// Tensor-core flash attention (bf16x3, causal, online softmax, LPT grid).
// Unchanged from round 9 except: epilogue writes the fp16 hi plane g_cxh.
// ---------------------------------------------------------------------------
#define AKST     136
#define AROWB    (AKST * 2)
#define QPLANE   (128 * AROWB)
#define KVPLANE  (64 * AROWB)
#define STAGE_B  (4 * KVPLANE)
#define KVSTAGES 3
#define ATTN_SMEM (KVSTAGES * STAGE_B)

__device__ __forceinline__ void load_kv_stage(
    uint32_t dst, const __nv_bfloat16* Kp, const __nv_bfloat16* Vp,
    int k0, int tid)
{
#pragma unroll
    for (int t = 0; t < 16; t++) {
        int c = tid + t * 256;
        int plane = c >> 10;
        int r = (c >> 4) & 63;
        int co = c & 15;
        const __nv_bfloat16* src = (plane < 2)
            ? Kp + ((size_t)plane * SEQ + k0 + r) * HD + co * 8
            : Vp + ((size_t)(plane - 2) * SEQ + k0 + r) * HD + co * 8;
        CP_ASYNC16(dst + plane * KVPLANE + r * AROWB + co * 16, src);
    }
}

__global__ void __launch_bounds__(256) attn_mma_kernel() {
    extern __shared__ char sma[];
    uint32_t smb = s2u(sma);
    int tid = threadIdx.x, lane = tid & 31, w = tid >> 5;
    int qt = 15 - ((int)blockIdx.x >> 5);   // LPT: heaviest first
    int bh = (int)blockIdx.x & 31;
    int q0 = qt * 128;
    int nkt = 2 * qt + 2;

    const __nv_bfloat16* Qp = g_qp + (size_t)(bh * 2) * SEQ * HD;
    const __nv_bfloat16* Kp = g_kp + (size_t)(bh * 2) * SEQ * HD;
    const __nv_bfloat16* Vp = g_vp + (size_t)(bh * 2) * SEQ * HD;

    uint32_t sQstage = smb + 2 * STAGE_B;
#pragma unroll
    for (int t = 0; t < 16; t++) {
        int c = tid + t * 256;
        int plane = c >> 11, r = (c >> 4) & 127, co = c & 15;
        CP_ASYNC16(sQstage + plane * QPLANE + r * AROWB + co * 16,
                   Qp + ((size_t)plane * SEQ + q0 + r) * HD + co * 8);
    }
    CP_COMMIT();
    load_kv_stage(smb, Kp, Vp, 0, tid);
    CP_COMMIT();
    load_kv_stage(smb + STAGE_B, Kp, Vp, 64, tid);
    CP_COMMIT();

    int rq = lane >> 2, cq = lane & 3;
    uint32_t qoff = (uint32_t)(16 * w + (lane & 15)) * AROWB + ((lane >> 4) & 1) * 16;
    uint32_t koff = (uint32_t)(((lane >> 4) & 1) * 8 + (lane & 7)) * AROWB +
                    ((lane >> 3) & 1) * 16;
    uint32_t voff = (uint32_t)(((lane >> 3) & 1) * 8 + (lane & 7)) * AROWB +
                    ((lane >> 4) & 1) * 16;

    CP_WAIT2();
    __syncthreads();
    uint32_t qfh[8][4], qfl[8][4];
#pragma unroll
    for (int kc = 0; kc < 8; kc++) {
        LDSM4(qfh[kc], sQstage + qoff + kc * 32);
        LDSM4(qfl[kc], sQstage + QPLANE + qoff + kc * 32);
    }

    float out[16][4];
#pragma unroll
    for (int n = 0; n < 16; n++)
#pragma unroll
        for (int e = 0; e < 4; e++) out[n][e] = 0.f;
    float m0 = -1e30f, m1 = -1e30f, l0 = 0.f, l1 = 0.f;

    const float SCALE2 = 0.08838834764831845f * 1.44269504088896341f;

    for (int kt = 0; kt < nkt; kt++) {
        CP_WAIT1();
        __syncthreads();
        if (kt + 2 < nkt)
            load_kv_stage(smb + ((kt + 2) % KVSTAGES) * STAGE_B, Kp, Vp,
                          (kt + 2) * 64, tid);
        CP_COMMIT();

        uint32_t sKh = smb + (kt % KVSTAGES) * STAGE_B;
        uint32_t sKl = sKh + KVPLANE;
        uint32_t sVh = sKh + 2 * KVPLANE;
        uint32_t sVl = sKh + 3 * KVPLANE;

        float sc[8][4];
#pragma unroll
        for (int j = 0; j < 8; j++)
#pragma unroll
            for (int e = 0; e < 4; e++) sc[j][e] = 0.f;

        {
            uint32_t bkh[2][4], bkl[2][4];
            LDSM4(bkh[0], sKh + koff);
            LDSM4(bkl[0], sKl + koff);
#pragma unroll
            for (int t = 0; t < 32; t++) {
                int kc = t >> 2, jj = t & 3;
                int cur = t & 1;
                if (t < 31) {
                    int tn = t + 1;
                    uint32_t on = koff + (uint32_t)(tn & 3) * (16 * AROWB) +
                                  (tn >> 2) * 32;
                    LDSM4(bkh[cur ^ 1], sKh + on);
                    LDSM4(bkl[cur ^ 1], sKl + on);
                }
                MMA16816(sc[2 * jj],     qfh[kc], bkh[cur][0], bkh[cur][1]);
                MMA16816(sc[2 * jj],     qfh[kc], bkl[cur][0], bkl[cur][1]);
                MMA16816(sc[2 * jj],     qfl[kc], bkh[cur][0], bkh[cur][1]);
                MMA16816(sc[2 * jj + 1], qfh[kc], bkh[cur][2], bkh[cur][3]);
                MMA16816(sc[2 * jj + 1], qfh[kc], bkl[cur][2], bkl[cur][3]);
                MMA16816(sc[2 * jj + 1], qfl[kc], bkh[cur][2], bkh[cur][3]);
            }
        }

        int k0 = kt * 64;
#pragma unroll
        for (int j = 0; j < 8; j++)
#pragma unroll
            for (int e = 0; e < 4; e++) sc[j][e] *= SCALE2;
        if (k0 + 64 > q0) {
            int rg0 = q0 + 16 * w + rq, rg1 = rg0 + 8;
#pragma unroll
            for (int j = 0; j < 8; j++) {
                int cg = k0 + 8 * j + 2 * cq;
                if (cg     > rg0) sc[j][0] = -1e30f;
                if (cg + 1 > rg0) sc[j][1] = -1e30f;
                if (cg     > rg1) sc[j][2] = -1e30f;
                if (cg + 1 > rg1) sc[j][3] = -1e30f;
            }
        }

        float t0 = -1e30f, t1 = -1e30f;
#pragma unroll
        for (int j = 0; j < 8; j++) {
            t0 = fmaxf(t0, fmaxf(sc[j][0], sc[j][1]));
            t1 = fmaxf(t1, fmaxf(sc[j][2], sc[j][3]));
        }
        t0 = fmaxf(t0, __shfl_xor_sync(0xffffffffu, t0, 1));
        t0 = fmaxf(t0, __shfl_xor_sync(0xffffffffu, t0, 2));
        t1 = fmaxf(t1, __shfl_xor_sync(0xffffffffu, t1, 1));
        t1 = fmaxf(t1, __shfl_xor_sync(0xffffffffu, t1, 2));
        float mn0 = fmaxf(m0, t0), mn1 = fmaxf(m1, t1);
        float al0 = ex2f(m0 - mn0), al1 = ex2f(m1 - mn1);
        m0 = mn0; m1 = mn1;
        l0 *= al0; l1 *= al1;
#pragma unroll
        for (int n = 0; n < 16; n++) {
            out[n][0] *= al0; out[n][1] *= al0;
            out[n][2] *= al1; out[n][3] *= al1;
        }

#pragma unroll
        for (int kc = 0; kc < 4; kc++) {
            int j0 = 2 * kc, j1 = 2 * kc + 1;
            float p00 = ex2f(sc[j0][0] - m0), p01 = ex2f(sc[j0][1] - m0);
            float p02 = ex2f(sc[j0][2] - m1), p03 = ex2f(sc[j0][3] - m1);
            float p10 = ex2f(sc[j1][0] - m0), p11 = ex2f(sc[j1][1] - m0);
            float p12 = ex2f(sc[j1][2] - m1), p13 = ex2f(sc[j1][3] - m1);
            l0 += p00 + p01 + p10 + p11;
            l1 += p02 + p03 + p12 + p13;

            uint32_t ah[4], al_[4];
            ah[0] = packbf(p01, p00);
            ah[1] = packbf(p03, p02);
            ah[2] = packbf(p11, p10);
            ah[3] = packbf(p13, p12);
            float h;
            h = __uint_as_float(ah[0] << 16);          float q00 = p00 - h;
            h = __uint_as_float(ah[0] & 0xffff0000u);  float q01 = p01 - h;
            h = __uint_as_float(ah[1] << 16);          float q02 = p02 - h;
            h = __uint_as_float(ah[1] & 0xffff0000u);  float q03 = p03 - h;
            h = __uint_as_float(ah[2] << 16);          float q10 = p10 - h;
            h = __uint_as_float(ah[2] & 0xffff0000u);  float q11 = p11 - h;
            h = __uint_as_float(ah[3] << 16);          float q12 = p12 - h;
            h = __uint_as_float(ah[3] & 0xffff0000u);  float q13 = p13 - h;
            al_[0] = packbf(q01, q00);
            al_[1] = packbf(q03, q02);
            al_[2] = packbf(q11, q10);
            al_[3] = packbf(q13, q12);

            uint32_t bvh[2][4], bvl[2][4];
            uint32_t o0 = voff + (uint32_t)kc * (16 * AROWB);
            LDSM4T(bvh[0], sVh + o0);
            LDSM4T(bvl[0], sVl + o0);
#pragma unroll
            for (int jp = 0; jp < 8; jp++) {
                int cur = jp & 1;
                if (jp < 7) {
                    LDSM4T(bvh[cur ^ 1], sVh + o0 + (jp + 1) * 32);
                    LDSM4T(bvl[cur ^ 1], sVl + o0 + (jp + 1) * 32);
                }
                MMA16816(out[2 * jp],     ah,  bvh[cur][0], bvh[cur][1]);
                MMA16816(out[2 * jp],     ah,  bvl[cur][0], bvl[cur][1]);
                MMA16816(out[2 * jp],     al_, bvh[cur][0], bvh[cur][1]);
                MMA16816(out[2 * jp + 1], ah,  bvh[cur][2], bvh[cur][3]);
                MMA16816(out[2 * jp + 1], ah,  bvl[cur][2], bvl[cur][3]);
                MMA16816(out[2 * jp + 1], al_, bvh[cur][2], bvh[cur][3]);
            }
        }
    }

    l0 += __shfl_xor_sync(0xffffffffu, l0, 1);
    l0 += __shfl_xor_sync(0xffffffffu, l0, 2);
    l1 += __shfl_xor_sync(0xffffffffu, l1, 1);
    l1 += __shfl_xor_sync(0xffffffffu, l1, 2);
    float il0 = 1.f / l0, il1 = 1.f / l1;

    // Epilogue: write fp16 hi plane of ctx directly (out-proj A operand)
    int b = bh >> 4, hh = bh & 15;
    int grow0 = b * SEQ + q0 + 16 * w + rq;
    __half* cb0 = g_cxh + (size_t)grow0 * KA + hh * HD + 2 * cq;
    __half* cb1 = cb0 + (size_t)8 * KA;
#pragma unroll
    for (int nt = 0; nt < 16; nt++) {
        *(__half2*)(cb0 + nt * 8) =
            __float22half2_rn(make_float2(out[nt][0] * il0, out[nt][1] * il0));
        *(__half2*)(cb1 + nt * 8) =
            __float22half2_rn(make_float2(out[nt][2] * il1, out[nt][3] * il1));
    }
}

// ---------------------------------------------------------------------------
// Launch graph (idx 3 = QKV GEMM, the ncu capture slot)
// ---------------------------------------------------------------------------
extern "C" void kernel_launch(void* const* d_in, const int* in_sizes, int n_in,
                              void* d_out, int out_size) {
    const float* x    = (const float*)d_in[0];
    // d_in[1] = attn_mask (pure causal) — reproduced analytically, not read
    const float* Wqkv = (const float*)d_in[2];
    const float* Wout = (const float*)d_in[3];
    float* out = (float*)d_out;

    float* qkv_ptr = 0;
    __half *xh = 0, *wqp = 0, *wop = 0, *cxh = 0;
    cudaGetSymbolAddress((void**)&qkv_ptr, g_qkv);
    cudaGetSymbolAddress((void**)&xh,  g_xh);
    cudaGetSymbolAddress((void**)&wqp, g_wqp);
    cudaGetSymbolAddress((void**)&wop, g_wop);
    cudaGetSymbolAddress((void**)&cxh, g_cxh);

    cudaFuncSetAttribute(tc_gemm_kernel,
                         cudaFuncAttributeMaxDynamicSharedMemorySize, GEMM_SMEM);
    cudaFuncSetAttribute(attn_mma_kernel,
                         cudaFuncAttributeMaxDynamicSharedMemorySize, ATTN_SMEM);

    // idx 0..2: packs
    pack_x_kernel<<<MROWS * HID / 2048, 256>>>(x, xh, MROWS * HID);
    pack_w_kernel<<<QKVN * HID / 2048, 256>>>(Wqkv, wqp, QKVN * HID);
    pack_w_kernel<<<HID  * HID / 2048, 256>>>(Wout, wop, HID * HID);

    // idx 3: QKV GEMM (ncu capture slot)
    tc_gemm_kernel<<<dim3(QKVN / 128, MROWS / 128), 128, GEMM_SMEM>>>(
        xh, wqp, qkv_ptr, QKVN);

    // idx 4..5: RoPE table + qkv pack
    rope_table_kernel<<<(SEQ * 64 + 255) / 256, 256>>>();
    qkv_pack_kernel<<<MROWS * NH * 16 / 256, 256>>>();

    // idx 6: attention (LPT grid; epilogue writes fp16 ctx hi plane)
    attn_mma_kernel<<<(SEQ / 128) * BATCH * NH, 256, ATTN_SMEM>>>();

    // idx 7: output GEMM
    tc_gemm_kernel<<<dim3(HID / 128, MROWS / 128), 128, GEMM_SMEM>>>(
        cxh, wop, out, HID);
}

// round 11
// speedup vs baseline: 9.4475x; 1.0738x over previous
#include <cuda_runtime.h>
#include <cuda_bf16.h>
#include <cuda_fp16.h>
#include <math.h>
#include <stdint.h>

// Problem constants
#define SEQ   2048
#define HID   2048
#define NH    16
#define HD    128
#define BATCH 2
#define MROWS (BATCH * SEQ)     // 4096
#define QKVN  (3 * HID)         // 6144
#define KA    2048              // activation row length (fp16 hi only)
#define KB    4096              // weight row length (fp16 hi | lo)

// ---------------------------------------------------------------------------
// Scratch (device globals — no runtime allocation allowed)
// ---------------------------------------------------------------------------
__device__ __align__(16) float g_qkv[(size_t)MROWS * QKVN];    // fp32 QKV
__device__ __align__(16) float g_cos[SEQ * 64];
__device__ __align__(16) float g_sin[SEQ * 64];
__device__ __align__(16) __half g_xh [(size_t)MROWS * KA];     // x, fp16 hi
__device__ __align__(16) __half g_wqp[(size_t)QKVN  * KB];     // Wqkv hi|lo
__device__ __align__(16) __half g_wop[(size_t)HID   * KB];     // Wout hi|lo
__device__ __align__(16) __half g_cxh[(size_t)MROWS * KA];     // ctx, fp16 hi
// attention operands (fp16): q hi only; k,v hi|lo planes
__device__ __align__(16) __half g_qp[(size_t)BATCH * NH * SEQ * HD];
__device__ __align__(16) __half g_kp[(size_t)BATCH * NH * 2 * SEQ * HD];
__device__ __align__(16) __half g_vp[(size_t)BATCH * NH * 2 * SEQ * HD];

// ---------------------------------------------------------------------------
// PTX helpers (arch-agnostic: cp.async / ldmatrix / mma.sync only)
// ---------------------------------------------------------------------------
__device__ __forceinline__ uint32_t s2u(const void* p) {
    uint32_t a;
    asm("{ .reg .u64 t; cvta.to.shared.u64 t, %1; cvt.u32.u64 %0, t; }"
        : "=r"(a) : "l"(p));
    return a;
}

#define CP_ASYNC16(saddr, gptr) \
    asm volatile("cp.async.cg.shared.global [%0], [%1], 16;" \
                 :: "r"(saddr), "l"(gptr))
#define CP_COMMIT()  asm volatile("cp.async.commit_group;" ::: "memory")
#define CP_WAIT1()   asm volatile("cp.async.wait_group 1;" ::: "memory")
#define CP_WAIT2()   asm volatile("cp.async.wait_group 2;" ::: "memory")

#define LDSM4(r, addr)                                                        \
    asm volatile("ldmatrix.sync.aligned.m8n8.x4.shared.b16 {%0,%1,%2,%3}, [%4];" \
        : "=r"((r)[0]), "=r"((r)[1]), "=r"((r)[2]), "=r"((r)[3]) : "r"(addr))
#define LDSM4T(r, addr)                                                       \
    asm volatile("ldmatrix.sync.aligned.m8n8.x4.trans.shared.b16 {%0,%1,%2,%3}, [%4];" \
        : "=r"((r)[0]), "=r"((r)[1]), "=r"((r)[2]), "=r"((r)[3]) : "r"(addr))

// fp16 MMA
#define MMA16816H(d, a, b0, b1)                                               \
    asm volatile("mma.sync.aligned.m16n8k16.row.col.f32.f16.f16.f32 "         \
        "{%0,%1,%2,%3},{%4,%5,%6,%7},{%8,%9},{%0,%1,%2,%3};"                  \
        : "+f"((d)[0]), "+f"((d)[1]), "+f"((d)[2]), "+f"((d)[3])              \
        : "r"((a)[0]), "r"((a)[1]), "r"((a)[2]), "r"((a)[3]),                 \
          "r"(b0), "r"(b1))

__device__ __forceinline__ float ex2f(float x) {
    float y;
    asm("ex2.approx.ftz.f32 %0, %1;" : "=f"(y) : "f"(x));
    return y;
}
__device__ __forceinline__ uint32_t h2u(__half2 h) {
    return *(uint32_t*)&h;
}
__device__ __forceinline__ uint32_t packh(float lo, float hi) {
    __half2 h = __float22half2_rn(make_float2(lo, hi));
    return h2u(h);
}

// split 4 fp32 -> 4 fp16 hi (uint2) + 4 fp16 lo residuals (uint2)
__device__ __forceinline__ void pack4h(const float* x, uint2& hi, uint2& lo) {
    __half2 h0 = __float22half2_rn(make_float2(x[0], x[1]));
    __half2 h1 = __float22half2_rn(make_float2(x[2], x[3]));
    float2 f0 = __half22float2(h0);
    float2 f1 = __half22float2(h1);
    __half2 l0 = __float22half2_rn(make_float2(x[0] - f0.x, x[1] - f0.y));
    __half2 l1 = __float22half2_rn(make_float2(x[2] - f1.x, x[3] - f1.y));
    hi.x = h2u(h0); hi.y = h2u(h1);
    lo.x = h2u(l0); lo.y = h2u(l1);
}

// ---------------------------------------------------------------------------
// RoPE table (reference-matching numerics)
// ---------------------------------------------------------------------------
__global__ void rope_table_kernel() {
    int idx = blockIdx.x * blockDim.x + threadIdx.x;
    if (idx >= SEQ * 64) return;
    int s = idx >> 6;
    int j = idx & 63;
    double inv = exp(-((double)j / 64.0) * log(10000.0));
    float  invf = (float)inv;
    float  ang  = (float)s * invf;
    g_cos[idx] = (float)cos((double)ang);
    g_sin[idx] = (float)sin((double)ang);
}

// ---------------------------------------------------------------------------
// Activation pack: fp32 -> fp16 hi plane only (8 elems/thread)
// ---------------------------------------------------------------------------
__global__ void pack_x_kernel(const float* __restrict__ X,
                              __half* __restrict__ P, int n) {
    int i = (blockIdx.x * 256 + threadIdx.x) * 8;
    if (i >= n) return;
    float4 a = *(const float4*)(X + i);
    float4 b = *(const float4*)(X + i + 4);
    *(uint4*)(P + i) = make_uint4(
        packh(a.x, a.y), packh(a.z, a.w), packh(b.x, b.y), packh(b.z, b.w));
}

// ---------------------------------------------------------------------------
// Weight pack: fp32 [N][2048] -> fp16 [N][4096] hi|lo (8 elems/thread)
// ---------------------------------------------------------------------------
__global__ void pack_w_kernel(const float* __restrict__ X,
                              __half* __restrict__ P, int n) {
    int i = (blockIdx.x * 256 + threadIdx.x) * 8;
    if (i >= n) return;
    int row = i >> 11, col = i & 2047;
    float4 a = *(const float4*)(X + i);
    float4 b = *(const float4*)(X + i + 4);
    float v0[4] = {a.x, a.y, a.z, a.w};
    float v1[4] = {b.x, b.y, b.z, b.w};
    uint2 h0, l0, h1, l1;
    pack4h(v0, h0, l0);
    pack4h(v1, h1, l1);
    *(uint4*)(P + (size_t)row * KB + col) = make_uint4(h0.x, h0.y, h1.x, h1.y);
    *(uint4*)(P + (size_t)row * KB + 2048 + col) = make_uint4(l0.x, l0.y, l1.x, l1.y);
}

// ---------------------------------------------------------------------------
// QKV pack: RoPE on q,k; fp16 split — q hi only, k/v hi|lo planes
// ---------------------------------------------------------------------------
__global__ void qkv_pack_kernel() {
    int idx = blockIdx.x * blockDim.x + threadIdx.x;   // MROWS*NH*16
    int jq  = (idx & 15) << 2;
    int h   = (idx >> 4) & (NH - 1);
    int row = idx >> 8;
    int s   = row & (SEQ - 1);
    int b   = row >> 11;
    int bh  = b * NH + h;

    float4 c4 = *(const float4*)&g_cos[(s << 6) + jq];
    float4 s4 = *(const float4*)&g_sin[(s << 6) + jq];
    float cc[4] = {c4.x, c4.y, c4.z, c4.w};
    float ss[4] = {s4.x, s4.y, s4.z, s4.w};

    const float* base = g_qkv + (size_t)row * QKVN + h * HD;
    float4 qa4 = *(const float4*)(base + jq);
    float4 qb4 = *(const float4*)(base + jq + 64);
    float4 ka4 = *(const float4*)(base + HID + jq);
    float4 kb4 = *(const float4*)(base + HID + jq + 64);
    float4 va4 = *(const float4*)(base + 2 * HID + jq);
    float4 vb4 = *(const float4*)(base + 2 * HID + jq + 64);
    float q1[4] = {qa4.x, qa4.y, qa4.z, qa4.w};
    float q2[4] = {qb4.x, qb4.y, qb4.z, qb4.w};
    float k1[4] = {ka4.x, ka4.y, ka4.z, ka4.w};
    float k2[4] = {kb4.x, kb4.y, kb4.z, kb4.w};
    float v1[4] = {va4.x, va4.y, va4.z, va4.w};
    float v2[4] = {vb4.x, vb4.y, vb4.z, vb4.w};

    float qa[4], qb[4], ka[4], kb[4];
#pragma unroll
    for (int e = 0; e < 4; e++) {
        qa[e] = q1[e] * cc[e] - q2[e] * ss[e];
        qb[e] = q2[e] * cc[e] + q1[e] * ss[e];
        ka[e] = k1[e] * cc[e] - k2[e] * ss[e];
        kb[e] = k2[e] * cc[e] + k1[e] * ss[e];
    }

    // q: single hi plane
    size_t qbse = ((size_t)bh * SEQ + s) * HD;
    *(uint2*)(g_qp + qbse + jq) =
        make_uint2(packh(qa[0], qa[1]), packh(qa[2], qa[3]));
    *(uint2*)(g_qp + qbse + jq + 64) =
        make_uint2(packh(qb[0], qb[1]), packh(qb[2], qb[3]));

    // k, v: hi | lo planes
    size_t pb = ((size_t)(bh * 2) * SEQ + s) * HD;
    const size_t PL = (size_t)SEQ * HD;
    uint2 hi, lo;
    pack4h(ka, hi, lo);
    *(uint2*)(g_kp + pb + jq)      = hi; *(uint2*)(g_kp + pb + PL + jq)      = lo;
    pack4h(kb, hi, lo);
    *(uint2*)(g_kp + pb + jq + 64) = hi; *(uint2*)(g_kp + pb + PL + jq + 64) = lo;
    pack4h(v1, hi, lo);
    *(uint2*)(g_vp + pb + jq)      = hi; *(uint2*)(g_vp + pb + PL + jq)      = lo;
    pack4h(v2, hi, lo);
    *(uint2*)(g_vp + pb + jq + 64) = hi; *(uint2*)(g_vp + pb + PL + jq + 64) = lo;
}

// ---------------------------------------------------------------------------
// fp16 2-pass tensor-core GEMM (unchanged from round 10 — passing).
// C = Ah*Bh + Ah*Bl; A: [M][2048], B: [N][4096] hi|lo.
// ---------------------------------------------------------------------------
#define AST         72
#define STG_MAT     (128 * AST * 2)
#define STG_BYTES   (2 * STG_MAT)
#define GEMM_STAGES 3
#define GEMM_SMEM   (GEMM_STAGES * STG_BYTES)
#define GNITER      64

__device__ __forceinline__ void g_load_stage(
    uint32_t sA, const __half* Ab, const __half* Bb, int tid)
{
#pragma unroll
    for (int t = 0; t < 8; t++) {
        int c = tid + t * 128;
        int r = c >> 3, co = (c & 7) << 3;
        CP_ASYNC16(sA + (r * AST + co) * 2, Ab + (size_t)r * KA + co);
        CP_ASYNC16(sA + STG_MAT + (r * AST + co) * 2, Bb + (size_t)r * KB + co);
    }
}

__global__ void __launch_bounds__(128, 2) tc_gemm_kernel(
    const __half* __restrict__ A, const __half* __restrict__ B,
    float* __restrict__ C, int ldc)
{
    extern __shared__ char smg[];
    uint32_t smb = s2u(smg);
    int tid  = threadIdx.x;
    int lane = tid & 31, wid = tid >> 5;
    int wm = (wid & 1) * 64, wn = (wid >> 1) * 64;
    int m0 = blockIdx.y * 128, n0 = blockIdx.x * 128;

    float acc[4][8][4];
#pragma unroll
    for (int i = 0; i < 4; i++)
#pragma unroll
        for (int j = 0; j < 8; j++)
#pragma unroll
            for (int k = 0; k < 4; k++) acc[i][j][k] = 0.f;

    auto chunk_off = [&](int it, int& boff, int& k0) {
        k0   = (it & 31) << 6;
        boff = (it >> 5) ? 2048 : 0;
    };

    uint32_t a_off[4][4], b_off[4][4];
#pragma unroll
    for (int ks = 0; ks < 4; ks++) {
#pragma unroll
        for (int mt = 0; mt < 4; mt++)
            a_off[ks][mt] = ((wm + mt * 16 + (lane & 15)) * AST +
                             ks * 16 + (lane >> 4) * 8) * 2;
#pragma unroll
        for (int np = 0; np < 4; np++)
            b_off[ks][np] = STG_MAT +
                ((wn + np * 16 + ((lane >> 4) & 1) * 8 + (lane & 7)) * AST +
                 ks * 16 + ((lane >> 3) & 1) * 8) * 2;
    }

#pragma unroll
    for (int p = 0; p < GEMM_STAGES - 1; p++) {
        int boff, k0;
        chunk_off(p, boff, k0);
        g_load_stage(smb + p * STG_BYTES,
                     A + (size_t)m0 * KA + k0,
                     B + (size_t)n0 * KB + boff + k0, tid);
        CP_COMMIT();
    }
    CP_WAIT1();
    __syncthreads();

    uint32_t af[2][4][4], bf[2][4];
#pragma unroll
    for (int mt = 0; mt < 4; mt++) LDSM4(af[0][mt], smb + a_off[0][mt]);
    LDSM4(bf[0], smb + b_off[0][0]);

    for (int it = 0; it < GNITER; ++it) {
        uint32_t sbase = smb + (it % GEMM_STAGES) * STG_BYTES;

        int nx = it + GEMM_STAGES - 1;
        if (nx < GNITER) {
            int boff, k0;
            chunk_off(nx, boff, k0);
            g_load_stage(smb + (nx % GEMM_STAGES) * STG_BYTES,
                         A + (size_t)m0 * KA + k0,
                         B + (size_t)n0 * KB + boff + k0, tid);
        }
        CP_COMMIT();

#pragma unroll
        for (int ks = 0; ks < 4; ks++) {
            int cur = ks & 1, nxt = cur ^ 1;
            uint32_t bb[2][4];
#pragma unroll
            for (int e = 0; e < 4; e++) bb[0][e] = bf[cur][e];
#pragma unroll
            for (int np = 0; np < 4; np++) {
                if (np < 3) LDSM4(bb[(np + 1) & 1], sbase + b_off[ks][np + 1]);
#pragma unroll
                for (int mt = 0; mt < 4; mt++) {
                    MMA16816H(acc[mt][2 * np],     af[cur][mt], bb[np & 1][0], bb[np & 1][1]);
                    MMA16816H(acc[mt][2 * np + 1], af[cur][mt], bb[np & 1][2], bb[np & 1][3]);
                }
            }
            if (ks < 3) {
#pragma unroll
                for (int mt = 0; mt < 4; mt++)
                    LDSM4(af[nxt][mt], sbase + a_off[ks + 1][mt]);
                LDSM4(bf[nxt], sbase + b_off[ks + 1][0]);
            }
        }

        CP_WAIT1();
        __syncthreads();
        uint32_t nbase = smb + ((it + 1) % GEMM_STAGES) * STG_BYTES;
#pragma unroll
        for (int mt = 0; mt < 4; mt++) LDSM4(af[0][mt], nbase + a_off[0][mt]);
        LDSM4(bf[0], nbase + b_off[0][0]);
    }

    float* Cb = C + (size_t)(m0 + wm) * ldc + n0 + wn;
    int rq = lane >> 2, cq = (lane & 3) * 2;
#pragma unroll
    for (int mt = 0; mt < 4; mt++)
#pragma unroll
        for (int nt = 0; nt < 8; nt++) {
            *(float2*)(Cb + (size_t)(mt * 16 + rq) * ldc + nt * 8 + cq) =
                make_float2(acc[mt][nt][0], acc[mt][nt][1]);
            *(float2*)(Cb + (size_t)(mt * 16 + rq + 8) * ldc + nt * 8 + cq) =
                make_float2(acc[mt][nt][2], acc[mt][nt][3]);
        }
}

// ---------------------------------------------------------------------------
// Tensor-core flash attention v4: fp16 2-pass (K,V split hi/lo; Q,P hi only),
// causal, online softmax, LPT grid, 3-stage KV ring, 1 sync/K-tile,
// fused fp16 ctx epilogue.
// ---------------------------------------------------------------------------
#define AKST     136
#define AROWB    (AKST * 2)
#define QPLANE   (128 * AROWB)
#define KVPLANE  (64 * AROWB)
#define STAGE_B  (4 * KVPLANE)
#define KVSTAGES 3
#define ATTN_SMEM (KVSTAGES * STAGE_B)

__device__ __forceinline__ void load_kv_stage(
    uint32_t dst, const __half* Kp, const __half* Vp, int k0, int tid)
{
#pragma unroll
    for (int t = 0; t < 16; t++) {
        int c = tid + t * 256;
        int plane = c >> 10;                // 0:Kh 1:Kl 2:Vh 3:Vl
        int r = (c >> 4) & 63;
        int co = c & 15;
        const __half* src = (plane < 2)
            ? Kp + ((size_t)plane * SEQ + k0 + r) * HD + co * 8
            : Vp + ((size_t)(plane - 2) * SEQ + k0 + r) * HD + co * 8;
        CP_ASYNC16(dst + plane * KVPLANE + r * AROWB + co * 16, src);
    }
}

__global__ void __launch_bounds__(256) attn_mma_kernel() {
    extern __shared__ char sma[];
    uint32_t smb = s2u(sma);
    int tid = threadIdx.x, lane = tid & 31, w = tid >> 5;
    int qt = 15 - ((int)blockIdx.x >> 5);   // LPT: heaviest first
    int bh = (int)blockIdx.x & 31;
    int q0 = qt * 128;
    int nkt = 2 * qt + 2;

    const __half* Qp = g_qp + (size_t)bh * SEQ * HD;
    const __half* Kp = g_kp + (size_t)(bh * 2) * SEQ * HD;
    const __half* Vp = g_vp + (size_t)(bh * 2) * SEQ * HD;

    // group 0: Q tile (single hi plane, 32 KB) into ring slot 2
    uint32_t sQstage = smb + 2 * STAGE_B;
#pragma unroll
    for (int t = 0; t < 8; t++) {
        int c = tid + t * 256;
        int r = c >> 4, co = c & 15;
        CP_ASYNC16(sQstage + r * AROWB + co * 16,
                   Qp + ((size_t)q0 + r) * HD + co * 8);
    }
    CP_COMMIT();
    load_kv_stage(smb, Kp, Vp, 0, tid);
    CP_COMMIT();
    load_kv_stage(smb + STAGE_B, Kp, Vp, 64, tid);
    CP_COMMIT();

    int rq = lane >> 2, cq = lane & 3;
    uint32_t qoff = (uint32_t)(16 * w + (lane & 15)) * AROWB + ((lane >> 4) & 1) * 16;
    uint32_t koff = (uint32_t)(((lane >> 4) & 1) * 8 + (lane & 7)) * AROWB +
                    ((lane >> 3) & 1) * 16;
    uint32_t voff = (uint32_t)(((lane >> 3) & 1) * 8 + (lane & 7)) * AROWB +
                    ((lane >> 4) & 1) * 16;

    // Q fragments -> registers (once, hi plane only)
    CP_WAIT2();
    __syncthreads();
    uint32_t qfh[8][4];
#pragma unroll
    for (int kc = 0; kc < 8; kc++)
        LDSM4(qfh[kc], sQstage + qoff + kc * 32);

    float out[16][4];
#pragma unroll
    for (int n = 0; n < 16; n++)
#pragma unroll
        for (int e = 0; e < 4; e++) out[n][e] = 0.f;
    float m0 = -1e30f, m1 = -1e30f, l0 = 0.f, l1 = 0.f;

    const float SCALE2 = 0.08838834764831845f * 1.44269504088896341f;

    for (int kt = 0; kt < nkt; kt++) {
        CP_WAIT1();
        __syncthreads();
        if (kt + 2 < nkt)
            load_kv_stage(smb + ((kt + 2) % KVSTAGES) * STAGE_B, Kp, Vp,
                          (kt + 2) * 64, tid);
        CP_COMMIT();

        uint32_t sKh = smb + (kt % KVSTAGES) * STAGE_B;
        uint32_t sKl = sKh + KVPLANE;
        uint32_t sVh = sKh + 2 * KVPLANE;
        uint32_t sVl = sKh + 3 * KVPLANE;

        // ---- scores: S = Qh*Kh + Qh*Kl (double-buffered K frags) ----
        float sc[8][4];
#pragma unroll
        for (int j = 0; j < 8; j++)
#pragma unroll
            for (int e = 0; e < 4; e++) sc[j][e] = 0.f;

        {
            uint32_t bkh[2][4], bkl[2][4];
            LDSM4(bkh[0], sKh + koff);
            LDSM4(bkl[0], sKl + koff);
#pragma unroll
            for (int t = 0; t < 32; t++) {
                int kc = t >> 2, jj = t & 3;
                int cur = t & 1;
                if (t < 31) {
                    int tn = t + 1;
                    uint32_t on = koff + (uint32_t)(tn & 3) * (16 * AROWB) +
                                  (tn >> 2) * 32;
                    LDSM4(bkh[cur ^ 1], sKh + on);
                    LDSM4(bkl[cur ^ 1], sKl + on);
                }
                MMA16816H(sc[2 * jj],     qfh[kc], bkh[cur][0], bkh[cur][1]);
                MMA16816H(sc[2 * jj],     qfh[kc], bkl[cur][0], bkl[cur][1]);
                MMA16816H(sc[2 * jj + 1], qfh[kc], bkh[cur][2], bkh[cur][3]);
                MMA16816H(sc[2 * jj + 1], qfh[kc], bkl[cur][2], bkl[cur][3]);
            }
        }

        int k0 = kt * 64;
#pragma unroll
        for (int j = 0; j < 8; j++)
#pragma unroll
            for (int e = 0; e < 4; e++) sc[j][e] *= SCALE2;
        if (k0 + 64 > q0) {
            int rg0 = q0 + 16 * w + rq, rg1 = rg0 + 8;
#pragma unroll
            for (int j = 0; j < 8; j++) {
                int cg = k0 + 8 * j + 2 * cq;
                if (cg     > rg0) sc[j][0] = -1e30f;
                if (cg + 1 > rg0) sc[j][1] = -1e30f;
                if (cg     > rg1) sc[j][2] = -1e30f;
                if (cg + 1 > rg1) sc[j][3] = -1e30f;
            }
        }

        float t0 = -1e30f, t1 = -1e30f;
#pragma unroll
        for (int j = 0; j < 8; j++) {
            t0 = fmaxf(t0, fmaxf(sc[j][0], sc[j][1]));
            t1 = fmaxf(t1, fmaxf(sc[j][2], sc[j][3]));
        }
        t0 = fmaxf(t0, __shfl_xor_sync(0xffffffffu, t0, 1));
        t0 = fmaxf(t0, __shfl_xor_sync(0xffffffffu, t0, 2));
        t1 = fmaxf(t1, __shfl_xor_sync(0xffffffffu, t1, 1));
        t1 = fmaxf(t1, __shfl_xor_sync(0xffffffffu, t1, 2));
        float mn0 = fmaxf(m0, t0), mn1 = fmaxf(m1, t1);
        float al0 = ex2f(m0 - mn0), al1 = ex2f(m1 - mn1);
        m0 = mn0; m1 = mn1;
        l0 *= al0; l1 *= al1;
#pragma unroll
        for (int n = 0; n < 16; n++) {
            out[n][0] *= al0; out[n][1] *= al0;
            out[n][2] *= al1; out[n][3] *= al1;
        }

        // ---- exp (P hi only) + PV (2 passes, double-buffered V frags) ----
#pragma unroll
        for (int kc = 0; kc < 4; kc++) {
            int j0 = 2 * kc, j1 = 2 * kc + 1;
            float p00 = ex2f(sc[j0][0] - m0), p01 = ex2f(sc[j0][1] - m0);
            float p02 = ex2f(sc[j0][2] - m1), p03 = ex2f(sc[j0][3] - m1);
            float p10 = ex2f(sc[j1][0] - m0), p11 = ex2f(sc[j1][1] - m0);
            float p12 = ex2f(sc[j1][2] - m1), p13 = ex2f(sc[j1][3] - m1);
            l0 += p00 + p01 + p10 + p11;
            l1 += p02 + p03 + p12 + p13;

            uint32_t ah[4];
            ah[0] = packh(p00, p01);
            ah[1] = packh(p02, p03);
            ah[2] = packh(p10, p11);
            ah[3] = packh(p12, p13);

            uint32_t bvh[2][4], bvl[2][4];
            uint32_t o0 = voff + (uint32_t)kc * (16 * AROWB);
            LDSM4T(bvh[0], sVh + o0);
            LDSM4T(bvl[0], sVl + o0);
#pragma unroll
            for (int jp = 0; jp < 8; jp++) {
                int cur = jp & 1;
                if (jp < 7) {
                    LDSM4T(bvh[cur ^ 1], sVh + o0 + (jp + 1) * 32);
                    LDSM4T(bvl[cur ^ 1], sVl + o0 + (jp + 1) * 32);
                }
                MMA16816H(out[2 * jp],     ah, bvh[cur][0], bvh[cur][1]);
                MMA16816H(out[2 * jp],     ah, bvl[cur][0], bvl[cur][1]);
                MMA16816H(out[2 * jp + 1], ah, bvh[cur][2], bvh[cur][3]);
                MMA16816H(out[2 * jp + 1], ah, bvl[cur][2], bvl[cur][3]);
            }
        }
    }

    l0 += __shfl_xor_sync(0xffffffffu, l0, 1);
    l0 += __shfl_xor_sync(0xffffffffu, l0, 2);
    l1 += __shfl_xor_sync(0xffffffffu, l1, 1);
    l1 += __shfl_xor_sync(0xffffffffu, l1, 2);
    float il0 = 1.f / l0, il1 = 1.f / l1;

    // Epilogue: write fp16 hi plane of ctx (out-proj A operand)
    int b = bh >> 4, hh = bh & 15;
    int grow0 = b * SEQ + q0 + 16 * w + rq;
    __half* cb0 = g_cxh + (size_t)grow0 * KA + hh * HD + 2 * cq;
    __half* cb1 = cb0 + (size_t)8 * KA;
#pragma unroll
    for (int nt = 0; nt < 16; nt++) {
        *(uint32_t*)(cb0 + nt * 8) = packh(out[nt][0] * il0, out[nt][1] * il0);
        *(uint32_t*)(cb1 + nt * 8) = packh(out[nt][2] * il1, out[nt][3] * il1);
    }
}

// ---------------------------------------------------------------------------
// Launch graph (idx 3 = QKV GEMM, the ncu capture slot)
// ---------------------------------------------------------------------------
extern "C" void kernel_launch(void* const* d_in, const int* in_sizes, int n_in,
                              void* d_out, int out_size) {
    const float* x    = (const float*)d_in[0];
    // d_in[1] = attn_mask (pure causal) — reproduced analytically, not read
    const float* Wqkv = (const float*)d_in[2];
    const float* Wout = (const float*)d_in[3];
    float* out = (float*)d_out;

    float* qkv_ptr = 0;
    __half *xh = 0, *wqp = 0, *wop = 0, *cxh = 0;
    cudaGetSymbolAddress((void**)&qkv_ptr, g_qkv);
    cudaGetSymbolAddress((void**)&xh,  g_xh);
    cudaGetSymbolAddress((void**)&wqp, g_wqp);
    cudaGetSymbolAddress((void**)&wop, g_wop);
    cudaGetSymbolAddress((void**)&cxh, g_cxh);

    cudaFuncSetAttribute(tc_gemm_kernel,
                         cudaFuncAttributeMaxDynamicSharedMemorySize, GEMM_SMEM);
    cudaFuncSetAttribute(attn_mma_kernel,
                         cudaFuncAttributeMaxDynamicSharedMemorySize, ATTN_SMEM);

    // idx 0..2: packs
    pack_x_kernel<<<MROWS * HID / 2048, 256>>>(x, xh, MROWS * HID);
    pack_w_kernel<<<QKVN * HID / 2048, 256>>>(Wqkv, wqp, QKVN * HID);
    pack_w_kernel<<<HID  * HID / 2048, 256>>>(Wout, wop, HID * HID);

    // idx 3: QKV GEMM (ncu capture slot)
    tc_gemm_kernel<<<dim3(QKVN / 128, MROWS / 128), 128, GEMM_SMEM>>>(
        xh, wqp, qkv_ptr, QKVN);

    // idx 4..5: RoPE table + qkv pack
    rope_table_kernel<<<(SEQ * 64 + 255) / 256, 256>>>();
    qkv_pack_kernel<<<MROWS * NH * 16 / 256, 256>>>();

    // idx 6: attention (fp16 2-pass, LPT grid, fused fp16 ctx epilogue)
    attn_mma_kernel<<<(SEQ / 128) * BATCH * NH, 256, ATTN_SMEM>>>();

    // idx 7: output GEMM
    tc_gemm_kernel<<<dim3(HID / 128, MROWS / 128), 128, GEMM_SMEM>>>(
        cxh, wop, out, HID);
}

// round 12
// speedup vs baseline: 13.5844x; 1.4379x over previous
#include <cuda_runtime.h>
#include <cuda_bf16.h>
#include <cuda_fp16.h>
#include <math.h>
#include <stdint.h>

// Problem constants
#define SEQ   2048
#define HID   2048
#define NH    16
#define HD    128
#define BATCH 2
#define MROWS (BATCH * SEQ)     // 4096
#define QKVN  (3 * HID)         // 6144
#define KA    2048              // fp16 row length (single hi plane)

// ---------------------------------------------------------------------------
// Scratch (device globals — no runtime allocation allowed)
// ---------------------------------------------------------------------------
__device__ __align__(16) float g_qkv[(size_t)MROWS * QKVN];    // fp32 QKV
__device__ __align__(16) float g_cos[SEQ * 64];
__device__ __align__(16) float g_sin[SEQ * 64];
__device__ __align__(16) __half g_xh [(size_t)MROWS * KA];     // x, fp16
__device__ __align__(16) __half g_wqp[(size_t)QKVN  * KA];     // Wqkv fp16
__device__ __align__(16) __half g_wop[(size_t)HID   * KA];     // Wout fp16
__device__ __align__(16) __half g_cxh[(size_t)MROWS * KA];     // ctx, fp16
// attention operands (fp16): q hi only; k,v hi|lo planes
__device__ __align__(16) __half g_qp[(size_t)BATCH * NH * SEQ * HD];
__device__ __align__(16) __half g_kp[(size_t)BATCH * NH * 2 * SEQ * HD];
__device__ __align__(16) __half g_vp[(size_t)BATCH * NH * 2 * SEQ * HD];

// ---------------------------------------------------------------------------
// PTX helpers (arch-agnostic: cp.async / ldmatrix / mma.sync only)
// ---------------------------------------------------------------------------
__device__ __forceinline__ uint32_t s2u(const void* p) {
    uint32_t a;
    asm("{ .reg .u64 t; cvta.to.shared.u64 t, %1; cvt.u32.u64 %0, t; }"
        : "=r"(a) : "l"(p));
    return a;
}

#define CP_ASYNC16(saddr, gptr) \
    asm volatile("cp.async.cg.shared.global [%0], [%1], 16;" \
                 :: "r"(saddr), "l"(gptr))
#define CP_COMMIT()  asm volatile("cp.async.commit_group;" ::: "memory")
#define CP_WAIT1()   asm volatile("cp.async.wait_group 1;" ::: "memory")
#define CP_WAIT2()   asm volatile("cp.async.wait_group 2;" ::: "memory")

#define LDSM4(r, addr)                                                        \
    asm volatile("ldmatrix.sync.aligned.m8n8.x4.shared.b16 {%0,%1,%2,%3}, [%4];" \
        : "=r"((r)[0]), "=r"((r)[1]), "=r"((r)[2]), "=r"((r)[3]) : "r"(addr))
#define LDSM4T(r, addr)                                                       \
    asm volatile("ldmatrix.sync.aligned.m8n8.x4.trans.shared.b16 {%0,%1,%2,%3}, [%4];" \
        : "=r"((r)[0]), "=r"((r)[1]), "=r"((r)[2]), "=r"((r)[3]) : "r"(addr))

// fp16 MMA
#define MMA16816H(d, a, b0, b1)                                               \
    asm volatile("mma.sync.aligned.m16n8k16.row.col.f32.f16.f16.f32 "         \
        "{%0,%1,%2,%3},{%4,%5,%6,%7},{%8,%9},{%0,%1,%2,%3};"                  \
        : "+f"((d)[0]), "+f"((d)[1]), "+f"((d)[2]), "+f"((d)[3])              \
        : "r"((a)[0]), "r"((a)[1]), "r"((a)[2]), "r"((a)[3]),                 \
          "r"(b0), "r"(b1))

__device__ __forceinline__ float ex2f(float x) {
    float y;
    asm("ex2.approx.ftz.f32 %0, %1;" : "=f"(y) : "f"(x));
    return y;
}
__device__ __forceinline__ uint32_t h2u(__half2 h) {
    return *(uint32_t*)&h;
}
__device__ __forceinline__ uint32_t packh(float lo, float hi) {
    __half2 h = __float22half2_rn(make_float2(lo, hi));
    return h2u(h);
}

// split 4 fp32 -> 4 fp16 hi (uint2) + 4 fp16 lo residuals (uint2)
__device__ __forceinline__ void pack4h(const float* x, uint2& hi, uint2& lo) {
    __half2 h0 = __float22half2_rn(make_float2(x[0], x[1]));
    __half2 h1 = __float22half2_rn(make_float2(x[2], x[3]));
    float2 f0 = __half22float2(h0);
    float2 f1 = __half22float2(h1);
    __half2 l0 = __float22half2_rn(make_float2(x[0] - f0.x, x[1] - f0.y));
    __half2 l1 = __float22half2_rn(make_float2(x[2] - f1.x, x[3] - f1.y));
    hi.x = h2u(h0); hi.y = h2u(h1);
    lo.x = h2u(l0); lo.y = h2u(l1);
}

// ---------------------------------------------------------------------------
// RoPE table (reference-matching numerics)
// ---------------------------------------------------------------------------
__global__ void rope_table_kernel() {
    int idx = blockIdx.x * blockDim.x + threadIdx.x;
    if (idx >= SEQ * 64) return;
    int s = idx >> 6;
    int j = idx & 63;
    double inv = exp(-((double)j / 64.0) * log(10000.0));
    float  invf = (float)inv;
    float  ang  = (float)s * invf;
    g_cos[idx] = (float)cos((double)ang);
    g_sin[idx] = (float)sin((double)ang);
}

// ---------------------------------------------------------------------------
// fp32 -> fp16 single-plane pack (8 elems/thread) — used for x and weights
// ---------------------------------------------------------------------------
__global__ void pack_x_kernel(const float* __restrict__ X,
                              __half* __restrict__ P, int n) {
    int i = (blockIdx.x * 256 + threadIdx.x) * 8;
    if (i >= n) return;
    float4 a = *(const float4*)(X + i);
    float4 b = *(const float4*)(X + i + 4);
    *(uint4*)(P + i) = make_uint4(
        packh(a.x, a.y), packh(a.z, a.w), packh(b.x, b.y), packh(b.z, b.w));
}

// ---------------------------------------------------------------------------
// QKV pack: RoPE on q,k; fp16 split — q hi only, k/v hi|lo planes
// ---------------------------------------------------------------------------
__global__ void qkv_pack_kernel() {
    int idx = blockIdx.x * blockDim.x + threadIdx.x;   // MROWS*NH*16
    int jq  = (idx & 15) << 2;
    int h   = (idx >> 4) & (NH - 1);
    int row = idx >> 8;
    int s   = row & (SEQ - 1);
    int b   = row >> 11;
    int bh  = b * NH + h;

    float4 c4 = *(const float4*)&g_cos[(s << 6) + jq];
    float4 s4 = *(const float4*)&g_sin[(s << 6) + jq];
    float cc[4] = {c4.x, c4.y, c4.z, c4.w};
    float ss[4] = {s4.x, s4.y, s4.z, s4.w};

    const float* base = g_qkv + (size_t)row * QKVN + h * HD;
    float4 qa4 = *(const float4*)(base + jq);
    float4 qb4 = *(const float4*)(base + jq + 64);
    float4 ka4 = *(const float4*)(base + HID + jq);
    float4 kb4 = *(const float4*)(base + HID + jq + 64);
    float4 va4 = *(const float4*)(base + 2 * HID + jq);
    float4 vb4 = *(const float4*)(base + 2 * HID + jq + 64);
    float q1[4] = {qa4.x, qa4.y, qa4.z, qa4.w};
    float q2[4] = {qb4.x, qb4.y, qb4.z, qb4.w};
    float k1[4] = {ka4.x, ka4.y, ka4.z, ka4.w};
    float k2[4] = {kb4.x, kb4.y, kb4.z, kb4.w};
    float v1[4] = {va4.x, va4.y, va4.z, va4.w};
    float v2[4] = {vb4.x, vb4.y, vb4.z, vb4.w};

    float qa[4], qb[4], ka[4], kb[4];
#pragma unroll
    for (int e = 0; e < 4; e++) {
        qa[e] = q1[e] * cc[e] - q2[e] * ss[e];
        qb[e] = q2[e] * cc[e] + q1[e] * ss[e];
        ka[e] = k1[e] * cc[e] - k2[e] * ss[e];
        kb[e] = k2[e] * cc[e] + k1[e] * ss[e];
    }

    // q: single hi plane
    size_t qbse = ((size_t)bh * SEQ + s) * HD;
    *(uint2*)(g_qp + qbse + jq) =
        make_uint2(packh(qa[0], qa[1]), packh(qa[2], qa[3]));
    *(uint2*)(g_qp + qbse + jq + 64) =
        make_uint2(packh(qb[0], qb[1]), packh(qb[2], qb[3]));

    // k, v: hi | lo planes
    size_t pb = ((size_t)(bh * 2) * SEQ + s) * HD;
    const size_t PL = (size_t)SEQ * HD;
    uint2 hi, lo;
    pack4h(ka, hi, lo);
    *(uint2*)(g_kp + pb + jq)      = hi; *(uint2*)(g_kp + pb + PL + jq)      = lo;
    pack4h(kb, hi, lo);
    *(uint2*)(g_kp + pb + jq + 64) = hi; *(uint2*)(g_kp + pb + PL + jq + 64) = lo;
    pack4h(v1, hi, lo);
    *(uint2*)(g_vp + pb + jq)      = hi; *(uint2*)(g_vp + pb + PL + jq)      = lo;
    pack4h(v2, hi, lo);
    *(uint2*)(g_vp + pb + jq + 64) = hi; *(uint2*)(g_vp + pb + PL + jq + 64) = lo;
}

// ---------------------------------------------------------------------------
// fp16 1-pass tensor-core GEMM: C = Ah * Bh^T.
// A: [M][2048], B: [N][2048]. 4 warps, 64x64 warp tiles, K=64 stages,
// 3-stage cp.async ring, software-pipelined fragments.
// ---------------------------------------------------------------------------
#define AST         72
#define STG_MAT     (128 * AST * 2)
#define STG_BYTES   (2 * STG_MAT)
#define GEMM_STAGES 3
#define GEMM_SMEM   (GEMM_STAGES * STG_BYTES)
#define GNITER      32                   // 1 pass x 32 chunks of K=64

__device__ __forceinline__ void g_load_stage(
    uint32_t sA, const __half* Ab, const __half* Bb, int tid)
{
#pragma unroll
    for (int t = 0; t < 8; t++) {
        int c = tid + t * 128;
        int r = c >> 3, co = (c & 7) << 3;
        CP_ASYNC16(sA + (r * AST + co) * 2, Ab + (size_t)r * KA + co);
        CP_ASYNC16(sA + STG_MAT + (r * AST + co) * 2, Bb + (size_t)r * KA + co);
    }
}

__global__ void __launch_bounds__(128, 2) tc_gemm_kernel(
    const __half* __restrict__ A, const __half* __restrict__ B,
    float* __restrict__ C, int ldc)
{
    extern __shared__ char smg[];
    uint32_t smb = s2u(smg);
    int tid  = threadIdx.x;
    int lane = tid & 31, wid = tid >> 5;
    int wm = (wid & 1) * 64, wn = (wid >> 1) * 64;
    int m0 = blockIdx.y * 128, n0 = blockIdx.x * 128;

    float acc[4][8][4];
#pragma unroll
    for (int i = 0; i < 4; i++)
#pragma unroll
        for (int j = 0; j < 8; j++)
#pragma unroll
            for (int k = 0; k < 4; k++) acc[i][j][k] = 0.f;

    uint32_t a_off[4][4], b_off[4][4];
#pragma unroll
    for (int ks = 0; ks < 4; ks++) {
#pragma unroll
        for (int mt = 0; mt < 4; mt++)
            a_off[ks][mt] = ((wm + mt * 16 + (lane & 15)) * AST +
                             ks * 16 + (lane >> 4) * 8) * 2;
#pragma unroll
        for (int np = 0; np < 4; np++)
            b_off[ks][np] = STG_MAT +
                ((wn + np * 16 + ((lane >> 4) & 1) * 8 + (lane & 7)) * AST +
                 ks * 16 + ((lane >> 3) & 1) * 8) * 2;
    }

#pragma unroll
    for (int p = 0; p < GEMM_STAGES - 1; p++) {
        g_load_stage(smb + p * STG_BYTES,
                     A + (size_t)m0 * KA + (p << 6),
                     B + (size_t)n0 * KA + (p << 6), tid);
        CP_COMMIT();
    }
    CP_WAIT1();
    __syncthreads();

    uint32_t af[2][4][4], bf[2][4];
#pragma unroll
    for (int mt = 0; mt < 4; mt++) LDSM4(af[0][mt], smb + a_off[0][mt]);
    LDSM4(bf[0], smb + b_off[0][0]);

    for (int it = 0; it < GNITER; ++it) {
        uint32_t sbase = smb + (it % GEMM_STAGES) * STG_BYTES;

        int nx = it + GEMM_STAGES - 1;
        if (nx < GNITER) {
            g_load_stage(smb + (nx % GEMM_STAGES) * STG_BYTES,
                         A + (size_t)m0 * KA + (nx << 6),
                         B + (size_t)n0 * KA + (nx << 6), tid);
        }
        CP_COMMIT();

#pragma unroll
        for (int ks = 0; ks < 4; ks++) {
            int cur = ks & 1, nxt = cur ^ 1;
            uint32_t bb[2][4];
#pragma unroll
            for (int e = 0; e < 4; e++) bb[0][e] = bf[cur][e];
#pragma unroll
            for (int np = 0; np < 4; np++) {
                if (np < 3) LDSM4(bb[(np + 1) & 1], sbase + b_off[ks][np + 1]);
#pragma unroll
                for (int mt = 0; mt < 4; mt++) {
                    MMA16816H(acc[mt][2 * np],     af[cur][mt], bb[np & 1][0], bb[np & 1][1]);
                    MMA16816H(acc[mt][2 * np + 1], af[cur][mt], bb[np & 1][2], bb[np & 1][3]);
                }
            }
            if (ks < 3) {
#pragma unroll
                for (int mt = 0; mt < 4; mt++)
                    LDSM4(af[nxt][mt], sbase + a_off[ks + 1][mt]);
                LDSM4(bf[nxt], sbase + b_off[ks + 1][0]);
            }
        }

        CP_WAIT1();
        __syncthreads();
        uint32_t nbase = smb + ((it + 1) % GEMM_STAGES) * STG_BYTES;
#pragma unroll
        for (int mt = 0; mt < 4; mt++) LDSM4(af[0][mt], nbase + a_off[0][mt]);
        LDSM4(bf[0], nbase + b_off[0][0]);
    }

    float* Cb = C + (size_t)(m0 + wm) * ldc + n0 + wn;
    int rq = lane >> 2, cq = (lane & 3) * 2;
#pragma unroll
    for (int mt = 0; mt < 4; mt++)
#pragma unroll
        for (int nt = 0; nt < 8; nt++) {
            *(float2*)(Cb + (size_t)(mt * 16 + rq) * ldc + nt * 8 + cq) =
                make_float2(acc[mt][nt][0], acc[mt][nt][1]);
            *(float2*)(Cb + (size_t)(mt * 16 + rq + 8) * ldc + nt * 8 + cq) =
                make_float2(acc[mt][nt][2], acc[mt][nt][3]);
        }
}

// ---------------------------------------------------------------------------
// Tensor-core flash attention (fp16 2-pass: K,V hi|lo; Q,P hi only),
// causal, online softmax, LPT grid, 3-stage KV ring, 1 sync/K-tile,
// fused fp16 ctx epilogue. Unchanged from round 11 (passing).
// ---------------------------------------------------------------------------
#define AKST     136
#define AROWB    (AKST * 2)
#define QPLANE   (128 * AROWB)
#define KVPLANE  (64 * AROWB)
#define STAGE_B  (4 * KVPLANE)
#define KVSTAGES 3
#define ATTN_SMEM (KVSTAGES * STAGE_B)

__device__ __forceinline__ void load_kv_stage(
    uint32_t dst, const __half* Kp, const __half* Vp, int k0, int tid)
{
#pragma unroll
    for (int t = 0; t < 16; t++) {
        int c = tid + t * 256;
        int plane = c >> 10;                // 0:Kh 1:Kl 2:Vh 3:Vl
        int r = (c >> 4) & 63;
        int co = c & 15;
        const __half* src = (plane < 2)
            ? Kp + ((size_t)plane * SEQ + k0 + r) * HD + co * 8
            : Vp + ((size_t)(plane - 2) * SEQ + k0 + r) * HD + co * 8;
        CP_ASYNC16(dst + plane * KVPLANE + r * AROWB + co * 16, src);
    }
}

__global__ void __launch_bounds__(256) attn_mma_kernel() {
    extern __shared__ char sma[];
    uint32_t smb = s2u(sma);
    int tid = threadIdx.x, lane = tid & 31, w = tid >> 5;
    int qt = 15 - ((int)blockIdx.x >> 5);   // LPT: heaviest first
    int bh = (int)blockIdx.x & 31;
    int q0 = qt * 128;
    int nkt = 2 * qt + 2;

    const __half* Qp = g_qp + (size_t)bh * SEQ * HD;
    const __half* Kp = g_kp + (size_t)(bh * 2) * SEQ * HD;
    const __half* Vp = g_vp + (size_t)(bh * 2) * SEQ * HD;

    uint32_t sQstage = smb + 2 * STAGE_B;
#pragma unroll
    for (int t = 0; t < 8; t++) {
        int c = tid + t * 256;
        int r = c >> 4, co = c & 15;
        CP_ASYNC16(sQstage + r * AROWB + co * 16,
                   Qp + ((size_t)q0 + r) * HD + co * 8);
    }
    CP_COMMIT();
    load_kv_stage(smb, Kp, Vp, 0, tid);
    CP_COMMIT();
    load_kv_stage(smb + STAGE_B, Kp, Vp, 64, tid);
    CP_COMMIT();

    int rq = lane >> 2, cq = lane & 3;
    uint32_t qoff = (uint32_t)(16 * w + (lane & 15)) * AROWB + ((lane >> 4) & 1) * 16;
    uint32_t koff = (uint32_t)(((lane >> 4) & 1) * 8 + (lane & 7)) * AROWB +
                    ((lane >> 3) & 1) * 16;
    uint32_t voff = (uint32_t)(((lane >> 3) & 1) * 8 + (lane & 7)) * AROWB +
                    ((lane >> 4) & 1) * 16;

    CP_WAIT2();
    __syncthreads();
    uint32_t qfh[8][4];
#pragma unroll
    for (int kc = 0; kc < 8; kc++)
        LDSM4(qfh[kc], sQstage + qoff + kc * 32);

    float out[16][4];
#pragma unroll
    for (int n = 0; n < 16; n++)
#pragma unroll
        for (int e = 0; e < 4; e++) out[n][e] = 0.f;
    float m0 = -1e30f, m1 = -1e30f, l0 = 0.f, l1 = 0.f;

    const float SCALE2 = 0.08838834764831845f * 1.44269504088896341f;

    for (int kt = 0; kt < nkt; kt++) {
        CP_WAIT1();
        __syncthreads();
        if (kt + 2 < nkt)
            load_kv_stage(smb + ((kt + 2) % KVSTAGES) * STAGE_B, Kp, Vp,
                          (kt + 2) * 64, tid);
        CP_COMMIT();

        uint32_t sKh = smb + (kt % KVSTAGES) * STAGE_B;
        uint32_t sKl = sKh + KVPLANE;
        uint32_t sVh = sKh + 2 * KVPLANE;
        uint32_t sVl = sKh + 3 * KVPLANE;

        float sc[8][4];
#pragma unroll
        for (int j = 0; j < 8; j++)
#pragma unroll
            for (int e = 0; e < 4; e++) sc[j][e] = 0.f;

        {
            uint32_t bkh[2][4], bkl[2][4];
            LDSM4(bkh[0], sKh + koff);
            LDSM4(bkl[0], sKl + koff);
#pragma unroll
            for (int t = 0; t < 32; t++) {
                int kc = t >> 2, jj = t & 3;
                int cur = t & 1;
                if (t < 31) {
                    int tn = t + 1;
                    uint32_t on = koff + (uint32_t)(tn & 3) * (16 * AROWB) +
                                  (tn >> 2) * 32;
                    LDSM4(bkh[cur ^ 1], sKh + on);
                    LDSM4(bkl[cur ^ 1], sKl + on);
                }
                MMA16816H(sc[2 * jj],     qfh[kc], bkh[cur][0], bkh[cur][1]);
                MMA16816H(sc[2 * jj],     qfh[kc], bkl[cur][0], bkl[cur][1]);
                MMA16816H(sc[2 * jj + 1], qfh[kc], bkh[cur][2], bkh[cur][3]);
                MMA16816H(sc[2 * jj + 1], qfh[kc], bkl[cur][2], bkl[cur][3]);
            }
        }

        int k0 = kt * 64;
#pragma unroll
        for (int j = 0; j < 8; j++)
#pragma unroll
            for (int e = 0; e < 4; e++) sc[j][e] *= SCALE2;
        if (k0 + 64 > q0) {
            int rg0 = q0 + 16 * w + rq, rg1 = rg0 + 8;
#pragma unroll
            for (int j = 0; j < 8; j++) {
                int cg = k0 + 8 * j + 2 * cq;
                if (cg     > rg0) sc[j][0] = -1e30f;
                if (cg + 1 > rg0) sc[j][1] = -1e30f;
                if (cg     > rg1) sc[j][2] = -1e30f;
                if (cg + 1 > rg1) sc[j][3] = -1e30f;
            }
        }

        float t0 = -1e30f, t1 = -1e30f;
#pragma unroll
        for (int j = 0; j < 8; j++) {
            t0 = fmaxf(t0, fmaxf(sc[j][0], sc[j][1]));
            t1 = fmaxf(t1, fmaxf(sc[j][2], sc[j][3]));
        }
        t0 = fmaxf(t0, __shfl_xor_sync(0xffffffffu, t0, 1));
        t0 = fmaxf(t0, __shfl_xor_sync(0xffffffffu, t0, 2));
        t1 = fmaxf(t1, __shfl_xor_sync(0xffffffffu, t1, 1));
        t1 = fmaxf(t1, __shfl_xor_sync(0xffffffffu, t1, 2));
        float mn0 = fmaxf(m0, t0), mn1 = fmaxf(m1, t1);
        float al0 = ex2f(m0 - mn0), al1 = ex2f(m1 - mn1);
        m0 = mn0; m1 = mn1;
        l0 *= al0; l1 *= al1;
#pragma unroll
        for (int n = 0; n < 16; n++) {
            out[n][0] *= al0; out[n][1] *= al0;
            out[n][2] *= al1; out[n][3] *= al1;
        }

#pragma unroll
        for (int kc = 0; kc < 4; kc++) {
            int j0 = 2 * kc, j1 = 2 * kc + 1;
            float p00 = ex2f(sc[j0][0] - m0), p01 = ex2f(sc[j0][1] - m0);
            float p02 = ex2f(sc[j0][2] - m1), p03 = ex2f(sc[j0][3] - m1);
            float p10 = ex2f(sc[j1][0] - m0), p11 = ex2f(sc[j1][1] - m0);
            float p12 = ex2f(sc[j1][2] - m1), p13 = ex2f(sc[j1][3] - m1);
            l0 += p00 + p01 + p10 + p11;
            l1 += p02 + p03 + p12 + p13;

            uint32_t ah[4];
            ah[0] = packh(p00, p01);
            ah[1] = packh(p02, p03);
            ah[2] = packh(p10, p11);
            ah[3] = packh(p12, p13);

            uint32_t bvh[2][4], bvl[2][4];
            uint32_t o0 = voff + (uint32_t)kc * (16 * AROWB);
            LDSM4T(bvh[0], sVh + o0);
            LDSM4T(bvl[0], sVl + o0);
#pragma unroll
            for (int jp = 0; jp < 8; jp++) {
                int cur = jp & 1;
                if (jp < 7) {
                    LDSM4T(bvh[cur ^ 1], sVh + o0 + (jp + 1) * 32);
                    LDSM4T(bvl[cur ^ 1], sVl + o0 + (jp + 1) * 32);
                }
                MMA16816H(out[2 * jp],     ah, bvh[cur][0], bvh[cur][1]);
                MMA16816H(out[2 * jp],     ah, bvl[cur][0], bvl[cur][1]);
                MMA16816H(out[2 * jp + 1], ah, bvh[cur][2], bvh[cur][3]);
                MMA16816H(out[2 * jp + 1], ah, bvl[cur][2], bvl[cur][3]);
            }
        }
    }

    l0 += __shfl_xor_sync(0xffffffffu, l0, 1);
    l0 += __shfl_xor_sync(0xffffffffu, l0, 2);
    l1 += __shfl_xor_sync(0xffffffffu, l1, 1);
    l1 += __shfl_xor_sync(0xffffffffu, l1, 2);
    float il0 = 1.f / l0, il1 = 1.f / l1;

    int b = bh >> 4, hh = bh & 15;
    int grow0 = b * SEQ + q0 + 16 * w + rq;
    __half* cb0 = g_cxh + (size_t)grow0 * KA + hh * HD + 2 * cq;
    __half* cb1 = cb0 + (size_t)8 * KA;
#pragma unroll
    for (int nt = 0; nt < 16; nt++) {
        *(uint32_t*)(cb0 + nt * 8) = packh(out[nt][0] * il0, out[nt][1] * il0);
        *(uint32_t*)(cb1 + nt * 8) = packh(out[nt][2] * il1, out[nt][3] * il1);
    }
}

// ---------------------------------------------------------------------------
// Launch graph (idx 3 = QKV GEMM, the ncu capture slot)
// ---------------------------------------------------------------------------
extern "C" void kernel_launch(void* const* d_in, const int* in_sizes, int n_in,
                              void* d_out, int out_size) {
    const float* x    = (const float*)d_in[0];
    // d_in[1] = attn_mask (pure causal) — reproduced analytically, not read
    const float* Wqkv = (const float*)d_in[2];
    const float* Wout = (const float*)d_in[3];
    float* out = (float*)d_out;

    float* qkv_ptr = 0;
    __half *xh = 0, *wqp = 0, *wop = 0, *cxh = 0;
    cudaGetSymbolAddress((void**)&qkv_ptr, g_qkv);
    cudaGetSymbolAddress((void**)&xh,  g_xh);
    cudaGetSymbolAddress((void**)&wqp, g_wqp);
    cudaGetSymbolAddress((void**)&wop, g_wop);
    cudaGetSymbolAddress((void**)&cxh, g_cxh);

    cudaFuncSetAttribute(tc_gemm_kernel,
                         cudaFuncAttributeMaxDynamicSharedMemorySize, GEMM_SMEM);
    cudaFuncSetAttribute(attn_mma_kernel,
                         cudaFuncAttributeMaxDynamicSharedMemorySize, ATTN_SMEM);

    // idx 0..2: packs (all single fp16 plane now)
    pack_x_kernel<<<MROWS * HID / 2048, 256>>>(x, xh, MROWS * HID);
    pack_x_kernel<<<QKVN * HID / 2048, 256>>>(Wqkv, wqp, QKVN * HID);
    pack_x_kernel<<<HID  * HID / 2048, 256>>>(Wout, wop, HID * HID);

    // idx 3: QKV GEMM (ncu capture slot)
    tc_gemm_kernel<<<dim3(QKVN / 128, MROWS / 128), 128, GEMM_SMEM>>>(
        xh, wqp, qkv_ptr, QKVN);

    // idx 4..5: RoPE table + qkv pack
    rope_table_kernel<<<(SEQ * 64 + 255) / 256, 256>>>();
    qkv_pack_kernel<<<MROWS * NH * 16 / 256, 256>>>();

    // idx 6: attention (fp16 2-pass, LPT grid, fused fp16 ctx epilogue)
    attn_mma_kernel<<<(SEQ / 128) * BATCH * NH, 256, ATTN_SMEM>>>();

    // idx 7: output GEMM
    tc_gemm_kernel<<<dim3(HID / 128, MROWS / 128), 128, GEMM_SMEM>>>(
        cxh, wop, out, HID);
}

// round 13
// speedup vs baseline: 15.8586x; 1.1674x over previous
#include <cuda_runtime.h>
#include <cuda_bf16.h>
#include <cuda_fp16.h>
#include <math.h>
#include <stdint.h>

// Problem constants
#define SEQ   2048
#define HID   2048
#define NH    16
#define HD    128
#define BATCH 2
#define MROWS (BATCH * SEQ)     // 4096
#define QKVN  (3 * HID)         // 6144
#define KA    2048              // fp16 row length (single plane)

// ---------------------------------------------------------------------------
// Scratch (device globals — no runtime allocation allowed)
// ---------------------------------------------------------------------------
__device__ __align__(16) float g_qkv[(size_t)MROWS * QKVN];    // fp32 QKV
__device__ __align__(16) float g_cos[SEQ * 64];
__device__ __align__(16) float g_sin[SEQ * 64];
__device__ __align__(16) __half g_xh [(size_t)MROWS * KA];     // x, fp16
__device__ __align__(16) __half g_wqp[(size_t)QKVN  * KA];     // Wqkv fp16
__device__ __align__(16) __half g_wop[(size_t)HID   * KA];     // Wout fp16
__device__ __align__(16) __half g_cxh[(size_t)MROWS * KA];     // ctx, fp16
// attention operands (fp16, single plane each)
__device__ __align__(16) __half g_qp[(size_t)BATCH * NH * SEQ * HD];
__device__ __align__(16) __half g_kp[(size_t)BATCH * NH * SEQ * HD];
__device__ __align__(16) __half g_vp[(size_t)BATCH * NH * SEQ * HD];

// ---------------------------------------------------------------------------
// PTX helpers (arch-agnostic: cp.async / ldmatrix / mma.sync only)
// ---------------------------------------------------------------------------
__device__ __forceinline__ uint32_t s2u(const void* p) {
    uint32_t a;
    asm("{ .reg .u64 t; cvta.to.shared.u64 t, %1; cvt.u32.u64 %0, t; }"
        : "=r"(a) : "l"(p));
    return a;
}

#define CP_ASYNC16(saddr, gptr) \
    asm volatile("cp.async.cg.shared.global [%0], [%1], 16;" \
                 :: "r"(saddr), "l"(gptr))
#define CP_COMMIT()  asm volatile("cp.async.commit_group;" ::: "memory")
#define CP_WAIT1()   asm volatile("cp.async.wait_group 1;" ::: "memory")
#define CP_WAIT2()   asm volatile("cp.async.wait_group 2;" ::: "memory")

#define LDSM4(r, addr)                                                        \
    asm volatile("ldmatrix.sync.aligned.m8n8.x4.shared.b16 {%0,%1,%2,%3}, [%4];" \
        : "=r"((r)[0]), "=r"((r)[1]), "=r"((r)[2]), "=r"((r)[3]) : "r"(addr))
#define LDSM4T(r, addr)                                                       \
    asm volatile("ldmatrix.sync.aligned.m8n8.x4.trans.shared.b16 {%0,%1,%2,%3}, [%4];" \
        : "=r"((r)[0]), "=r"((r)[1]), "=r"((r)[2]), "=r"((r)[3]) : "r"(addr))

// fp16 MMA
#define MMA16816H(d, a, b0, b1)                                               \
    asm volatile("mma.sync.aligned.m16n8k16.row.col.f32.f16.f16.f32 "         \
        "{%0,%1,%2,%3},{%4,%5,%6,%7},{%8,%9},{%0,%1,%2,%3};"                  \
        : "+f"((d)[0]), "+f"((d)[1]), "+f"((d)[2]), "+f"((d)[3])              \
        : "r"((a)[0]), "r"((a)[1]), "r"((a)[2]), "r"((a)[3]),                 \
          "r"(b0), "r"(b1))

__device__ __forceinline__ float ex2f(float x) {
    float y;
    asm("ex2.approx.ftz.f32 %0, %1;" : "=f"(y) : "f"(x));
    return y;
}
__device__ __forceinline__ uint32_t h2u(__half2 h) {
    return *(uint32_t*)&h;
}
__device__ __forceinline__ uint32_t packh(float lo, float hi) {
    __half2 h = __float22half2_rn(make_float2(lo, hi));
    return h2u(h);
}

// ---------------------------------------------------------------------------
// RoPE table (reference-matching numerics)
// ---------------------------------------------------------------------------
__global__ void rope_table_kernel() {
    int idx = blockIdx.x * blockDim.x + threadIdx.x;
    if (idx >= SEQ * 64) return;
    int s = idx >> 6;
    int j = idx & 63;
    double inv = exp(-((double)j / 64.0) * log(10000.0));
    float  invf = (float)inv;
    float  ang  = (float)s * invf;
    g_cos[idx] = (float)cos((double)ang);
    g_sin[idx] = (float)sin((double)ang);
}

// ---------------------------------------------------------------------------
// fp32 -> fp16 single-plane pack (8 elems/thread) — x and weights
// ---------------------------------------------------------------------------
__global__ void pack_x_kernel(const float* __restrict__ X,
                              __half* __restrict__ P, int n) {
    int i = (blockIdx.x * 256 + threadIdx.x) * 8;
    if (i >= n) return;
    float4 a = *(const float4*)(X + i);
    float4 b = *(const float4*)(X + i + 4);
    *(uint4*)(P + i) = make_uint4(
        packh(a.x, a.y), packh(a.z, a.w), packh(b.x, b.y), packh(b.z, b.w));
}

// ---------------------------------------------------------------------------
// QKV pack: RoPE on q,k; fp16 single plane for q,k,v
// ---------------------------------------------------------------------------
__global__ void qkv_pack_kernel() {
    int idx = blockIdx.x * blockDim.x + threadIdx.x;   // MROWS*NH*16
    int jq  = (idx & 15) << 2;
    int h   = (idx >> 4) & (NH - 1);
    int row = idx >> 8;
    int s   = row & (SEQ - 1);
    int b   = row >> 11;
    int bh  = b * NH + h;

    float4 c4 = *(const float4*)&g_cos[(s << 6) + jq];
    float4 s4 = *(const float4*)&g_sin[(s << 6) + jq];
    float cc[4] = {c4.x, c4.y, c4.z, c4.w};
    float ss[4] = {s4.x, s4.y, s4.z, s4.w};

    const float* base = g_qkv + (size_t)row * QKVN + h * HD;
    float4 qa4 = *(const float4*)(base + jq);
    float4 qb4 = *(const float4*)(base + jq + 64);
    float4 ka4 = *(const float4*)(base + HID + jq);
    float4 kb4 = *(const float4*)(base + HID + jq + 64);
    float4 va4 = *(const float4*)(base + 2 * HID + jq);
    float4 vb4 = *(const float4*)(base + 2 * HID + jq + 64);
    float q1[4] = {qa4.x, qa4.y, qa4.z, qa4.w};
    float q2[4] = {qb4.x, qb4.y, qb4.z, qb4.w};
    float k1[4] = {ka4.x, ka4.y, ka4.z, ka4.w};
    float k2[4] = {kb4.x, kb4.y, kb4.z, kb4.w};

    float qa[4], qb[4], ka[4], kb[4];
#pragma unroll
    for (int e = 0; e < 4; e++) {
        qa[e] = q1[e] * cc[e] - q2[e] * ss[e];
        qb[e] = q2[e] * cc[e] + q1[e] * ss[e];
        ka[e] = k1[e] * cc[e] - k2[e] * ss[e];
        kb[e] = k2[e] * cc[e] + k1[e] * ss[e];
    }

    size_t pbse = ((size_t)bh * SEQ + s) * HD;
    *(uint2*)(g_qp + pbse + jq) =
        make_uint2(packh(qa[0], qa[1]), packh(qa[2], qa[3]));
    *(uint2*)(g_qp + pbse + jq + 64) =
        make_uint2(packh(qb[0], qb[1]), packh(qb[2], qb[3]));
    *(uint2*)(g_kp + pbse + jq) =
        make_uint2(packh(ka[0], ka[1]), packh(ka[2], ka[3]));
    *(uint2*)(g_kp + pbse + jq + 64) =
        make_uint2(packh(kb[0], kb[1]), packh(kb[2], kb[3]));
    *(uint2*)(g_vp + pbse + jq) =
        make_uint2(packh(va4.x, va4.y), packh(va4.z, va4.w));
    *(uint2*)(g_vp + pbse + jq + 64) =
        make_uint2(packh(vb4.x, vb4.y), packh(vb4.z, vb4.w));
}

// ---------------------------------------------------------------------------
// fp16 1-pass tensor-core GEMM (unchanged from round 12 — passing).
// ---------------------------------------------------------------------------
#define AST         72
#define STG_MAT     (128 * AST * 2)
#define STG_BYTES   (2 * STG_MAT)
#define GEMM_STAGES 3
#define GEMM_SMEM   (GEMM_STAGES * STG_BYTES)
#define GNITER      32

__device__ __forceinline__ void g_load_stage(
    uint32_t sA, const __half* Ab, const __half* Bb, int tid)
{
#pragma unroll
    for (int t = 0; t < 8; t++) {
        int c = tid + t * 128;
        int r = c >> 3, co = (c & 7) << 3;
        CP_ASYNC16(sA + (r * AST + co) * 2, Ab + (size_t)r * KA + co);
        CP_ASYNC16(sA + STG_MAT + (r * AST + co) * 2, Bb + (size_t)r * KA + co);
    }
}

__global__ void __launch_bounds__(128, 2) tc_gemm_kernel(
    const __half* __restrict__ A, const __half* __restrict__ B,
    float* __restrict__ C, int ldc)
{
    extern __shared__ char smg[];
    uint32_t smb = s2u(smg);
    int tid  = threadIdx.x;
    int lane = tid & 31, wid = tid >> 5;
    int wm = (wid & 1) * 64, wn = (wid >> 1) * 64;
    int m0 = blockIdx.y * 128, n0 = blockIdx.x * 128;

    float acc[4][8][4];
#pragma unroll
    for (int i = 0; i < 4; i++)
#pragma unroll
        for (int j = 0; j < 8; j++)
#pragma unroll
            for (int k = 0; k < 4; k++) acc[i][j][k] = 0.f;

    uint32_t a_off[4][4], b_off[4][4];
#pragma unroll
    for (int ks = 0; ks < 4; ks++) {
#pragma unroll
        for (int mt = 0; mt < 4; mt++)
            a_off[ks][mt] = ((wm + mt * 16 + (lane & 15)) * AST +
                             ks * 16 + (lane >> 4) * 8) * 2;
#pragma unroll
        for (int np = 0; np < 4; np++)
            b_off[ks][np] = STG_MAT +
                ((wn + np * 16 + ((lane >> 4) & 1) * 8 + (lane & 7)) * AST +
                 ks * 16 + ((lane >> 3) & 1) * 8) * 2;
    }

#pragma unroll
    for (int p = 0; p < GEMM_STAGES - 1; p++) {
        g_load_stage(smb + p * STG_BYTES,
                     A + (size_t)m0 * KA + (p << 6),
                     B + (size_t)n0 * KA + (p << 6), tid);
        CP_COMMIT();
    }
    CP_WAIT1();
    __syncthreads();

    uint32_t af[2][4][4], bf[2][4];
#pragma unroll
    for (int mt = 0; mt < 4; mt++) LDSM4(af[0][mt], smb + a_off[0][mt]);
    LDSM4(bf[0], smb + b_off[0][0]);

    for (int it = 0; it < GNITER; ++it) {
        uint32_t sbase = smb + (it % GEMM_STAGES) * STG_BYTES;

        int nx = it + GEMM_STAGES - 1;
        if (nx < GNITER) {
            g_load_stage(smb + (nx % GEMM_STAGES) * STG_BYTES,
                         A + (size_t)m0 * KA + (nx << 6),
                         B + (size_t)n0 * KA + (nx << 6), tid);
        }
        CP_COMMIT();

#pragma unroll
        for (int ks = 0; ks < 4; ks++) {
            int cur = ks & 1, nxt = cur ^ 1;
            uint32_t bb[2][4];
#pragma unroll
            for (int e = 0; e < 4; e++) bb[0][e] = bf[cur][e];
#pragma unroll
            for (int np = 0; np < 4; np++) {
                if (np < 3) LDSM4(bb[(np + 1) & 1], sbase + b_off[ks][np + 1]);
#pragma unroll
                for (int mt = 0; mt < 4; mt++) {
                    MMA16816H(acc[mt][2 * np],     af[cur][mt], bb[np & 1][0], bb[np & 1][1]);
                    MMA16816H(acc[mt][2 * np + 1], af[cur][mt], bb[np & 1][2], bb[np & 1][3]);
                }
            }
            if (ks < 3) {
#pragma unroll
                for (int mt = 0; mt < 4; mt++)
                    LDSM4(af[nxt][mt], sbase + a_off[ks + 1][mt]);
                LDSM4(bf[nxt], sbase + b_off[ks + 1][0]);
            }
        }

        CP_WAIT1();
        __syncthreads();
        uint32_t nbase = smb + ((it + 1) % GEMM_STAGES) * STG_BYTES;
#pragma unroll
        for (int mt = 0; mt < 4; mt++) LDSM4(af[0][mt], nbase + a_off[0][mt]);
        LDSM4(bf[0], nbase + b_off[0][0]);
    }

    float* Cb = C + (size_t)(m0 + wm) * ldc + n0 + wn;
    int rq = lane >> 2, cq = (lane & 3) * 2;
#pragma unroll
    for (int mt = 0; mt < 4; mt++)
#pragma unroll
        for (int nt = 0; nt < 8; nt++) {
            *(float2*)(Cb + (size_t)(mt * 16 + rq) * ldc + nt * 8 + cq) =
                make_float2(acc[mt][nt][0], acc[mt][nt][1]);
            *(float2*)(Cb + (size_t)(mt * 16 + rq + 8) * ldc + nt * 8 + cq) =
                make_float2(acc[mt][nt][2], acc[mt][nt][3]);
        }
}

// ---------------------------------------------------------------------------
// Tensor-core flash attention v5: pure fp16 1-pass (Q,K,V,P single plane),
// causal, online softmax, LPT grid, 3-stage KV ring, 1 sync/K-tile,
// fused fp16 ctx epilogue.
// ---------------------------------------------------------------------------
#define AKST     136
#define AROWB    (AKST * 2)                 // 272 B
#define QPLANE   (128 * AROWB)              // 34816
#define KVPLANE  (64 * AROWB)               // 17408
#define STAGE_B  (2 * KVPLANE)              // 34816 (K + V, single planes)
#define KVSTAGES 3
#define ATTN_SMEM (KVSTAGES * STAGE_B)      // 104448

__device__ __forceinline__ void load_kv_stage(
    uint32_t dst, const __half* Kp, const __half* Vp, int k0, int tid)
{
#pragma unroll
    for (int t = 0; t < 8; t++) {
        int c = tid + t * 256;
        int plane = c >> 10;                // 0:K 1:V
        int r = (c >> 4) & 63;
        int co = c & 15;
        const __half* src = (plane == 0)
            ? Kp + ((size_t)k0 + r) * HD + co * 8
            : Vp + ((size_t)k0 + r) * HD + co * 8;
        CP_ASYNC16(dst + plane * KVPLANE + r * AROWB + co * 16, src);
    }
}

__global__ void __launch_bounds__(256) attn_mma_kernel() {
    extern __shared__ char sma[];
    uint32_t smb = s2u(sma);
    int tid = threadIdx.x, lane = tid & 31, w = tid >> 5;
    int qt = 15 - ((int)blockIdx.x >> 5);   // LPT: heaviest first
    int bh = (int)blockIdx.x & 31;
    int q0 = qt * 128;
    int nkt = 2 * qt + 2;

    const __half* Qp = g_qp + (size_t)bh * SEQ * HD;
    const __half* Kp = g_kp + (size_t)bh * SEQ * HD;
    const __half* Vp = g_vp + (size_t)bh * SEQ * HD;

    // group 0: Q tile (128 rows, exactly one ring slot) into slot 2
    uint32_t sQstage = smb + 2 * STAGE_B;
#pragma unroll
    for (int t = 0; t < 8; t++) {
        int c = tid + t * 256;
        int r = c >> 4, co = c & 15;
        CP_ASYNC16(sQstage + r * AROWB + co * 16,
                   Qp + ((size_t)q0 + r) * HD + co * 8);
    }
    CP_COMMIT();
    load_kv_stage(smb, Kp, Vp, 0, tid);
    CP_COMMIT();
    load_kv_stage(smb + STAGE_B, Kp, Vp, 64, tid);
    CP_COMMIT();

    int rq = lane >> 2, cq = lane & 3;
    uint32_t qoff = (uint32_t)(16 * w + (lane & 15)) * AROWB + ((lane >> 4) & 1) * 16;
    uint32_t koff = (uint32_t)(((lane >> 4) & 1) * 8 + (lane & 7)) * AROWB +
                    ((lane >> 3) & 1) * 16;
    uint32_t voff = KVPLANE +
                    (uint32_t)(((lane >> 3) & 1) * 8 + (lane & 7)) * AROWB +
                    ((lane >> 4) & 1) * 16;

    // Q fragments -> registers (once)
    CP_WAIT2();
    __syncthreads();
    uint32_t qfh[8][4];
#pragma unroll
    for (int kc = 0; kc < 8; kc++)
        LDSM4(qfh[kc], sQstage + qoff + kc * 32);

    float out[16][4];
#pragma unroll
    for (int n = 0; n < 16; n++)
#pragma unroll
        for (int e = 0; e < 4; e++) out[n][e] = 0.f;
    float m0 = -1e30f, m1 = -1e30f, l0 = 0.f, l1 = 0.f;

    const float SCALE2 = 0.08838834764831845f * 1.44269504088896341f;

    for (int kt = 0; kt < nkt; kt++) {
        CP_WAIT1();
        __syncthreads();
        if (kt + 2 < nkt)
            load_kv_stage(smb + ((kt + 2) % KVSTAGES) * STAGE_B, Kp, Vp,
                          (kt + 2) * 64, tid);
        CP_COMMIT();

        uint32_t sS = smb + (kt % KVSTAGES) * STAGE_B;   // K at +0, V at +KVPLANE

        // ---- scores: S = Q*K (double-buffered K frags) ----
        float sc[8][4];
#pragma unroll
        for (int j = 0; j < 8; j++)
#pragma unroll
            for (int e = 0; e < 4; e++) sc[j][e] = 0.f;

        {
            uint32_t bkh[2][4];
            LDSM4(bkh[0], sS + koff);
#pragma unroll
            for (int t = 0; t < 32; t++) {
                int kc = t >> 2, jj = t & 3;
                int cur = t & 1;
                if (t < 31) {
                    int tn = t + 1;
                    uint32_t on = koff + (uint32_t)(tn & 3) * (16 * AROWB) +
                                  (tn >> 2) * 32;
                    LDSM4(bkh[cur ^ 1], sS + on);
                }
                MMA16816H(sc[2 * jj],     qfh[kc], bkh[cur][0], bkh[cur][1]);
                MMA16816H(sc[2 * jj + 1], qfh[kc], bkh[cur][2], bkh[cur][3]);
            }
        }

        int k0 = kt * 64;
#pragma unroll
        for (int j = 0; j < 8; j++)
#pragma unroll
            for (int e = 0; e < 4; e++) sc[j][e] *= SCALE2;
        if (k0 + 64 > q0) {
            int rg0 = q0 + 16 * w + rq, rg1 = rg0 + 8;
#pragma unroll
            for (int j = 0; j < 8; j++) {
                int cg = k0 + 8 * j + 2 * cq;
                if (cg     > rg0) sc[j][0] = -1e30f;
                if (cg + 1 > rg0) sc[j][1] = -1e30f;
                if (cg     > rg1) sc[j][2] = -1e30f;
                if (cg + 1 > rg1) sc[j][3] = -1e30f;
            }
        }

        float t0 = -1e30f, t1 = -1e30f;
#pragma unroll
        for (int j = 0; j < 8; j++) {
            t0 = fmaxf(t0, fmaxf(sc[j][0], sc[j][1]));
            t1 = fmaxf(t1, fmaxf(sc[j][2], sc[j][3]));
        }
        t0 = fmaxf(t0, __shfl_xor_sync(0xffffffffu, t0, 1));
        t0 = fmaxf(t0, __shfl_xor_sync(0xffffffffu, t0, 2));
        t1 = fmaxf(t1, __shfl_xor_sync(0xffffffffu, t1, 1));
        t1 = fmaxf(t1, __shfl_xor_sync(0xffffffffu, t1, 2));
        float mn0 = fmaxf(m0, t0), mn1 = fmaxf(m1, t1);
        float al0 = ex2f(m0 - mn0), al1 = ex2f(m1 - mn1);
        m0 = mn0; m1 = mn1;
        l0 *= al0; l1 *= al1;
#pragma unroll
        for (int n = 0; n < 16; n++) {
            out[n][0] *= al0; out[n][1] *= al0;
            out[n][2] *= al1; out[n][3] *= al1;
        }

        // ---- exp + PV (1 pass, double-buffered V frags) ----
#pragma unroll
        for (int kc = 0; kc < 4; kc++) {
            int j0 = 2 * kc, j1 = 2 * kc + 1;
            float p00 = ex2f(sc[j0][0] - m0), p01 = ex2f(sc[j0][1] - m0);
            float p02 = ex2f(sc[j0][2] - m1), p03 = ex2f(sc[j0][3] - m1);
            float p10 = ex2f(sc[j1][0] - m0), p11 = ex2f(sc[j1][1] - m0);
            float p12 = ex2f(sc[j1][2] - m1), p13 = ex2f(sc[j1][3] - m1);
            l0 += p00 + p01 + p10 + p11;
            l1 += p02 + p03 + p12 + p13;

            uint32_t ah[4];
            ah[0] = packh(p00, p01);
            ah[1] = packh(p02, p03);
            ah[2] = packh(p10, p11);
            ah[3] = packh(p12, p13);

            uint32_t bvh[2][4];
            uint32_t o0 = voff + (uint32_t)kc * (16 * AROWB);
            LDSM4T(bvh[0], sS + o0);
#pragma unroll
            for (int jp = 0; jp < 8; jp++) {
                int cur = jp & 1;
                if (jp < 7)
                    LDSM4T(bvh[cur ^ 1], sS + o0 + (jp + 1) * 32);
                MMA16816H(out[2 * jp],     ah, bvh[cur][0], bvh[cur][1]);
                MMA16816H(out[2 * jp + 1], ah, bvh[cur][2], bvh[cur][3]);
            }
        }
    }

    l0 += __shfl_xor_sync(0xffffffffu, l0, 1);
    l0 += __shfl_xor_sync(0xffffffffu, l0, 2);
    l1 += __shfl_xor_sync(0xffffffffu, l1, 1);
    l1 += __shfl_xor_sync(0xffffffffu, l1, 2);
    float il0 = 1.f / l0, il1 = 1.f / l1;

    // Epilogue: write fp16 ctx plane (out-proj A operand)
    int b = bh >> 4, hh = bh & 15;
    int grow0 = b * SEQ + q0 + 16 * w + rq;
    __half* cb0 = g_cxh + (size_t)grow0 * KA + hh * HD + 2 * cq;
    __half* cb1 = cb0 + (size_t)8 * KA;
#pragma unroll
    for (int nt = 0; nt < 16; nt++) {
        *(uint32_t*)(cb0 + nt * 8) = packh(out[nt][0] * il0, out[nt][1] * il0);
        *(uint32_t*)(cb1 + nt * 8) = packh(out[nt][2] * il1, out[nt][3] * il1);
    }
}

// ---------------------------------------------------------------------------
// Launch graph (idx 3 = QKV GEMM, the ncu capture slot)
// ---------------------------------------------------------------------------
extern "C" void kernel_launch(void* const* d_in, const int* in_sizes, int n_in,
                              void* d_out, int out_size) {
    const float* x    = (const float*)d_in[0];
    // d_in[1] = attn_mask (pure causal) — reproduced analytically, not read
    const float* Wqkv = (const float*)d_in[2];
    const float* Wout = (const float*)d_in[3];
    float* out = (float*)d_out;

    float* qkv_ptr = 0;
    __half *xh = 0, *wqp = 0, *wop = 0, *cxh = 0;
    cudaGetSymbolAddress((void**)&qkv_ptr, g_qkv);
    cudaGetSymbolAddress((void**)&xh,  g_xh);
    cudaGetSymbolAddress((void**)&wqp, g_wqp);
    cudaGetSymbolAddress((void**)&wop, g_wop);
    cudaGetSymbolAddress((void**)&cxh, g_cxh);

    cudaFuncSetAttribute(tc_gemm_kernel,
                         cudaFuncAttributeMaxDynamicSharedMemorySize, GEMM_SMEM);
    cudaFuncSetAttribute(attn_mma_kernel,
                         cudaFuncAttributeMaxDynamicSharedMemorySize, ATTN_SMEM);

    // idx 0..2: packs (single fp16 plane)
    pack_x_kernel<<<MROWS * HID / 2048, 256>>>(x, xh, MROWS * HID);
    pack_x_kernel<<<QKVN * HID / 2048, 256>>>(Wqkv, wqp, QKVN * HID);
    pack_x_kernel<<<HID  * HID / 2048, 256>>>(Wout, wop, HID * HID);

    // idx 3: QKV GEMM (ncu capture slot)
    tc_gemm_kernel<<<dim3(QKVN / 128, MROWS / 128), 128, GEMM_SMEM>>>(
        xh, wqp, qkv_ptr, QKVN);

    // idx 4..5: RoPE table + qkv pack
    rope_table_kernel<<<(SEQ * 64 + 255) / 256, 256>>>();
    qkv_pack_kernel<<<MROWS * NH * 16 / 256, 256>>>();

    // idx 6: attention (fp16 1-pass, LPT grid, fused fp16 ctx epilogue)
    attn_mma_kernel<<<(SEQ / 128) * BATCH * NH, 256, ATTN_SMEM>>>();

    // idx 7: output GEMM
    tc_gemm_kernel<<<dim3(HID / 128, MROWS / 128), 128, GEMM_SMEM>>>(
        cxh, wop, out, HID);
}